// round 3
// baseline (speedup 1.0000x reference)
#include <cuda_runtime.h>

#define B_ 2
#define S_ 2048
#define H_ 1024
#define NH_ 16
#define DH_ 64
#define RV_ 4096

// Scratch (allocation-free contract: __device__ globals)
__device__ float g_q[(size_t)B_ * NH_ * S_ * DH_];
__device__ float g_k[(size_t)B_ * NH_ * S_ * DH_];
__device__ float g_v[(size_t)B_ * NH_ * S_ * DH_];
__device__ float g_dT[NH_ * RV_];   // dist_emb transposed: [h][vocab]

// ---------------------------------------------------------------------------
// Kernel 0: transpose dist_emb [4096,16] -> [16,4096]
// ---------------------------------------------------------------------------
__global__ void transpose_dist(const float* __restrict__ de) {
    int t = blockIdx.x * blockDim.x + threadIdx.x;
    if (t < RV_ * NH_) {
        int v = t / NH_;
        int h = t - v * NH_;
        g_dT[h * RV_ + v] = de[t];
    }
}

// ---------------------------------------------------------------------------
// Kernel 1: fused QKV projection.
//   q/k/v = X @ W^T + b, written as [B, NH, S, DH].
//   Grid: x = 48 (3 weights x 16 n-tiles of 64), y = 64 (m-tiles of 64).
//   64x64 tile, BK=16, 256 threads, 4x4 microtile.
// ---------------------------------------------------------------------------
__global__ __launch_bounds__(256) void qkv_proj(
    const float* __restrict__ X,
    const float* __restrict__ Wq, const float* __restrict__ bq,
    const float* __restrict__ Wk, const float* __restrict__ bk,
    const float* __restrict__ Wv, const float* __restrict__ bv)
{
    __shared__ float As[16][65];   // [k][m], padded
    __shared__ float Bs[16][65];   // [k][n], padded

    const int w  = blockIdx.x >> 4;            // 0=Q, 1=K, 2=V
    const int n0 = (blockIdx.x & 15) * 64;     // output-feature tile (one head)
    const int m0 = blockIdx.y * 64;            // row tile (b*S+s)

    const float* W    = (w == 0) ? Wq : (w == 1) ? Wk : Wv;
    const float* bias = (w == 0) ? bq : (w == 1) ? bk : bv;
    float* out        = (w == 0) ? g_q : (w == 1) ? g_k : g_v;

    const int t  = threadIdx.x;
    const int tx = t & 15;
    const int ty = t >> 4;
    const int lr = t >> 2;            // load row 0..63
    const int lc = (t & 3) * 4;       // load col (of 16)

    float acc[4][4];
#pragma unroll
    for (int i = 0; i < 4; i++)
#pragma unroll
        for (int j = 0; j < 4; j++) acc[i][j] = 0.0f;

    for (int k0 = 0; k0 < H_; k0 += 16) {
        float4 xa = *(const float4*)(X + (size_t)(m0 + lr) * H_ + k0 + lc);
        float4 wb = *(const float4*)(W + (size_t)(n0 + lr) * H_ + k0 + lc);
        __syncthreads();
        As[lc + 0][lr] = xa.x; As[lc + 1][lr] = xa.y;
        As[lc + 2][lr] = xa.z; As[lc + 3][lr] = xa.w;
        Bs[lc + 0][lr] = wb.x; Bs[lc + 1][lr] = wb.y;
        Bs[lc + 2][lr] = wb.z; Bs[lc + 3][lr] = wb.w;
        __syncthreads();
#pragma unroll
        for (int kk = 0; kk < 16; kk++) {
            float a[4], bcol[4];
#pragma unroll
            for (int i = 0; i < 4; i++) a[i] = As[kk][ty * 4 + i];
#pragma unroll
            for (int j = 0; j < 4; j++) bcol[j] = Bs[kk][tx * 4 + j];
#pragma unroll
            for (int i = 0; i < 4; i++)
#pragma unroll
                for (int j = 0; j < 4; j++) acc[i][j] += a[i] * bcol[j];
        }
    }

    // Epilogue: add bias, scatter into [B, NH, S, DH]. One n-tile == one head.
    const int h = n0 >> 6;
    float4 b4 = *(const float4*)(bias + n0 + tx * 4);
#pragma unroll
    for (int i = 0; i < 4; i++) {
        int m = m0 + ty * 4 + i;
        int bb = m >> 11;            // / 2048
        int s  = m & (S_ - 1);
        float4 o4;
        o4.x = acc[i][0] + b4.x;
        o4.y = acc[i][1] + b4.y;
        o4.z = acc[i][2] + b4.z;
        o4.w = acc[i][3] + b4.w;
        *(float4*)(out + (((size_t)bb * NH_ + h) * S_ + s) * DH_ + tx * 4) = o4;
    }
}

// ---------------------------------------------------------------------------
// Kernel 2: flash attention with relative scalar bias.
//   Grid: (32 q-tiles, NH, B). Block: 256 threads, BM=BN=64, DH=64.
//   Online softmax; bias gathered from smem-resident dist_emb column.
// ---------------------------------------------------------------------------
#define FLASH_SMEM_FLOATS (64 * 65 * 3 + 64 * 68 + RV_ + 64)
#define FLASH_SMEM_BYTES  (FLASH_SMEM_FLOATS * 4)

__global__ __launch_bounds__(256, 2) void flash_attn(
    const float* __restrict__ mask,       // [B,1,1,S]
    const int*   __restrict__ dist_idx,   // [S,S]
    float*       __restrict__ out)        // [B,S,H]
{
    extern __shared__ float sm[];
    float* Qt      = sm;                    // [64][65]  Qt[d][m]
    float* Kt      = Qt + 64 * 65;          // [64][65]  Kt[d][n]
    float* Ps      = Kt + 64 * 65;          // [64][65]  Ps[n][m]
    float* Vs      = Ps + 64 * 65;          // [64][68]  Vs[n][d]
    float* distcol = Vs + 64 * 68;          // [4096]
    float* maskv   = distcol + RV_;         // [64]

    const int t  = threadIdx.x;
    const int tx = t & 15;
    const int ty = t >> 4;
    const int q0 = blockIdx.x * 64;
    const int h  = blockIdx.y;
    const int b  = blockIdx.z;
    const size_t base = ((size_t)b * NH_ + h) * S_;

    const int lr = t >> 2;           // 0..63: tile row
    const int lc = (t & 3) * 4;      // 0,4,8,12: base col segment

    // Load full 64x64 Q tile transposed (4 column-segments of 16 per thread)
#pragma unroll
    for (int it = 0; it < 4; it++) {
        const int c = lc + 16 * it;
        float4 q4 = *(const float4*)(g_q + (base + q0 + lr) * DH_ + c);
        Qt[(c + 0) * 65 + lr] = q4.x;
        Qt[(c + 1) * 65 + lr] = q4.y;
        Qt[(c + 2) * 65 + lr] = q4.z;
        Qt[(c + 3) * 65 + lr] = q4.w;
    }
    // Preload this head's dist_emb column (16 KB)
    for (int i = t; i < RV_; i += 256) distcol[i] = g_dT[h * RV_ + i];

    float m_r[4], l_r[4], O[4][4];
#pragma unroll
    for (int i = 0; i < 4; i++) {
        m_r[i] = -1e30f;
        l_r[i] = 0.0f;
#pragma unroll
        for (int j = 0; j < 4; j++) O[i][j] = 0.0f;
    }

    for (int kt = 0; kt < 32; kt++) {
        const int k0 = kt * 64;
        __syncthreads();   // prev PV done reading Ps/Vs before overwrite
#pragma unroll
        for (int it = 0; it < 4; it++) {
            const int c = lc + 16 * it;
            float4 k4 = *(const float4*)(g_k + (base + k0 + lr) * DH_ + c);
            Kt[(c + 0) * 65 + lr] = k4.x;
            Kt[(c + 1) * 65 + lr] = k4.y;
            Kt[(c + 2) * 65 + lr] = k4.z;
            Kt[(c + 3) * 65 + lr] = k4.w;
            float4 v4 = *(const float4*)(g_v + (base + k0 + lr) * DH_ + c);
            *(float4*)&Vs[lr * 68 + c] = v4;
        }
        if (t < 64) maskv[t] = mask[(size_t)b * S_ + k0 + t];
        __syncthreads();

        // S = Q K^T
        float s[4][4];
#pragma unroll
        for (int i = 0; i < 4; i++)
#pragma unroll
            for (int j = 0; j < 4; j++) s[i][j] = 0.0f;
#pragma unroll 8
        for (int d = 0; d < 64; d++) {
            float a[4], kb[4];
#pragma unroll
            for (int i = 0; i < 4; i++) a[i] = Qt[d * 65 + ty * 4 + i];
#pragma unroll
            for (int j = 0; j < 4; j++) kb[j] = Kt[d * 65 + tx * 4 + j];
#pragma unroll
            for (int i = 0; i < 4; i++)
#pragma unroll
                for (int j = 0; j < 4; j++) s[i][j] += a[i] * kb[j];
        }

        // scale + relative bias + mask
        float mk[4];
#pragma unroll
        for (int j = 0; j < 4; j++) mk[j] = maskv[tx * 4 + j];
#pragma unroll
        for (int i = 0; i < 4; i++) {
            int4 idx = *(const int4*)(dist_idx +
                        (size_t)(q0 + ty * 4 + i) * S_ + k0 + tx * 4);
            s[i][0] = s[i][0] * 0.125f + distcol[idx.x] + mk[0];
            s[i][1] = s[i][1] * 0.125f + distcol[idx.y] + mk[1];
            s[i][2] = s[i][2] * 0.125f + distcol[idx.z] + mk[2];
            s[i][3] = s[i][3] * 0.125f + distcol[idx.w] + mk[3];
        }

        // online softmax (16 lanes with the same ty share a row set)
#pragma unroll
        for (int i = 0; i < 4; i++) {
            float v = fmaxf(fmaxf(s[i][0], s[i][1]), fmaxf(s[i][2], s[i][3]));
            v = fmaxf(v, __shfl_xor_sync(0xffffffffu, v, 1));
            v = fmaxf(v, __shfl_xor_sync(0xffffffffu, v, 2));
            v = fmaxf(v, __shfl_xor_sync(0xffffffffu, v, 4));
            v = fmaxf(v, __shfl_xor_sync(0xffffffffu, v, 8));
            float mn    = fmaxf(m_r[i], v);
            float scale = __expf(m_r[i] - mn);
            float rs = 0.0f;
#pragma unroll
            for (int j = 0; j < 4; j++) {
                float p = __expf(s[i][j] - mn);
                s[i][j] = p;
                rs += p;
            }
            rs += __shfl_xor_sync(0xffffffffu, rs, 1);
            rs += __shfl_xor_sync(0xffffffffu, rs, 2);
            rs += __shfl_xor_sync(0xffffffffu, rs, 4);
            rs += __shfl_xor_sync(0xffffffffu, rs, 8);
            l_r[i] = l_r[i] * scale + rs;
            m_r[i] = mn;
#pragma unroll
            for (int j = 0; j < 4; j++) {
                O[i][j] *= scale;
                Ps[(tx * 4 + j) * 65 + ty * 4 + i] = s[i][j];
            }
        }
        __syncthreads();

        // O += P V
#pragma unroll 8
        for (int n = 0; n < 64; n++) {
            float a[4], vb[4];
#pragma unroll
            for (int i = 0; i < 4; i++) a[i] = Ps[n * 65 + ty * 4 + i];
#pragma unroll
            for (int j = 0; j < 4; j++) vb[j] = Vs[n * 68 + tx * 4 + j];
#pragma unroll
            for (int i = 0; i < 4; i++)
#pragma unroll
                for (int j = 0; j < 4; j++) O[i][j] += a[i] * vb[j];
        }
    }

    // normalize + write [B,S,H] (heads interleaved back)
#pragma unroll
    for (int i = 0; i < 4; i++) {
        float inv = 1.0f / l_r[i];
        float4 o4;
        o4.x = O[i][0] * inv;
        o4.y = O[i][1] * inv;
        o4.z = O[i][2] * inv;
        o4.w = O[i][3] * inv;
        *(float4*)(out + ((size_t)b * S_ + q0 + ty * 4 + i) * H_
                       + h * DH_ + tx * 4) = o4;
    }
}

// ---------------------------------------------------------------------------
extern "C" void kernel_launch(void* const* d_in, const int* in_sizes, int n_in,
                              void* d_out, int out_size)
{
    const float* X    = (const float*)d_in[0];
    const float* mask = (const float*)d_in[1];
    const int*   didx = (const int*)d_in[2];
    const float* Wq   = (const float*)d_in[3];
    const float* bq   = (const float*)d_in[4];
    const float* Wk   = (const float*)d_in[5];
    const float* bk   = (const float*)d_in[6];
    const float* Wv   = (const float*)d_in[7];
    const float* bv   = (const float*)d_in[8];
    const float* de   = (const float*)d_in[9];
    float* out = (float*)d_out;

    static bool attr_set = false;
    if (!attr_set) {
        cudaFuncSetAttribute(flash_attn,
                             cudaFuncAttributeMaxDynamicSharedMemorySize,
                             FLASH_SMEM_BYTES);
        attr_set = true;
    }

    transpose_dist<<<(RV_ * NH_ + 255) / 256, 256>>>(de);
    qkv_proj<<<dim3(48, 64), 256>>>(X, Wq, bq, Wk, bk, Wv, bv);
    flash_attn<<<dim3(32, NH_, B_), 256, FLASH_SMEM_BYTES>>>(mask, didx, out);
}

// round 4
// speedup vs baseline: 1.2231x; 1.2231x over previous
#include <cuda_runtime.h>

#define B_ 2
#define S_ 2048
#define H_ 1024
#define NH_ 16
#define DH_ 64
#define RV_ 4096

typedef unsigned long long u64;

// ---- packed f32x2 helpers (sm_100+ PTX; ptxas won't emit these from C++) ----
__device__ __forceinline__ u64 pk2(float lo, float hi) {
    u64 r; asm("mov.b64 %0, {%1, %2};" : "=l"(r) : "f"(lo), "f"(hi)); return r;
}
__device__ __forceinline__ void upk2(u64 v, float& lo, float& hi) {
    asm("mov.b64 {%0, %1}, %2;" : "=f"(lo), "=f"(hi) : "l"(v));
}
__device__ __forceinline__ void fma2(u64& d, u64 a, u64 b) {
    asm("fma.rn.f32x2 %0, %1, %2, %0;" : "+l"(d) : "l"(a), "l"(b));
}
__device__ __forceinline__ void mul2(u64& d, u64 a) {
    asm("mul.rn.f32x2 %0, %0, %1;" : "+l"(d) : "l"(a));
}

// Scratch (allocation-free contract: __device__ globals)
__device__ float g_q[(size_t)B_ * NH_ * S_ * DH_];
__device__ float g_k[(size_t)B_ * NH_ * S_ * DH_];
__device__ float g_v[(size_t)B_ * NH_ * S_ * DH_];
__device__ float g_dT[NH_ * RV_];   // dist_emb transposed: [h][vocab]

// ---------------------------------------------------------------------------
// Kernel 0: transpose dist_emb [4096,16] -> [16,4096]
// ---------------------------------------------------------------------------
__global__ void transpose_dist(const float* __restrict__ de) {
    int t = blockIdx.x * blockDim.x + threadIdx.x;
    if (t < RV_ * NH_) {
        int v = t / NH_;
        int h = t - v * NH_;
        g_dT[h * RV_ + v] = de[t];
    }
}

// ---------------------------------------------------------------------------
// Kernel 1: fused QKV projection (packed f32x2 inner loop).
//   64x64 tile, BK=16, 256 threads, 4x4 microtile (as 2x f32x2 per row).
// ---------------------------------------------------------------------------
__global__ __launch_bounds__(256) void qkv_proj(
    const float* __restrict__ X,
    const float* __restrict__ Wq, const float* __restrict__ bq,
    const float* __restrict__ Wk, const float* __restrict__ bk,
    const float* __restrict__ Wv, const float* __restrict__ bv)
{
    __shared__ float As[16][68];   // [k][m], pad 68 keeps 16B alignment
    __shared__ float Bs[16][68];   // [k][n]

    const int w  = blockIdx.x >> 4;            // 0=Q, 1=K, 2=V
    const int n0 = (blockIdx.x & 15) * 64;     // output-feature tile (one head)
    const int m0 = blockIdx.y * 64;            // row tile (b*S+s)

    const float* W    = (w == 0) ? Wq : (w == 1) ? Wk : Wv;
    const float* bias = (w == 0) ? bq : (w == 1) ? bk : bv;
    float* out        = (w == 0) ? g_q : (w == 1) ? g_k : g_v;

    const int t  = threadIdx.x;
    const int tx = t & 15;
    const int ty = t >> 4;
    const int lr = t >> 2;            // load row 0..63
    const int lc = (t & 3) * 4;       // load col (of 16)

    u64 acc[4][2];
#pragma unroll
    for (int i = 0; i < 4; i++) { acc[i][0] = 0ull; acc[i][1] = 0ull; }

    for (int k0 = 0; k0 < H_; k0 += 16) {
        float4 xa = *(const float4*)(X + (size_t)(m0 + lr) * H_ + k0 + lc);
        float4 wb = *(const float4*)(W + (size_t)(n0 + lr) * H_ + k0 + lc);
        __syncthreads();
        As[lc + 0][lr] = xa.x; As[lc + 1][lr] = xa.y;
        As[lc + 2][lr] = xa.z; As[lc + 3][lr] = xa.w;
        Bs[lc + 0][lr] = wb.x; Bs[lc + 1][lr] = wb.y;
        Bs[lc + 2][lr] = wb.z; Bs[lc + 3][lr] = wb.w;
        __syncthreads();
#pragma unroll
        for (int kk = 0; kk < 16; kk++) {
            float4 a4 = *(const float4*)&As[kk][ty * 4];
            float4 b4 = *(const float4*)&Bs[kk][tx * 4];
            u64 b01 = pk2(b4.x, b4.y);
            u64 b23 = pk2(b4.z, b4.w);
            u64 aa;
            aa = pk2(a4.x, a4.x); fma2(acc[0][0], aa, b01); fma2(acc[0][1], aa, b23);
            aa = pk2(a4.y, a4.y); fma2(acc[1][0], aa, b01); fma2(acc[1][1], aa, b23);
            aa = pk2(a4.z, a4.z); fma2(acc[2][0], aa, b01); fma2(acc[2][1], aa, b23);
            aa = pk2(a4.w, a4.w); fma2(acc[3][0], aa, b01); fma2(acc[3][1], aa, b23);
        }
    }

    // Epilogue: add bias, scatter into [B, NH, S, DH]. One n-tile == one head.
    const int h = n0 >> 6;
    float4 b4 = *(const float4*)(bias + n0 + tx * 4);
#pragma unroll
    for (int i = 0; i < 4; i++) {
        int m = m0 + ty * 4 + i;
        int bb = m >> 11;            // / 2048
        int s  = m & (S_ - 1);
        float4 o4;
        upk2(acc[i][0], o4.x, o4.y);
        upk2(acc[i][1], o4.z, o4.w);
        o4.x += b4.x; o4.y += b4.y; o4.z += b4.z; o4.w += b4.w;
        *(float4*)(out + (((size_t)bb * NH_ + h) * S_ + s) * DH_ + tx * 4) = o4;
    }
}

// ---------------------------------------------------------------------------
// Kernel 2: flash attention with relative scalar bias (packed f32x2 GEMMs).
//   Grid: (32 q-tiles, NH, B). Block: 256 threads, BM=BN=64, DH=64.
// ---------------------------------------------------------------------------
#define PADF 68
#define FLASH_SMEM_FLOATS (64 * PADF * 4 + RV_ + 64)
#define FLASH_SMEM_BYTES  (FLASH_SMEM_FLOATS * 4)

__global__ __launch_bounds__(256, 2) void flash_attn(
    const float* __restrict__ mask,       // [B,1,1,S]
    const int*   __restrict__ dist_idx,   // [S,S]
    float*       __restrict__ out)        // [B,S,H]
{
    extern __shared__ float sm[];
    float* Qt      = sm;                    // [64][PADF]  Qt[d][m]
    float* Kt      = Qt + 64 * PADF;        // [64][PADF]  Kt[d][n]
    float* Ps      = Kt + 64 * PADF;        // [64][PADF]  Ps[n][m]
    float* Vs      = Ps + 64 * PADF;        // [64][PADF]  Vs[n][d]
    float* distcol = Vs + 64 * PADF;        // [4096]
    float* maskv   = distcol + RV_;         // [64]

    const int t  = threadIdx.x;
    const int tx = t & 15;
    const int ty = t >> 4;
    const int q0 = blockIdx.x * 64;
    const int h  = blockIdx.y;
    const int b  = blockIdx.z;
    const size_t base = ((size_t)b * NH_ + h) * S_;

    const int lr = t >> 2;           // 0..63: tile row
    const int lc = (t & 3) * 4;      // 0,4,8,12: base col segment

    // Load full 64x64 Q tile transposed (4 column-segments of 16 per thread)
#pragma unroll
    for (int it = 0; it < 4; it++) {
        const int c = lc + 16 * it;
        float4 q4 = *(const float4*)(g_q + (base + q0 + lr) * DH_ + c);
        Qt[(c + 0) * PADF + lr] = q4.x;
        Qt[(c + 1) * PADF + lr] = q4.y;
        Qt[(c + 2) * PADF + lr] = q4.z;
        Qt[(c + 3) * PADF + lr] = q4.w;
    }
    // Preload this head's dist_emb column (16 KB)
    for (int i = t; i < RV_; i += 256) distcol[i] = g_dT[h * RV_ + i];

    float m_r[4], l_r[4];
    u64 O2[4][2];
#pragma unroll
    for (int i = 0; i < 4; i++) {
        m_r[i] = -1e30f;
        l_r[i] = 0.0f;
        O2[i][0] = 0ull;
        O2[i][1] = 0ull;
    }

    for (int kt = 0; kt < 32; kt++) {
        const int k0 = kt * 64;
        __syncthreads();   // prev PV done reading Ps/Vs before overwrite
#pragma unroll
        for (int it = 0; it < 4; it++) {
            const int c = lc + 16 * it;
            float4 k4 = *(const float4*)(g_k + (base + k0 + lr) * DH_ + c);
            Kt[(c + 0) * PADF + lr] = k4.x;
            Kt[(c + 1) * PADF + lr] = k4.y;
            Kt[(c + 2) * PADF + lr] = k4.z;
            Kt[(c + 3) * PADF + lr] = k4.w;
            float4 v4 = *(const float4*)(g_v + (base + k0 + lr) * DH_ + c);
            *(float4*)&Vs[lr * PADF + c] = v4;
        }
        if (t < 64) maskv[t] = mask[(size_t)b * S_ + k0 + t];
        __syncthreads();

        // S = Q K^T  (packed f32x2)
        u64 s2[4][2];
#pragma unroll
        for (int i = 0; i < 4; i++) { s2[i][0] = 0ull; s2[i][1] = 0ull; }
#pragma unroll 8
        for (int d = 0; d < 64; d++) {
            float4 a4 = *(const float4*)&Qt[d * PADF + ty * 4];
            float4 k4 = *(const float4*)&Kt[d * PADF + tx * 4];
            u64 k01 = pk2(k4.x, k4.y);
            u64 k23 = pk2(k4.z, k4.w);
            u64 aa;
            aa = pk2(a4.x, a4.x); fma2(s2[0][0], aa, k01); fma2(s2[0][1], aa, k23);
            aa = pk2(a4.y, a4.y); fma2(s2[1][0], aa, k01); fma2(s2[1][1], aa, k23);
            aa = pk2(a4.z, a4.z); fma2(s2[2][0], aa, k01); fma2(s2[2][1], aa, k23);
            aa = pk2(a4.w, a4.w); fma2(s2[3][0], aa, k01); fma2(s2[3][1], aa, k23);
        }

        // unpack, scale + relative bias + mask
        float s[4][4];
        float mk[4];
#pragma unroll
        for (int j = 0; j < 4; j++) mk[j] = maskv[tx * 4 + j];
#pragma unroll
        for (int i = 0; i < 4; i++) {
            upk2(s2[i][0], s[i][0], s[i][1]);
            upk2(s2[i][1], s[i][2], s[i][3]);
            int4 idx = *(const int4*)(dist_idx +
                        (size_t)(q0 + ty * 4 + i) * S_ + k0 + tx * 4);
            s[i][0] = s[i][0] * 0.125f + distcol[idx.x] + mk[0];
            s[i][1] = s[i][1] * 0.125f + distcol[idx.y] + mk[1];
            s[i][2] = s[i][2] * 0.125f + distcol[idx.z] + mk[2];
            s[i][3] = s[i][3] * 0.125f + distcol[idx.w] + mk[3];
        }

        // online softmax (16 lanes with the same ty share a row set)
#pragma unroll
        for (int i = 0; i < 4; i++) {
            float v = fmaxf(fmaxf(s[i][0], s[i][1]), fmaxf(s[i][2], s[i][3]));
            v = fmaxf(v, __shfl_xor_sync(0xffffffffu, v, 1));
            v = fmaxf(v, __shfl_xor_sync(0xffffffffu, v, 2));
            v = fmaxf(v, __shfl_xor_sync(0xffffffffu, v, 4));
            v = fmaxf(v, __shfl_xor_sync(0xffffffffu, v, 8));
            float mn    = fmaxf(m_r[i], v);
            float scale = __expf(m_r[i] - mn);
            float rs = 0.0f;
#pragma unroll
            for (int j = 0; j < 4; j++) {
                float p = __expf(s[i][j] - mn);
                s[i][j] = p;
                rs += p;
            }
            rs += __shfl_xor_sync(0xffffffffu, rs, 1);
            rs += __shfl_xor_sync(0xffffffffu, rs, 2);
            rs += __shfl_xor_sync(0xffffffffu, rs, 4);
            rs += __shfl_xor_sync(0xffffffffu, rs, 8);
            l_r[i] = l_r[i] * scale + rs;
            m_r[i] = mn;
            u64 sc = pk2(scale, scale);
            mul2(O2[i][0], sc);
            mul2(O2[i][1], sc);
#pragma unroll
            for (int j = 0; j < 4; j++)
                Ps[(tx * 4 + j) * PADF + ty * 4 + i] = s[i][j];
        }
        __syncthreads();

        // O += P V  (packed f32x2)
#pragma unroll 8
        for (int n = 0; n < 64; n++) {
            float4 a4 = *(const float4*)&Ps[n * PADF + ty * 4];
            float4 v4 = *(const float4*)&Vs[n * PADF + tx * 4];
            u64 v01 = pk2(v4.x, v4.y);
            u64 v23 = pk2(v4.z, v4.w);
            u64 aa;
            aa = pk2(a4.x, a4.x); fma2(O2[0][0], aa, v01); fma2(O2[0][1], aa, v23);
            aa = pk2(a4.y, a4.y); fma2(O2[1][0], aa, v01); fma2(O2[1][1], aa, v23);
            aa = pk2(a4.z, a4.z); fma2(O2[2][0], aa, v01); fma2(O2[2][1], aa, v23);
            aa = pk2(a4.w, a4.w); fma2(O2[3][0], aa, v01); fma2(O2[3][1], aa, v23);
        }
    }

    // normalize + write [B,S,H] (heads interleaved back)
#pragma unroll
    for (int i = 0; i < 4; i++) {
        float inv = 1.0f / l_r[i];
        float4 o4;
        upk2(O2[i][0], o4.x, o4.y);
        upk2(O2[i][1], o4.z, o4.w);
        o4.x *= inv; o4.y *= inv; o4.z *= inv; o4.w *= inv;
        *(float4*)(out + ((size_t)b * S_ + q0 + ty * 4 + i) * H_
                       + h * DH_ + tx * 4) = o4;
    }
}

// ---------------------------------------------------------------------------
extern "C" void kernel_launch(void* const* d_in, const int* in_sizes, int n_in,
                              void* d_out, int out_size)
{
    const float* X    = (const float*)d_in[0];
    const float* mask = (const float*)d_in[1];
    const int*   didx = (const int*)d_in[2];
    const float* Wq   = (const float*)d_in[3];
    const float* bq   = (const float*)d_in[4];
    const float* Wk   = (const float*)d_in[5];
    const float* bk   = (const float*)d_in[6];
    const float* Wv   = (const float*)d_in[7];
    const float* bv   = (const float*)d_in[8];
    const float* de   = (const float*)d_in[9];
    float* out = (float*)d_out;

    cudaFuncSetAttribute(flash_attn,
                         cudaFuncAttributeMaxDynamicSharedMemorySize,
                         FLASH_SMEM_BYTES);

    transpose_dist<<<(RV_ * NH_ + 255) / 256, 256>>>(de);
    qkv_proj<<<dim3(48, 64), 256>>>(X, Wq, bq, Wk, bk, Wv, bv);
    flash_attn<<<dim3(32, NH_, B_), 256, FLASH_SMEM_BYTES>>>(mask, didx, out);
}

// round 6
// speedup vs baseline: 1.5757x; 1.2882x over previous
#include <cuda_runtime.h>
#include <cuda_bf16.h>
#include <cstdint>

#define B_ 2
#define S_ 2048
#define H_ 1024
#define NH_ 16
#define DH_ 64
#define RV_ 4096

typedef unsigned long long u64;

// ---- packed f32x2 helpers ----
__device__ __forceinline__ u64 pk2(float lo, float hi) {
    u64 r; asm("mov.b64 %0, {%1, %2};" : "=l"(r) : "f"(lo), "f"(hi)); return r;
}
__device__ __forceinline__ void upk2(u64 v, float& lo, float& hi) {
    asm("mov.b64 {%0, %1}, %2;" : "=f"(lo), "=f"(hi) : "l"(v));
}
__device__ __forceinline__ void fma2(u64& d, u64 a, u64 b) {
    asm("fma.rn.f32x2 %0, %1, %2, %0;" : "+l"(d) : "l"(a), "l"(b));
}
__device__ __forceinline__ void mul2(u64& d, u64 a) {
    asm("mul.rn.f32x2 %0, %0, %1;" : "+l"(d) : "l"(a));
}

__device__ __forceinline__ uint32_t smem_u32(const void* p) {
    uint32_t a;
    asm("{ .reg .u64 t; cvta.to.shared.u64 t, %1; cvt.u32.u64 %0, t; }"
        : "=r"(a) : "l"(p));
    return a;
}
// ldmatrix x4 (non-transposed, b16)
__device__ __forceinline__ void ldm_x4(uint32_t* r, uint32_t addr) {
    asm volatile("ldmatrix.sync.aligned.m8n8.x4.shared.b16 {%0,%1,%2,%3}, [%4];"
                 : "=r"(r[0]), "=r"(r[1]), "=r"(r[2]), "=r"(r[3]) : "r"(addr));
}
// mma m16n8k16 row.col f32.bf16.bf16.f32
__device__ __forceinline__ void hmma(float* c, const uint32_t* a,
                                     uint32_t b0, uint32_t b1) {
    asm volatile(
        "mma.sync.aligned.m16n8k16.row.col.f32.bf16.bf16.f32 "
        "{%0,%1,%2,%3}, {%4,%5,%6,%7}, {%8,%9}, {%0,%1,%2,%3};"
        : "+f"(c[0]), "+f"(c[1]), "+f"(c[2]), "+f"(c[3])
        : "r"(a[0]), "r"(a[1]), "r"(a[2]), "r"(a[3]), "r"(b0), "r"(b1));
}

// Scratch (allocation-free contract: __device__ globals)
__device__ float g_q[(size_t)B_ * NH_ * S_ * DH_];
__device__ float g_k[(size_t)B_ * NH_ * S_ * DH_];
__device__ float g_v[(size_t)B_ * NH_ * S_ * DH_];
__device__ float g_dT[NH_ * RV_];                    // dist_emb transposed
__device__ __nv_bfloat16 g_xh[(size_t)4096 * 1024];  // X split hi/lo
__device__ __nv_bfloat16 g_xl[(size_t)4096 * 1024];
__device__ __nv_bfloat16 g_wh[(size_t)3 * 1024 * 1024];
__device__ __nv_bfloat16 g_wl[(size_t)3 * 1024 * 1024];

// ---------------------------------------------------------------------------
// Kernel 0: transpose dist_emb [4096,16] -> [16,4096]
// ---------------------------------------------------------------------------
__global__ void transpose_dist(const float* __restrict__ de) {
    int t = blockIdx.x * blockDim.x + threadIdx.x;
    if (t < RV_ * NH_) {
        int v = t / NH_;
        int h = t - v * NH_;
        g_dT[h * RV_ + v] = de[t];
    }
}

// ---------------------------------------------------------------------------
// bf16 split conversion: x = hi + lo
// ---------------------------------------------------------------------------
__global__ void cvt_x(const float* __restrict__ src) {
    int i = blockIdx.x * blockDim.x + threadIdx.x;   // over 1048576 float4s
    float4 v = ((const float4*)src)[i];
    __nv_bfloat16 h0 = __float2bfloat16(v.x), h1 = __float2bfloat16(v.y);
    __nv_bfloat16 h2 = __float2bfloat16(v.z), h3 = __float2bfloat16(v.w);
    __nv_bfloat16 l0 = __float2bfloat16(v.x - __bfloat162float(h0));
    __nv_bfloat16 l1 = __float2bfloat16(v.y - __bfloat162float(h1));
    __nv_bfloat16 l2 = __float2bfloat16(v.z - __bfloat162float(h2));
    __nv_bfloat16 l3 = __float2bfloat16(v.w - __bfloat162float(h3));
    ((__nv_bfloat162*)g_xh)[2 * i]     = __halves2bfloat162(h0, h1);
    ((__nv_bfloat162*)g_xh)[2 * i + 1] = __halves2bfloat162(h2, h3);
    ((__nv_bfloat162*)g_xl)[2 * i]     = __halves2bfloat162(l0, l1);
    ((__nv_bfloat162*)g_xl)[2 * i + 1] = __halves2bfloat162(l2, l3);
}
__global__ void cvt_w(const float* __restrict__ src, int w) {
    int i = blockIdx.x * blockDim.x + threadIdx.x;   // over 262144 float4s
    float4 v = ((const float4*)src)[i];
    __nv_bfloat16 h0 = __float2bfloat16(v.x), h1 = __float2bfloat16(v.y);
    __nv_bfloat16 h2 = __float2bfloat16(v.z), h3 = __float2bfloat16(v.w);
    __nv_bfloat16 l0 = __float2bfloat16(v.x - __bfloat162float(h0));
    __nv_bfloat16 l1 = __float2bfloat16(v.y - __bfloat162float(h1));
    __nv_bfloat16 l2 = __float2bfloat16(v.z - __bfloat162float(h2));
    __nv_bfloat16 l3 = __float2bfloat16(v.w - __bfloat162float(h3));
    __nv_bfloat162* dh = (__nv_bfloat162*)(g_wh + (size_t)w * 1048576);
    __nv_bfloat162* dl = (__nv_bfloat162*)(g_wl + (size_t)w * 1048576);
    dh[2 * i]     = __halves2bfloat162(h0, h1);
    dh[2 * i + 1] = __halves2bfloat162(h2, h3);
    dl[2 * i]     = __halves2bfloat162(l0, l1);
    dl[2 * i + 1] = __halves2bfloat162(l2, l3);
}

// ---------------------------------------------------------------------------
// Kernel 1: QKV projection via mma.sync (bf16 3-way split, fp32 accum).
//   CTA tile: M=128, N=64 (one head). 256 threads = 8 warps, warp w owns
//   rows w*16..w*16+15, all 64 cols. K-chunk 32, smem stride 40 bf16
//   (80B rows -> ldmatrix 8-row phases tile all 32 banks).
//   Grid: x = 48 (3 weights x 16 heads), y = 32 (m-tiles of 128).
// ---------------------------------------------------------------------------
#define SSTR 40
__global__ __launch_bounds__(256) void qkv_proj_hmma(
    const float* __restrict__ bq, const float* __restrict__ bk,
    const float* __restrict__ bv)
{
    __shared__ __align__(16) __nv_bfloat16 sAh[128 * SSTR];
    __shared__ __align__(16) __nv_bfloat16 sAl[128 * SSTR];
    __shared__ __align__(16) __nv_bfloat16 sBh[64 * SSTR];
    __shared__ __align__(16) __nv_bfloat16 sBl[64 * SSTR];

    const int w   = blockIdx.x >> 4;           // 0=Q,1=K,2=V
    const int h   = blockIdx.x & 15;
    const int n0  = h * 64;
    const int m0  = blockIdx.y * 128;
    const int tid = threadIdx.x;
    const int wid = tid >> 5;
    const int lane = tid & 31;

    const float* bias = (w == 0) ? bq : (w == 1) ? bk : bv;
    float* out        = (w == 0) ? g_q : (w == 1) ? g_k : g_v;
    const __nv_bfloat16* Wh = g_wh + (size_t)w * 1048576;
    const __nv_bfloat16* Wl = g_wl + (size_t)w * 1048576;

    float acc[8][4];
#pragma unroll
    for (int i = 0; i < 8; i++)
#pragma unroll
        for (int j = 0; j < 4; j++) acc[i][j] = 0.0f;

    // ldmatrix source addresses (fixed per thread, k16 offset added in loop)
    const uint32_t a_h_base = smem_u32(sAh);
    const uint32_t a_l_base = smem_u32(sAl);
    const uint32_t b_h_base = smem_u32(sBh);
    const uint32_t b_l_base = smem_u32(sBl);
    // A frag rows: row = wid*16 + (lane&15); k-half = (lane>>4)&1
    const uint32_t a_off = (uint32_t)(wid * 16 + (lane & 15)) * (SSTR * 2)
                         + ((lane >> 4) & 1) * 16;
    // B frag rows: nrow = (lane&7) + ((lane>>4)&1)*8 ; k-half = (lane>>3)&1
    const uint32_t b_off = (uint32_t)((lane & 7) + ((lane >> 4) & 1) * 8) * (SSTR * 2)
                         + ((lane >> 3) & 1) * 16;

    for (int kc = 0; kc < 32; kc++) {            // K chunks of 32
        __syncthreads();
        // Load A: 128 rows x 32 bf16 = 512 16B-units; 2 per thread (hi & lo)
#pragma unroll
        for (int rep = 0; rep < 2; rep++) {
            int u   = tid + rep * 256;
            int row = u >> 2, uc = u & 3;
            size_t go = (size_t)(m0 + row) * 1024 + kc * 32 + uc * 8;
            *(uint4*)&sAh[row * SSTR + uc * 8] = *(const uint4*)(g_xh + go);
            *(uint4*)&sAl[row * SSTR + uc * 8] = *(const uint4*)(g_xl + go);
        }
        // Load B: 64 rows x 32 bf16 = 256 units; 1 per thread (hi & lo)
        {
            int row = tid >> 2, uc = tid & 3;
            size_t go = (size_t)(n0 + row) * 1024 + kc * 32 + uc * 8;
            *(uint4*)&sBh[row * SSTR + uc * 8] = *(const uint4*)(Wh + go);
            *(uint4*)&sBl[row * SSTR + uc * 8] = *(const uint4*)(Wl + go);
        }
        __syncthreads();

#pragma unroll
        for (int k16 = 0; k16 < 2; k16++) {
            const uint32_t ko = k16 * 32;        // 16 bf16 = 32 bytes
            uint32_t ah[4], al[4];
            ldm_x4(ah, a_h_base + a_off + ko);
            ldm_x4(al, a_l_base + a_off + ko);
#pragma unroll
            for (int g = 0; g < 4; g++) {        // 2 n-tiles per group
                uint32_t bh[4], bl[4];
                uint32_t goff = (uint32_t)(g * 16) * (SSTR * 2);
                ldm_x4(bh, b_h_base + b_off + goff + ko);
                ldm_x4(bl, b_l_base + b_off + goff + ko);
                hmma(acc[2 * g],     ah, bh[0], bh[1]);
                hmma(acc[2 * g],     al, bh[0], bh[1]);
                hmma(acc[2 * g],     ah, bl[0], bl[1]);
                hmma(acc[2 * g + 1], ah, bh[2], bh[3]);
                hmma(acc[2 * g + 1], al, bh[2], bh[3]);
                hmma(acc[2 * g + 1], ah, bl[2], bl[3]);
            }
        }
    }

    // Epilogue: frag layout m16n8 -> lane holds rows (lane>>2, +8), cols 2*(lane&3)
    const int r0 = lane >> 2;
    const int c0 = (lane & 3) * 2;
#pragma unroll
    for (int nt = 0; nt < 8; nt++) {
        int col = nt * 8 + c0;
        float b0v = bias[n0 + col], b1v = bias[n0 + col + 1];
        int m  = m0 + wid * 16 + r0;
        int bb = m >> 11, s = m & (S_ - 1);
        float* p = out + (((size_t)bb * NH_ + h) * S_ + s) * DH_ + col;
        ((float2*)p)[0] = make_float2(acc[nt][0] + b0v, acc[nt][1] + b1v);
        m  = m0 + wid * 16 + r0 + 8;
        bb = m >> 11; s = m & (S_ - 1);
        p = out + (((size_t)bb * NH_ + h) * S_ + s) * DH_ + col;
        ((float2*)p)[0] = make_float2(acc[nt][2] + b0v, acc[nt][3] + b1v);
    }
}

// ---------------------------------------------------------------------------
// Kernel 2: flash attention with relative scalar bias (packed f32x2 GEMMs).
//   UNCHANGED from the passing R4 version.
// ---------------------------------------------------------------------------
#define PADF 68
#define FLASH_SMEM_FLOATS (64 * PADF * 4 + RV_ + 64)
#define FLASH_SMEM_BYTES  (FLASH_SMEM_FLOATS * 4)

__global__ __launch_bounds__(256, 2) void flash_attn(
    const float* __restrict__ mask,       // [B,1,1,S]
    const int*   __restrict__ dist_idx,   // [S,S]
    float*       __restrict__ out)        // [B,S,H]
{
    extern __shared__ float sm[];
    float* Qt      = sm;                    // [64][PADF]  Qt[d][m]
    float* Kt      = Qt + 64 * PADF;        // [64][PADF]  Kt[d][n]
    float* Ps      = Kt + 64 * PADF;        // [64][PADF]  Ps[n][m]
    float* Vs      = Ps + 64 * PADF;        // [64][PADF]  Vs[n][d]
    float* distcol = Vs + 64 * PADF;        // [4096]
    float* maskv   = distcol + RV_;         // [64]

    const int t  = threadIdx.x;
    const int tx = t & 15;
    const int ty = t >> 4;
    const int q0 = blockIdx.x * 64;
    const int h  = blockIdx.y;
    const int b  = blockIdx.z;
    const size_t base = ((size_t)b * NH_ + h) * S_;

    const int lr = t >> 2;           // 0..63: tile row
    const int lc = (t & 3) * 4;      // 0,4,8,12: base col segment

#pragma unroll
    for (int it = 0; it < 4; it++) {
        const int c = lc + 16 * it;
        float4 q4 = *(const float4*)(g_q + (base + q0 + lr) * DH_ + c);
        Qt[(c + 0) * PADF + lr] = q4.x;
        Qt[(c + 1) * PADF + lr] = q4.y;
        Qt[(c + 2) * PADF + lr] = q4.z;
        Qt[(c + 3) * PADF + lr] = q4.w;
    }
    for (int i = t; i < RV_; i += 256) distcol[i] = g_dT[h * RV_ + i];

    float m_r[4], l_r[4];
    u64 O2[4][2];
#pragma unroll
    for (int i = 0; i < 4; i++) {
        m_r[i] = -1e30f;
        l_r[i] = 0.0f;
        O2[i][0] = 0ull;
        O2[i][1] = 0ull;
    }

    for (int kt = 0; kt < 32; kt++) {
        const int k0 = kt * 64;
        __syncthreads();
#pragma unroll
        for (int it = 0; it < 4; it++) {
            const int c = lc + 16 * it;
            float4 k4 = *(const float4*)(g_k + (base + k0 + lr) * DH_ + c);
            Kt[(c + 0) * PADF + lr] = k4.x;
            Kt[(c + 1) * PADF + lr] = k4.y;
            Kt[(c + 2) * PADF + lr] = k4.z;
            Kt[(c + 3) * PADF + lr] = k4.w;
            float4 v4 = *(const float4*)(g_v + (base + k0 + lr) * DH_ + c);
            *(float4*)&Vs[lr * PADF + c] = v4;
        }
        if (t < 64) maskv[t] = mask[(size_t)b * S_ + k0 + t];
        __syncthreads();

        u64 s2[4][2];
#pragma unroll
        for (int i = 0; i < 4; i++) { s2[i][0] = 0ull; s2[i][1] = 0ull; }
#pragma unroll 8
        for (int d = 0; d < 64; d++) {
            float4 a4 = *(const float4*)&Qt[d * PADF + ty * 4];
            float4 k4 = *(const float4*)&Kt[d * PADF + tx * 4];
            u64 k01 = pk2(k4.x, k4.y);
            u64 k23 = pk2(k4.z, k4.w);
            u64 aa;
            aa = pk2(a4.x, a4.x); fma2(s2[0][0], aa, k01); fma2(s2[0][1], aa, k23);
            aa = pk2(a4.y, a4.y); fma2(s2[1][0], aa, k01); fma2(s2[1][1], aa, k23);
            aa = pk2(a4.z, a4.z); fma2(s2[2][0], aa, k01); fma2(s2[2][1], aa, k23);
            aa = pk2(a4.w, a4.w); fma2(s2[3][0], aa, k01); fma2(s2[3][1], aa, k23);
        }

        float s[4][4];
        float mk[4];
#pragma unroll
        for (int j = 0; j < 4; j++) mk[j] = maskv[tx * 4 + j];
#pragma unroll
        for (int i = 0; i < 4; i++) {
            upk2(s2[i][0], s[i][0], s[i][1]);
            upk2(s2[i][1], s[i][2], s[i][3]);
            int4 idx = *(const int4*)(dist_idx +
                        (size_t)(q0 + ty * 4 + i) * S_ + k0 + tx * 4);
            s[i][0] = s[i][0] * 0.125f + distcol[idx.x] + mk[0];
            s[i][1] = s[i][1] * 0.125f + distcol[idx.y] + mk[1];
            s[i][2] = s[i][2] * 0.125f + distcol[idx.z] + mk[2];
            s[i][3] = s[i][3] * 0.125f + distcol[idx.w] + mk[3];
        }

#pragma unroll
        for (int i = 0; i < 4; i++) {
            float v = fmaxf(fmaxf(s[i][0], s[i][1]), fmaxf(s[i][2], s[i][3]));
            v = fmaxf(v, __shfl_xor_sync(0xffffffffu, v, 1));
            v = fmaxf(v, __shfl_xor_sync(0xffffffffu, v, 2));
            v = fmaxf(v, __shfl_xor_sync(0xffffffffu, v, 4));
            v = fmaxf(v, __shfl_xor_sync(0xffffffffu, v, 8));
            float mn    = fmaxf(m_r[i], v);
            float scale = __expf(m_r[i] - mn);
            float rs = 0.0f;
#pragma unroll
            for (int j = 0; j < 4; j++) {
                float p = __expf(s[i][j] - mn);
                s[i][j] = p;
                rs += p;
            }
            rs += __shfl_xor_sync(0xffffffffu, rs, 1);
            rs += __shfl_xor_sync(0xffffffffu, rs, 2);
            rs += __shfl_xor_sync(0xffffffffu, rs, 4);
            rs += __shfl_xor_sync(0xffffffffu, rs, 8);
            l_r[i] = l_r[i] * scale + rs;
            m_r[i] = mn;
            u64 sc = pk2(scale, scale);
            mul2(O2[i][0], sc);
            mul2(O2[i][1], sc);
#pragma unroll
            for (int j = 0; j < 4; j++)
                Ps[(tx * 4 + j) * PADF + ty * 4 + i] = s[i][j];
        }
        __syncthreads();

#pragma unroll 8
        for (int n = 0; n < 64; n++) {
            float4 a4 = *(const float4*)&Ps[n * PADF + ty * 4];
            float4 v4 = *(const float4*)&Vs[n * PADF + tx * 4];
            u64 v01 = pk2(v4.x, v4.y);
            u64 v23 = pk2(v4.z, v4.w);
            u64 aa;
            aa = pk2(a4.x, a4.x); fma2(O2[0][0], aa, v01); fma2(O2[0][1], aa, v23);
            aa = pk2(a4.y, a4.y); fma2(O2[1][0], aa, v01); fma2(O2[1][1], aa, v23);
            aa = pk2(a4.z, a4.z); fma2(O2[2][0], aa, v01); fma2(O2[2][1], aa, v23);
            aa = pk2(a4.w, a4.w); fma2(O2[3][0], aa, v01); fma2(O2[3][1], aa, v23);
        }
    }

#pragma unroll
    for (int i = 0; i < 4; i++) {
        float inv = 1.0f / l_r[i];
        float4 o4;
        upk2(O2[i][0], o4.x, o4.y);
        upk2(O2[i][1], o4.z, o4.w);
        o4.x *= inv; o4.y *= inv; o4.z *= inv; o4.w *= inv;
        *(float4*)(out + ((size_t)b * S_ + q0 + ty * 4 + i) * H_
                       + h * DH_ + tx * 4) = o4;
    }
}

// ---------------------------------------------------------------------------
extern "C" void kernel_launch(void* const* d_in, const int* in_sizes, int n_in,
                              void* d_out, int out_size)
{
    const float* X    = (const float*)d_in[0];
    const float* mask = (const float*)d_in[1];
    const int*   didx = (const int*)d_in[2];
    const float* Wq   = (const float*)d_in[3];
    const float* bq   = (const float*)d_in[4];
    const float* Wk   = (const float*)d_in[5];
    const float* bk   = (const float*)d_in[6];
    const float* Wv   = (const float*)d_in[7];
    const float* bv   = (const float*)d_in[8];
    const float* de   = (const float*)d_in[9];
    float* out = (float*)d_out;

    cudaFuncSetAttribute(flash_attn,
                         cudaFuncAttributeMaxDynamicSharedMemorySize,
                         FLASH_SMEM_BYTES);

    transpose_dist<<<(RV_ * NH_ + 255) / 256, 256>>>(de);
    cvt_x<<<4096, 256>>>(X);
    cvt_w<<<1024, 256>>>(Wq, 0);
    cvt_w<<<1024, 256>>>(Wk, 1);
    cvt_w<<<1024, 256>>>(Wv, 2);
    qkv_proj_hmma<<<dim3(48, 32), 256>>>(bq, bk, bv);
    flash_attn<<<dim3(32, NH_, B_), 256, FLASH_SMEM_BYTES>>>(mask, didx, out);
}

// round 7
// speedup vs baseline: 2.6684x; 1.6935x over previous
#include <cuda_runtime.h>
#include <cuda_bf16.h>
#include <cstdint>

#define B_ 2
#define S_ 2048
#define H_ 1024
#define NH_ 16
#define DH_ 64
#define RV_ 4096

__device__ __forceinline__ uint32_t smem_u32(const void* p) {
    uint32_t a;
    asm("{ .reg .u64 t; cvta.to.shared.u64 t, %1; cvt.u32.u64 %0, t; }"
        : "=r"(a) : "l"(p));
    return a;
}
__device__ __forceinline__ void ldm_x4(uint32_t* r, uint32_t addr) {
    asm volatile("ldmatrix.sync.aligned.m8n8.x4.shared.b16 {%0,%1,%2,%3}, [%4];"
                 : "=r"(r[0]), "=r"(r[1]), "=r"(r[2]), "=r"(r[3]) : "r"(addr));
}
__device__ __forceinline__ void ldm_x4_t(uint32_t* r, uint32_t addr) {
    asm volatile("ldmatrix.sync.aligned.m8n8.x4.trans.shared.b16 {%0,%1,%2,%3}, [%4];"
                 : "=r"(r[0]), "=r"(r[1]), "=r"(r[2]), "=r"(r[3]) : "r"(addr));
}
__device__ __forceinline__ void hmma(float* c, const uint32_t* a,
                                     uint32_t b0, uint32_t b1) {
    asm volatile(
        "mma.sync.aligned.m16n8k16.row.col.f32.bf16.bf16.f32 "
        "{%0,%1,%2,%3}, {%4,%5,%6,%7}, {%8,%9}, {%0,%1,%2,%3};"
        : "+f"(c[0]), "+f"(c[1]), "+f"(c[2]), "+f"(c[3])
        : "r"(a[0]), "r"(a[1]), "r"(a[2]), "r"(a[3]), "r"(b0), "r"(b1));
}
// pack (x -> lo half, y -> hi half)
__device__ __forceinline__ uint32_t bfpair(float x, float y) {
    uint32_t r;
    asm("cvt.rn.bf16x2.f32 %0, %1, %2;" : "=r"(r) : "f"(y), "f"(x));
    return r;
}
__device__ __forceinline__ uint32_t bfpair_lo(float x, float y, uint32_t h) {
    float hx = __uint_as_float(h << 16);
    float hy = __uint_as_float(h & 0xffff0000u);
    return bfpair(x - hx, y - hy);
}

// Scratch (allocation-free contract: __device__ globals)
__device__ float g_dT[NH_ * RV_];
__device__ __nv_bfloat16 g_xh[(size_t)4096 * 1024];
__device__ __nv_bfloat16 g_xl[(size_t)4096 * 1024];
__device__ __nv_bfloat16 g_wh[(size_t)3 * 1024 * 1024];
__device__ __nv_bfloat16 g_wl[(size_t)3 * 1024 * 1024];
// Q/K/V in bf16 hi/lo split, layout [B, NH, S, DH]
__device__ __nv_bfloat16 g_qh[(size_t)B_ * NH_ * S_ * DH_];
__device__ __nv_bfloat16 g_ql[(size_t)B_ * NH_ * S_ * DH_];
__device__ __nv_bfloat16 g_kh[(size_t)B_ * NH_ * S_ * DH_];
__device__ __nv_bfloat16 g_kl[(size_t)B_ * NH_ * S_ * DH_];
__device__ __nv_bfloat16 g_vh[(size_t)B_ * NH_ * S_ * DH_];
__device__ __nv_bfloat16 g_vl[(size_t)B_ * NH_ * S_ * DH_];

// ---------------------------------------------------------------------------
__global__ void transpose_dist(const float* __restrict__ de) {
    int t = blockIdx.x * blockDim.x + threadIdx.x;
    if (t < RV_ * NH_) {
        int v = t / NH_;
        int h = t - v * NH_;
        g_dT[h * RV_ + v] = de[t];
    }
}

// bf16 split conversion of X and W
__global__ void cvt_x(const float* __restrict__ src) {
    int i = blockIdx.x * blockDim.x + threadIdx.x;
    float4 v = ((const float4*)src)[i];
    uint32_t h0 = bfpair(v.x, v.y), h1 = bfpair(v.z, v.w);
    uint32_t l0 = bfpair_lo(v.x, v.y, h0), l1 = bfpair_lo(v.z, v.w, h1);
    ((uint32_t*)g_xh)[2 * i] = h0; ((uint32_t*)g_xh)[2 * i + 1] = h1;
    ((uint32_t*)g_xl)[2 * i] = l0; ((uint32_t*)g_xl)[2 * i + 1] = l1;
}
__global__ void cvt_w(const float* __restrict__ src, int w) {
    int i = blockIdx.x * blockDim.x + threadIdx.x;
    float4 v = ((const float4*)src)[i];
    uint32_t h0 = bfpair(v.x, v.y), h1 = bfpair(v.z, v.w);
    uint32_t l0 = bfpair_lo(v.x, v.y, h0), l1 = bfpair_lo(v.z, v.w, h1);
    uint32_t* dh = (uint32_t*)(g_wh + (size_t)w * 1048576);
    uint32_t* dl = (uint32_t*)(g_wl + (size_t)w * 1048576);
    dh[2 * i] = h0; dh[2 * i + 1] = h1;
    dl[2 * i] = l0; dl[2 * i + 1] = l1;
}

// ---------------------------------------------------------------------------
// Kernel 1: QKV projection via mma.sync (bf16 3-way split, fp32 accum).
//   Epilogue writes bf16 hi/lo Q/K/V directly.
// ---------------------------------------------------------------------------
#define SSTR 40
__global__ __launch_bounds__(256) void qkv_proj_hmma(
    const float* __restrict__ bq, const float* __restrict__ bk,
    const float* __restrict__ bv)
{
    __shared__ __align__(16) __nv_bfloat16 sAh[128 * SSTR];
    __shared__ __align__(16) __nv_bfloat16 sAl[128 * SSTR];
    __shared__ __align__(16) __nv_bfloat16 sBh[64 * SSTR];
    __shared__ __align__(16) __nv_bfloat16 sBl[64 * SSTR];

    const int w   = blockIdx.x >> 4;
    const int h   = blockIdx.x & 15;
    const int n0  = h * 64;
    const int m0  = blockIdx.y * 128;
    const int tid = threadIdx.x;
    const int wid = tid >> 5;
    const int lane = tid & 31;

    const float* bias = (w == 0) ? bq : (w == 1) ? bk : bv;
    __nv_bfloat16* oh = (w == 0) ? g_qh : (w == 1) ? g_kh : g_vh;
    __nv_bfloat16* ol = (w == 0) ? g_ql : (w == 1) ? g_kl : g_vl;
    const __nv_bfloat16* Wh = g_wh + (size_t)w * 1048576;
    const __nv_bfloat16* Wl = g_wl + (size_t)w * 1048576;

    float acc[8][4];
#pragma unroll
    for (int i = 0; i < 8; i++)
#pragma unroll
        for (int j = 0; j < 4; j++) acc[i][j] = 0.0f;

    const uint32_t a_h_base = smem_u32(sAh);
    const uint32_t a_l_base = smem_u32(sAl);
    const uint32_t b_h_base = smem_u32(sBh);
    const uint32_t b_l_base = smem_u32(sBl);
    const uint32_t a_off = (uint32_t)(wid * 16 + (lane & 15)) * (SSTR * 2)
                         + ((lane >> 4) & 1) * 16;
    const uint32_t b_off = (uint32_t)((lane & 7) + ((lane >> 4) & 1) * 8) * (SSTR * 2)
                         + ((lane >> 3) & 1) * 16;

    for (int kc = 0; kc < 32; kc++) {
        __syncthreads();
#pragma unroll
        for (int rep = 0; rep < 2; rep++) {
            int u   = tid + rep * 256;
            int row = u >> 2, uc = u & 3;
            size_t go = (size_t)(m0 + row) * 1024 + kc * 32 + uc * 8;
            *(uint4*)&sAh[row * SSTR + uc * 8] = *(const uint4*)(g_xh + go);
            *(uint4*)&sAl[row * SSTR + uc * 8] = *(const uint4*)(g_xl + go);
        }
        {
            int row = tid >> 2, uc = tid & 3;
            size_t go = (size_t)(n0 + row) * 1024 + kc * 32 + uc * 8;
            *(uint4*)&sBh[row * SSTR + uc * 8] = *(const uint4*)(Wh + go);
            *(uint4*)&sBl[row * SSTR + uc * 8] = *(const uint4*)(Wl + go);
        }
        __syncthreads();

#pragma unroll
        for (int k16 = 0; k16 < 2; k16++) {
            const uint32_t ko = k16 * 32;
            uint32_t ah[4], al[4];
            ldm_x4(ah, a_h_base + a_off + ko);
            ldm_x4(al, a_l_base + a_off + ko);
#pragma unroll
            for (int g = 0; g < 4; g++) {
                uint32_t bh[4], bl[4];
                uint32_t goff = (uint32_t)(g * 16) * (SSTR * 2);
                ldm_x4(bh, b_h_base + b_off + goff + ko);
                ldm_x4(bl, b_l_base + b_off + goff + ko);
                hmma(acc[2 * g],     ah, bh[0], bh[1]);
                hmma(acc[2 * g],     al, bh[0], bh[1]);
                hmma(acc[2 * g],     ah, bl[0], bl[1]);
                hmma(acc[2 * g + 1], ah, bh[2], bh[3]);
                hmma(acc[2 * g + 1], al, bh[2], bh[3]);
                hmma(acc[2 * g + 1], ah, bl[2], bl[3]);
            }
        }
    }

    // Epilogue: bias add, split to bf16 hi/lo, write [B,NH,S,DH]
    const int r0 = lane >> 2;
    const int c0 = (lane & 3) * 2;
#pragma unroll
    for (int nt = 0; nt < 8; nt++) {
        int col = nt * 8 + c0;
        float b0v = bias[n0 + col], b1v = bias[n0 + col + 1];

        int m  = m0 + wid * 16 + r0;
        int bb = m >> 11, s = m & (S_ - 1);
        size_t idx = (((size_t)bb * NH_ + h) * S_ + s) * DH_ + col;
        float v0 = acc[nt][0] + b0v, v1 = acc[nt][1] + b1v;
        uint32_t hp = bfpair(v0, v1);
        *(uint32_t*)(oh + idx) = hp;
        *(uint32_t*)(ol + idx) = bfpair_lo(v0, v1, hp);

        m  = m0 + wid * 16 + r0 + 8;
        bb = m >> 11; s = m & (S_ - 1);
        idx = (((size_t)bb * NH_ + h) * S_ + s) * DH_ + col;
        v0 = acc[nt][2] + b0v; v1 = acc[nt][3] + b1v;
        hp = bfpair(v0, v1);
        *(uint32_t*)(oh + idx) = hp;
        *(uint32_t*)(ol + idx) = bfpair_lo(v0, v1, hp);
    }
}

// ---------------------------------------------------------------------------
// Kernel 2: flash attention on mma.sync (bf16 3-way split, fp32 accum).
//   BM=128, BN=64, DH=64. 256 threads = 8 warps; warp owns 16 q-rows.
//   Smem stride 72 bf16 (144B rows; conflict-free ldmatrix).
// ---------------------------------------------------------------------------
#define SQ 72
#define SQB (SQ * 2)            // 144 bytes/row
#define O_QH 0
#define O_QL (O_QH + 128 * SQB)            // 18432
#define O_KH (O_QL + 128 * SQB)            // 36864
#define O_KL (O_KH + 64 * SQB)             // 46080
#define O_VH (O_KL + 64 * SQB)             // 55296
#define O_VL (O_VH + 64 * SQB)             // 64512
#define O_DIST (O_VL + 64 * SQB)           // 73728
#define O_MASK (O_DIST + RV_ * 4)          // 90112
#define FLASH_SMEM (O_MASK + 64 * 4)       // 90368

__global__ __launch_bounds__(256) void flash_hmma(
    const float* __restrict__ mask,       // [B,1,1,S]
    const int*   __restrict__ dist_idx,   // [S,S]
    float*       __restrict__ out)        // [B,S,H]
{
    extern __shared__ char fsm[];
    float* distcol = (float*)(fsm + O_DIST);
    float* maskv   = (float*)(fsm + O_MASK);
    const uint32_t sb  = smem_u32(fsm);
    const uint32_t sQh = sb + O_QH, sQl = sb + O_QL;
    const uint32_t sKh = sb + O_KH, sKl = sb + O_KL;
    const uint32_t sVh = sb + O_VH, sVl = sb + O_VL;

    const int tid  = threadIdx.x;
    const int wid  = tid >> 5;
    const int lane = tid & 31;
    const int q0 = blockIdx.x * 128;
    const int h  = blockIdx.y;
    const int b  = blockIdx.z;
    const size_t base = ((size_t)b * NH_ + h) * S_;

    // Load Q tile hi/lo (128 rows x 64 bf16)
#pragma unroll
    for (int rep = 0; rep < 4; rep++) {
        int u = tid + rep * 256;
        int row = u >> 3, uc = u & 7;
        size_t go = (base + q0 + row) * DH_ + uc * 8;
        *(uint4*)(fsm + O_QH + row * SQB + uc * 16) = *(const uint4*)(g_qh + go);
        *(uint4*)(fsm + O_QL + row * SQB + uc * 16) = *(const uint4*)(g_ql + go);
    }
    for (int i = tid; i < RV_; i += 256) distcol[i] = g_dT[h * RV_ + i];

    // per-lane fragment addresses
    const uint32_t a_off = (uint32_t)(wid * 16 + (lane & 15)) * SQB
                         + ((lane >> 4) & 1) * 16;
    const uint32_t b_off = (uint32_t)((lane & 7) + ((lane >> 4) & 1) * 8) * SQB
                         + ((lane >> 3) & 1) * 16;
    const int v_m = lane >> 3, v_r = lane & 7;
    const uint32_t v_off = (uint32_t)((v_m & 1) * 8 + v_r) * SQB + (v_m >> 1) * 16;

    const int r_q = lane >> 2;           // row within warp m16
    const int c_q = (lane & 3) * 2;      // col pair base within n8

    float m_t = -1e30f, m_b = -1e30f, l_t = 0.0f, l_b = 0.0f;
    float O[8][4];
#pragma unroll
    for (int i = 0; i < 8; i++)
#pragma unroll
        for (int j = 0; j < 4; j++) O[i][j] = 0.0f;

    const int qrt = q0 + wid * 16 + r_q;     // global q row (top)
    const int qrb = qrt + 8;

    for (int kt = 0; kt < 32; kt++) {
        const int k0 = kt * 64;
        __syncthreads();
        // load K,V hi/lo tiles (64 rows x 64 bf16 each)
#pragma unroll
        for (int rep = 0; rep < 2; rep++) {
            int u = tid + rep * 256;
            int row = u >> 3, uc = u & 7;
            size_t go = (base + k0 + row) * DH_ + uc * 8;
            uint32_t so = row * SQB + uc * 16;
            *(uint4*)(fsm + O_KH + so) = *(const uint4*)(g_kh + go);
            *(uint4*)(fsm + O_KL + so) = *(const uint4*)(g_kl + go);
            *(uint4*)(fsm + O_VH + so) = *(const uint4*)(g_vh + go);
            *(uint4*)(fsm + O_VL + so) = *(const uint4*)(g_vl + go);
        }
        if (tid < 64) maskv[tid] = mask[(size_t)b * S_ + k0 + tid];
        __syncthreads();

        // ---- S = Q K^T ----
        float sfr[8][4];
#pragma unroll
        for (int i = 0; i < 8; i++)
#pragma unroll
            for (int j = 0; j < 4; j++) sfr[i][j] = 0.0f;

#pragma unroll
        for (int kk = 0; kk < 4; kk++) {
            const uint32_t ko = kk * 32;
            uint32_t ah[4], al[4];
            ldm_x4(ah, sQh + a_off + ko);
            ldm_x4(al, sQl + a_off + ko);
#pragma unroll
            for (int np = 0; np < 4; np++) {
                uint32_t bh[4], bl[4];
                uint32_t noff = (uint32_t)np * 16 * SQB;
                ldm_x4(bh, sKh + b_off + noff + ko);
                ldm_x4(bl, sKl + b_off + noff + ko);
                hmma(sfr[2 * np],     ah, bh[0], bh[1]);
                hmma(sfr[2 * np],     al, bh[0], bh[1]);
                hmma(sfr[2 * np],     ah, bl[0], bl[1]);
                hmma(sfr[2 * np + 1], ah, bh[2], bh[3]);
                hmma(sfr[2 * np + 1], al, bh[2], bh[3]);
                hmma(sfr[2 * np + 1], ah, bl[2], bl[3]);
            }
        }

        // ---- scale + bias + mask ----
#pragma unroll
        for (int nt = 0; nt < 8; nt++) {
            int c = nt * 8 + c_q;
            int2 it = *(const int2*)(dist_idx + (size_t)qrt * S_ + k0 + c);
            int2 ib = *(const int2*)(dist_idx + (size_t)qrb * S_ + k0 + c);
            float mk0 = maskv[c], mk1 = maskv[c + 1];
            sfr[nt][0] = sfr[nt][0] * 0.125f + distcol[it.x] + mk0;
            sfr[nt][1] = sfr[nt][1] * 0.125f + distcol[it.y] + mk1;
            sfr[nt][2] = sfr[nt][2] * 0.125f + distcol[ib.x] + mk0;
            sfr[nt][3] = sfr[nt][3] * 0.125f + distcol[ib.y] + mk1;
        }

        // ---- online softmax (rows r_q and r_q+8) ----
        float vt = -1e30f, vb = -1e30f;
#pragma unroll
        for (int nt = 0; nt < 8; nt++) {
            vt = fmaxf(vt, fmaxf(sfr[nt][0], sfr[nt][1]));
            vb = fmaxf(vb, fmaxf(sfr[nt][2], sfr[nt][3]));
        }
        vt = fmaxf(vt, __shfl_xor_sync(0xffffffffu, vt, 1));
        vt = fmaxf(vt, __shfl_xor_sync(0xffffffffu, vt, 2));
        vb = fmaxf(vb, __shfl_xor_sync(0xffffffffu, vb, 1));
        vb = fmaxf(vb, __shfl_xor_sync(0xffffffffu, vb, 2));
        float mnt = fmaxf(m_t, vt), mnb = fmaxf(m_b, vb);
        float sct = __expf(m_t - mnt), scb = __expf(m_b - mnb);
        float rst = 0.0f, rsb = 0.0f;
#pragma unroll
        for (int nt = 0; nt < 8; nt++) {
            sfr[nt][0] = __expf(sfr[nt][0] - mnt);
            sfr[nt][1] = __expf(sfr[nt][1] - mnt);
            sfr[nt][2] = __expf(sfr[nt][2] - mnb);
            sfr[nt][3] = __expf(sfr[nt][3] - mnb);
            rst += sfr[nt][0] + sfr[nt][1];
            rsb += sfr[nt][2] + sfr[nt][3];
        }
        rst += __shfl_xor_sync(0xffffffffu, rst, 1);
        rst += __shfl_xor_sync(0xffffffffu, rst, 2);
        rsb += __shfl_xor_sync(0xffffffffu, rsb, 1);
        rsb += __shfl_xor_sync(0xffffffffu, rsb, 2);
        l_t = l_t * sct + rst;
        l_b = l_b * scb + rsb;
        m_t = mnt; m_b = mnb;
#pragma unroll
        for (int nt = 0; nt < 8; nt++) {
            O[nt][0] *= sct; O[nt][1] *= sct;
            O[nt][2] *= scb; O[nt][3] *= scb;
        }

        // ---- O += P V (per 16-wide kv chunk) ----
#pragma unroll
        for (int kk = 0; kk < 4; kk++) {
            uint32_t aph[4], apl[4];
            aph[0] = bfpair(sfr[2 * kk][0], sfr[2 * kk][1]);
            apl[0] = bfpair_lo(sfr[2 * kk][0], sfr[2 * kk][1], aph[0]);
            aph[1] = bfpair(sfr[2 * kk][2], sfr[2 * kk][3]);
            apl[1] = bfpair_lo(sfr[2 * kk][2], sfr[2 * kk][3], aph[1]);
            aph[2] = bfpair(sfr[2 * kk + 1][0], sfr[2 * kk + 1][1]);
            apl[2] = bfpair_lo(sfr[2 * kk + 1][0], sfr[2 * kk + 1][1], aph[2]);
            aph[3] = bfpair(sfr[2 * kk + 1][2], sfr[2 * kk + 1][3]);
            apl[3] = bfpair_lo(sfr[2 * kk + 1][2], sfr[2 * kk + 1][3], aph[3]);
#pragma unroll
            for (int np = 0; np < 4; np++) {
                uint32_t vh[4], vl[4];
                uint32_t va = v_off + (uint32_t)kk * 16 * SQB + np * 32;
                ldm_x4_t(vh, sVh + va);
                ldm_x4_t(vl, sVl + va);
                hmma(O[2 * np],     aph, vh[0], vh[1]);
                hmma(O[2 * np],     apl, vh[0], vh[1]);
                hmma(O[2 * np],     aph, vl[0], vl[1]);
                hmma(O[2 * np + 1], aph, vh[2], vh[3]);
                hmma(O[2 * np + 1], apl, vh[2], vh[3]);
                hmma(O[2 * np + 1], aph, vl[2], vl[3]);
            }
        }
    }

    // ---- epilogue: normalize + write [B,S,H] ----
    float ilt = 1.0f / l_t, ilb = 1.0f / l_b;
#pragma unroll
    for (int nt = 0; nt < 8; nt++) {
        int c = nt * 8 + c_q;
        float* pt = out + ((size_t)b * S_ + qrt) * H_ + h * DH_ + c;
        ((float2*)pt)[0] = make_float2(O[nt][0] * ilt, O[nt][1] * ilt);
        float* pb = out + ((size_t)b * S_ + qrb) * H_ + h * DH_ + c;
        ((float2*)pb)[0] = make_float2(O[nt][2] * ilb, O[nt][3] * ilb);
    }
}

// ---------------------------------------------------------------------------
extern "C" void kernel_launch(void* const* d_in, const int* in_sizes, int n_in,
                              void* d_out, int out_size)
{
    const float* X    = (const float*)d_in[0];
    const float* mask = (const float*)d_in[1];
    const int*   didx = (const int*)d_in[2];
    const float* Wq   = (const float*)d_in[3];
    const float* bq   = (const float*)d_in[4];
    const float* Wk   = (const float*)d_in[5];
    const float* bk   = (const float*)d_in[6];
    const float* Wv   = (const float*)d_in[7];
    const float* bv   = (const float*)d_in[8];
    const float* de   = (const float*)d_in[9];
    float* out = (float*)d_out;

    cudaFuncSetAttribute(flash_hmma,
                         cudaFuncAttributeMaxDynamicSharedMemorySize,
                         FLASH_SMEM);

    transpose_dist<<<(RV_ * NH_ + 255) / 256, 256>>>(de);
    cvt_x<<<4096, 256>>>(X);
    cvt_w<<<1024, 256>>>(Wq, 0);
    cvt_w<<<1024, 256>>>(Wk, 1);
    cvt_w<<<1024, 256>>>(Wv, 2);
    qkv_proj_hmma<<<dim3(48, 32), 256>>>(bq, bk, bv);
    flash_hmma<<<dim3(16, NH_, B_), 256, FLASH_SMEM>>>(mask, didx, out);
}

// round 8
// speedup vs baseline: 2.8528x; 1.0691x over previous
#include <cuda_runtime.h>
#include <cuda_bf16.h>
#include <cstdint>

#define B_ 2
#define S_ 2048
#define H_ 1024
#define NH_ 16
#define DH_ 64
#define RV_ 4096

__device__ __forceinline__ uint32_t smem_u32(const void* p) {
    uint32_t a;
    asm("{ .reg .u64 t; cvta.to.shared.u64 t, %1; cvt.u32.u64 %0, t; }"
        : "=r"(a) : "l"(p));
    return a;
}
__device__ __forceinline__ void ldm_x4(uint32_t* r, uint32_t addr) {
    asm volatile("ldmatrix.sync.aligned.m8n8.x4.shared.b16 {%0,%1,%2,%3}, [%4];"
                 : "=r"(r[0]), "=r"(r[1]), "=r"(r[2]), "=r"(r[3]) : "r"(addr));
}
__device__ __forceinline__ void ldm_x4_t(uint32_t* r, uint32_t addr) {
    asm volatile("ldmatrix.sync.aligned.m8n8.x4.trans.shared.b16 {%0,%1,%2,%3}, [%4];"
                 : "=r"(r[0]), "=r"(r[1]), "=r"(r[2]), "=r"(r[3]) : "r"(addr));
}
__device__ __forceinline__ void hmma(float* c, const uint32_t* a,
                                     uint32_t b0, uint32_t b1) {
    asm volatile(
        "mma.sync.aligned.m16n8k16.row.col.f32.bf16.bf16.f32 "
        "{%0,%1,%2,%3}, {%4,%5,%6,%7}, {%8,%9}, {%0,%1,%2,%3};"
        : "+f"(c[0]), "+f"(c[1]), "+f"(c[2]), "+f"(c[3])
        : "r"(a[0]), "r"(a[1]), "r"(a[2]), "r"(a[3]), "r"(b0), "r"(b1));
}
__device__ __forceinline__ uint32_t bfpair(float x, float y) {
    uint32_t r;
    asm("cvt.rn.bf16x2.f32 %0, %1, %2;" : "=r"(r) : "f"(y), "f"(x));
    return r;
}
__device__ __forceinline__ uint32_t bfpair_lo(float x, float y, uint32_t h) {
    float hx = __uint_as_float(h << 16);
    float hy = __uint_as_float(h & 0xffff0000u);
    return bfpair(x - hx, y - hy);
}
// cp.async helpers (sm_80 PTX, valid under compute_103)
__device__ __forceinline__ void cpa16(uint32_t dst, const void* src) {
    asm volatile("cp.async.cg.shared.global [%0], [%1], 16;"
                 :: "r"(dst), "l"(src));
}
__device__ __forceinline__ void cpa_commit() {
    asm volatile("cp.async.commit_group;" ::: "memory");
}
__device__ __forceinline__ void cpa_wait0() {
    asm volatile("cp.async.wait_group 0;" ::: "memory");
}

// Scratch (allocation-free contract: __device__ globals)
__device__ float g_dT[NH_ * RV_];
__device__ __nv_bfloat16 g_xh[(size_t)4096 * 1024];
__device__ __nv_bfloat16 g_xl[(size_t)4096 * 1024];
__device__ __nv_bfloat16 g_wh[(size_t)3 * 1024 * 1024];
__device__ __nv_bfloat16 g_wl[(size_t)3 * 1024 * 1024];
__device__ __nv_bfloat16 g_qh[(size_t)B_ * NH_ * S_ * DH_];
__device__ __nv_bfloat16 g_ql[(size_t)B_ * NH_ * S_ * DH_];
__device__ __nv_bfloat16 g_kh[(size_t)B_ * NH_ * S_ * DH_];
__device__ __nv_bfloat16 g_kl[(size_t)B_ * NH_ * S_ * DH_];
__device__ __nv_bfloat16 g_vh[(size_t)B_ * NH_ * S_ * DH_];
__device__ __nv_bfloat16 g_vl[(size_t)B_ * NH_ * S_ * DH_];

// ---------------------------------------------------------------------------
__global__ void transpose_dist(const float* __restrict__ de) {
    int t = blockIdx.x * blockDim.x + threadIdx.x;
    if (t < RV_ * NH_) {
        int v = t / NH_;
        int h = t - v * NH_;
        g_dT[h * RV_ + v] = de[t];
    }
}

__global__ void cvt_x(const float* __restrict__ src) {
    int i = blockIdx.x * blockDim.x + threadIdx.x;
    float4 v = ((const float4*)src)[i];
    uint32_t h0 = bfpair(v.x, v.y), h1 = bfpair(v.z, v.w);
    uint32_t l0 = bfpair_lo(v.x, v.y, h0), l1 = bfpair_lo(v.z, v.w, h1);
    ((uint32_t*)g_xh)[2 * i] = h0; ((uint32_t*)g_xh)[2 * i + 1] = h1;
    ((uint32_t*)g_xl)[2 * i] = l0; ((uint32_t*)g_xl)[2 * i + 1] = l1;
}
__global__ void cvt_w(const float* __restrict__ src, int w) {
    int i = blockIdx.x * blockDim.x + threadIdx.x;
    float4 v = ((const float4*)src)[i];
    uint32_t h0 = bfpair(v.x, v.y), h1 = bfpair(v.z, v.w);
    uint32_t l0 = bfpair_lo(v.x, v.y, h0), l1 = bfpair_lo(v.z, v.w, h1);
    uint32_t* dh = (uint32_t*)(g_wh + (size_t)w * 1048576);
    uint32_t* dl = (uint32_t*)(g_wl + (size_t)w * 1048576);
    dh[2 * i] = h0; dh[2 * i + 1] = h1;
    dl[2 * i] = l0; dl[2 * i + 1] = l1;
}

// ---------------------------------------------------------------------------
// Kernel 1: QKV projection via mma.sync, cp.async double-buffered.
//   Stage layout (bytes): AH 0 (10240), AL 10240, BH 20480 (5120), BL 25600.
// ---------------------------------------------------------------------------
#define SSTR 40
#define PSTG 30720
#define PROJ_SMEM (2 * PSTG)

__global__ __launch_bounds__(256) void qkv_proj_hmma(
    const float* __restrict__ bq, const float* __restrict__ bk,
    const float* __restrict__ bv)
{
    extern __shared__ char psm[];
    const uint32_t sb = smem_u32(psm);

    const int w   = blockIdx.x >> 4;
    const int h   = blockIdx.x & 15;
    const int n0  = h * 64;
    const int m0  = blockIdx.y * 128;
    const int tid = threadIdx.x;
    const int wid = tid >> 5;
    const int lane = tid & 31;

    const float* bias = (w == 0) ? bq : (w == 1) ? bk : bv;
    __nv_bfloat16* oh = (w == 0) ? g_qh : (w == 1) ? g_kh : g_vh;
    __nv_bfloat16* ol = (w == 0) ? g_ql : (w == 1) ? g_kl : g_vl;
    const __nv_bfloat16* Wh = g_wh + (size_t)w * 1048576;
    const __nv_bfloat16* Wl = g_wl + (size_t)w * 1048576;

    float acc[8][4];
#pragma unroll
    for (int i = 0; i < 8; i++)
#pragma unroll
        for (int j = 0; j < 4; j++) acc[i][j] = 0.0f;

    const uint32_t a_off = (uint32_t)(wid * 16 + (lane & 15)) * (SSTR * 2)
                         + ((lane >> 4) & 1) * 16;
    const uint32_t b_off = (uint32_t)((lane & 7) + ((lane >> 4) & 1) * 8) * (SSTR * 2)
                         + ((lane >> 3) & 1) * 16;

    // per-thread prefetch coords
    const int arow0 = tid >> 2, auc = tid & 3;          // A rep 0 (rows 0..63)
    const int brow  = tid >> 2, buc = tid & 3;          // B

    // prefetch chunk 0 -> stage 0
    {
        uint32_t dst = sb;
#pragma unroll
        for (int rep = 0; rep < 2; rep++) {
            int row = arow0 + rep * 64;
            size_t go = (size_t)(m0 + row) * 1024 + auc * 8;
            uint32_t so = row * (SSTR * 2) + auc * 16;
            cpa16(dst + so,        g_xh + go);
            cpa16(dst + 10240 + so, g_xl + go);
        }
        size_t go = (size_t)(n0 + brow) * 1024 + buc * 8;
        uint32_t so = brow * (SSTR * 2) + buc * 16;
        cpa16(dst + 20480 + so, Wh + go);
        cpa16(dst + 25600 + so, Wl + go);
        cpa_commit();
    }

    for (int kc = 0; kc < 32; kc++) {
        const uint32_t cur = sb + (kc & 1) * PSTG;
        cpa_wait0();
        __syncthreads();
        if (kc < 31) {
            uint32_t dst = sb + ((kc + 1) & 1) * PSTG;
            int kn = (kc + 1) * 32;
#pragma unroll
            for (int rep = 0; rep < 2; rep++) {
                int row = arow0 + rep * 64;
                size_t go = (size_t)(m0 + row) * 1024 + kn + auc * 8;
                uint32_t so = row * (SSTR * 2) + auc * 16;
                cpa16(dst + so,         g_xh + go);
                cpa16(dst + 10240 + so, g_xl + go);
            }
            size_t go = (size_t)(n0 + brow) * 1024 + kn + buc * 8;
            uint32_t so = brow * (SSTR * 2) + buc * 16;
            cpa16(dst + 20480 + so, Wh + go);
            cpa16(dst + 25600 + so, Wl + go);
            cpa_commit();
        }

#pragma unroll
        for (int k16 = 0; k16 < 2; k16++) {
            const uint32_t ko = k16 * 32;
            uint32_t ah[4], al[4];
            ldm_x4(ah, cur + a_off + ko);
            ldm_x4(al, cur + 10240 + a_off + ko);
#pragma unroll
            for (int g = 0; g < 4; g++) {
                uint32_t bh[4], bl[4];
                uint32_t goff = (uint32_t)(g * 16) * (SSTR * 2);
                ldm_x4(bh, cur + 20480 + b_off + goff + ko);
                ldm_x4(bl, cur + 25600 + b_off + goff + ko);
                hmma(acc[2 * g],     ah, bh[0], bh[1]);
                hmma(acc[2 * g],     al, bh[0], bh[1]);
                hmma(acc[2 * g],     ah, bl[0], bl[1]);
                hmma(acc[2 * g + 1], ah, bh[2], bh[3]);
                hmma(acc[2 * g + 1], al, bh[2], bh[3]);
                hmma(acc[2 * g + 1], ah, bl[2], bl[3]);
            }
        }
    }

    // Epilogue
    const int r0 = lane >> 2;
    const int c0 = (lane & 3) * 2;
#pragma unroll
    for (int nt = 0; nt < 8; nt++) {
        int col = nt * 8 + c0;
        float b0v = bias[n0 + col], b1v = bias[n0 + col + 1];

        int m  = m0 + wid * 16 + r0;
        int bb = m >> 11, s = m & (S_ - 1);
        size_t idx = (((size_t)bb * NH_ + h) * S_ + s) * DH_ + col;
        float v0 = acc[nt][0] + b0v, v1 = acc[nt][1] + b1v;
        uint32_t hp = bfpair(v0, v1);
        *(uint32_t*)(oh + idx) = hp;
        *(uint32_t*)(ol + idx) = bfpair_lo(v0, v1, hp);

        m  = m0 + wid * 16 + r0 + 8;
        bb = m >> 11; s = m & (S_ - 1);
        idx = (((size_t)bb * NH_ + h) * S_ + s) * DH_ + col;
        v0 = acc[nt][2] + b0v; v1 = acc[nt][3] + b1v;
        hp = bfpair(v0, v1);
        *(uint32_t*)(oh + idx) = hp;
        *(uint32_t*)(ol + idx) = bfpair_lo(v0, v1, hp);
    }
}

// ---------------------------------------------------------------------------
// Kernel 2: flash attention, Q fragments in registers, cp.async
//   double-buffered K/V (stage reuses Q's smem: zero extra footprint).
//   Per-stage: KH 0, KL 9216, VH 18432, VL 27648 (36864 B/stage).
// ---------------------------------------------------------------------------
#define SQB 144
#define FSTG 36864
#define O_DIST (2 * FSTG)                  // 73728
#define FLASH_SMEM (O_DIST + RV_ * 4)      // 90112

__global__ __launch_bounds__(256) void flash_hmma(
    const float* __restrict__ mask,       // [B,1,1,S]
    const int*   __restrict__ dist_idx,   // [S,S]
    float*       __restrict__ out)        // [B,S,H]
{
    extern __shared__ char fsm[];
    float* distcol = (float*)(fsm + O_DIST);
    const uint32_t sb = smem_u32(fsm);

    const int tid  = threadIdx.x;
    const int wid  = tid >> 5;
    const int lane = tid & 31;
    const int q0 = blockIdx.x * 128;
    const int h  = blockIdx.y;
    const int b  = blockIdx.z;
    const size_t base = ((size_t)b * NH_ + h) * S_;
    const float* maskrow = mask + (size_t)b * S_;

    // Phase 1: load Q (hi at stage0+0, lo at stage0+18432), plain loads
#pragma unroll
    for (int rep = 0; rep < 4; rep++) {
        int u = tid + rep * 256;
        int row = u >> 3, uc = u & 7;
        size_t go = (base + q0 + row) * DH_ + uc * 8;
        *(uint4*)(fsm + row * SQB + uc * 16)         = *(const uint4*)(g_qh + go);
        *(uint4*)(fsm + 18432 + row * SQB + uc * 16) = *(const uint4*)(g_ql + go);
    }
    for (int i = tid; i < RV_; i += 256) distcol[i] = g_dT[h * RV_ + i];
    __syncthreads();

    // Phase 2: hoist Q fragments to registers
    const uint32_t a_off = (uint32_t)(wid * 16 + (lane & 15)) * SQB
                         + ((lane >> 4) & 1) * 16;
    uint32_t qah[4][4], qal[4][4];
#pragma unroll
    for (int kk = 0; kk < 4; kk++) {
        ldm_x4(qah[kk], sb + a_off + kk * 32);
        ldm_x4(qal[kk], sb + 18432 + a_off + kk * 32);
    }
    __syncthreads();   // all warps done reading Q; stage0 is free

    const uint32_t b_off = (uint32_t)((lane & 7) + ((lane >> 4) & 1) * 8) * SQB
                         + ((lane >> 3) & 1) * 16;
    const int v_m = lane >> 3, v_r = lane & 7;
    const uint32_t v_off = (uint32_t)((v_m & 1) * 8 + v_r) * SQB + (v_m >> 1) * 16;

    const int r_q = lane >> 2;
    const int c_q = (lane & 3) * 2;
    const int qrt = q0 + wid * 16 + r_q;
    const int qrb = qrt + 8;

    float m_t = -1e30f, m_b = -1e30f, l_t = 0.0f, l_b = 0.0f;
    float O[8][4];
#pragma unroll
    for (int i = 0; i < 8; i++)
#pragma unroll
        for (int j = 0; j < 4; j++) O[i][j] = 0.0f;

    // per-thread prefetch coords
    const int prow0 = tid >> 3, puc = tid & 7;

    // prefetch tile 0 -> stage 0
    {
        uint32_t dst = sb;
#pragma unroll
        for (int rep = 0; rep < 2; rep++) {
            int row = prow0 + rep * 32;
            size_t go = (base + row) * DH_ + puc * 8;
            uint32_t so = row * SQB + puc * 16;
            cpa16(dst + so,         g_kh + go);
            cpa16(dst + 9216  + so, g_kl + go);
            cpa16(dst + 18432 + so, g_vh + go);
            cpa16(dst + 27648 + so, g_vl + go);
        }
        cpa_commit();
    }

    for (int kt = 0; kt < 32; kt++) {
        const int k0 = kt * 64;
        const uint32_t cur = sb + (kt & 1) * FSTG;
        cpa_wait0();
        __syncthreads();
        if (kt < 31) {
            uint32_t dst = sb + ((kt + 1) & 1) * FSTG;
            int kn = (kt + 1) * 64;
#pragma unroll
            for (int rep = 0; rep < 2; rep++) {
                int row = prow0 + rep * 32;
                size_t go = (base + kn + row) * DH_ + puc * 8;
                uint32_t so = row * SQB + puc * 16;
                cpa16(dst + so,         g_kh + go);
                cpa16(dst + 9216  + so, g_kl + go);
                cpa16(dst + 18432 + so, g_vh + go);
                cpa16(dst + 27648 + so, g_vl + go);
            }
            cpa_commit();
        }

        // ---- S = Q K^T ----
        float sfr[8][4];
#pragma unroll
        for (int i = 0; i < 8; i++)
#pragma unroll
            for (int j = 0; j < 4; j++) sfr[i][j] = 0.0f;

#pragma unroll
        for (int kk = 0; kk < 4; kk++) {
            const uint32_t ko = kk * 32;
#pragma unroll
            for (int np = 0; np < 4; np++) {
                uint32_t bh[4], bl[4];
                uint32_t noff = (uint32_t)np * 16 * SQB;
                ldm_x4(bh, cur + b_off + noff + ko);
                ldm_x4(bl, cur + 9216 + b_off + noff + ko);
                hmma(sfr[2 * np],     qah[kk], bh[0], bh[1]);
                hmma(sfr[2 * np],     qal[kk], bh[0], bh[1]);
                hmma(sfr[2 * np],     qah[kk], bl[0], bl[1]);
                hmma(sfr[2 * np + 1], qah[kk], bh[2], bh[3]);
                hmma(sfr[2 * np + 1], qal[kk], bh[2], bh[3]);
                hmma(sfr[2 * np + 1], qah[kk], bl[2], bl[3]);
            }
        }

        // ---- scale + bias + mask ----
#pragma unroll
        for (int nt = 0; nt < 8; nt++) {
            int c = nt * 8 + c_q;
            int2 it = *(const int2*)(dist_idx + (size_t)qrt * S_ + k0 + c);
            int2 ib = *(const int2*)(dist_idx + (size_t)qrb * S_ + k0 + c);
            float mk0 = __ldg(maskrow + k0 + c);
            float mk1 = __ldg(maskrow + k0 + c + 1);
            sfr[nt][0] = sfr[nt][0] * 0.125f + distcol[it.x] + mk0;
            sfr[nt][1] = sfr[nt][1] * 0.125f + distcol[it.y] + mk1;
            sfr[nt][2] = sfr[nt][2] * 0.125f + distcol[ib.x] + mk0;
            sfr[nt][3] = sfr[nt][3] * 0.125f + distcol[ib.y] + mk1;
        }

        // ---- online softmax ----
        float vt = -1e30f, vb = -1e30f;
#pragma unroll
        for (int nt = 0; nt < 8; nt++) {
            vt = fmaxf(vt, fmaxf(sfr[nt][0], sfr[nt][1]));
            vb = fmaxf(vb, fmaxf(sfr[nt][2], sfr[nt][3]));
        }
        vt = fmaxf(vt, __shfl_xor_sync(0xffffffffu, vt, 1));
        vt = fmaxf(vt, __shfl_xor_sync(0xffffffffu, vt, 2));
        vb = fmaxf(vb, __shfl_xor_sync(0xffffffffu, vb, 1));
        vb = fmaxf(vb, __shfl_xor_sync(0xffffffffu, vb, 2));
        float mnt = fmaxf(m_t, vt), mnb = fmaxf(m_b, vb);
        float sct = __expf(m_t - mnt), scb = __expf(m_b - mnb);
        float rst = 0.0f, rsb = 0.0f;
#pragma unroll
        for (int nt = 0; nt < 8; nt++) {
            sfr[nt][0] = __expf(sfr[nt][0] - mnt);
            sfr[nt][1] = __expf(sfr[nt][1] - mnt);
            sfr[nt][2] = __expf(sfr[nt][2] - mnb);
            sfr[nt][3] = __expf(sfr[nt][3] - mnb);
            rst += sfr[nt][0] + sfr[nt][1];
            rsb += sfr[nt][2] + sfr[nt][3];
        }
        rst += __shfl_xor_sync(0xffffffffu, rst, 1);
        rst += __shfl_xor_sync(0xffffffffu, rst, 2);
        rsb += __shfl_xor_sync(0xffffffffu, rsb, 1);
        rsb += __shfl_xor_sync(0xffffffffu, rsb, 2);
        l_t = l_t * sct + rst;
        l_b = l_b * scb + rsb;
        m_t = mnt; m_b = mnb;
#pragma unroll
        for (int nt = 0; nt < 8; nt++) {
            O[nt][0] *= sct; O[nt][1] *= sct;
            O[nt][2] *= scb; O[nt][3] *= scb;
        }

        // ---- O += P V ----
#pragma unroll
        for (int kk = 0; kk < 4; kk++) {
            uint32_t aph[4], apl[4];
            aph[0] = bfpair(sfr[2 * kk][0], sfr[2 * kk][1]);
            apl[0] = bfpair_lo(sfr[2 * kk][0], sfr[2 * kk][1], aph[0]);
            aph[1] = bfpair(sfr[2 * kk][2], sfr[2 * kk][3]);
            apl[1] = bfpair_lo(sfr[2 * kk][2], sfr[2 * kk][3], aph[1]);
            aph[2] = bfpair(sfr[2 * kk + 1][0], sfr[2 * kk + 1][1]);
            apl[2] = bfpair_lo(sfr[2 * kk + 1][0], sfr[2 * kk + 1][1], aph[2]);
            aph[3] = bfpair(sfr[2 * kk + 1][2], sfr[2 * kk + 1][3]);
            apl[3] = bfpair_lo(sfr[2 * kk + 1][2], sfr[2 * kk + 1][3], aph[3]);
#pragma unroll
            for (int np = 0; np < 4; np++) {
                uint32_t vh[4], vl[4];
                uint32_t va = v_off + (uint32_t)kk * 16 * SQB + np * 32;
                ldm_x4_t(vh, cur + 18432 + va);
                ldm_x4_t(vl, cur + 27648 + va);
                hmma(O[2 * np],     aph, vh[0], vh[1]);
                hmma(O[2 * np],     apl, vh[0], vh[1]);
                hmma(O[2 * np],     aph, vl[0], vl[1]);
                hmma(O[2 * np + 1], aph, vh[2], vh[3]);
                hmma(O[2 * np + 1], apl, vh[2], vh[3]);
                hmma(O[2 * np + 1], aph, vl[2], vl[3]);
            }
        }
    }

    // ---- epilogue ----
    float ilt = 1.0f / l_t, ilb = 1.0f / l_b;
#pragma unroll
    for (int nt = 0; nt < 8; nt++) {
        int c = nt * 8 + c_q;
        float* pt = out + ((size_t)b * S_ + qrt) * H_ + h * DH_ + c;
        ((float2*)pt)[0] = make_float2(O[nt][0] * ilt, O[nt][1] * ilt);
        float* pb = out + ((size_t)b * S_ + qrb) * H_ + h * DH_ + c;
        ((float2*)pb)[0] = make_float2(O[nt][2] * ilb, O[nt][3] * ilb);
    }
}

// ---------------------------------------------------------------------------
extern "C" void kernel_launch(void* const* d_in, const int* in_sizes, int n_in,
                              void* d_out, int out_size)
{
    const float* X    = (const float*)d_in[0];
    const float* mask = (const float*)d_in[1];
    const int*   didx = (const int*)d_in[2];
    const float* Wq   = (const float*)d_in[3];
    const float* bq   = (const float*)d_in[4];
    const float* Wk   = (const float*)d_in[5];
    const float* bk   = (const float*)d_in[6];
    const float* Wv   = (const float*)d_in[7];
    const float* bv   = (const float*)d_in[8];
    const float* de   = (const float*)d_in[9];
    float* out = (float*)d_out;

    cudaFuncSetAttribute(flash_hmma,
                         cudaFuncAttributeMaxDynamicSharedMemorySize,
                         FLASH_SMEM);
    cudaFuncSetAttribute(qkv_proj_hmma,
                         cudaFuncAttributeMaxDynamicSharedMemorySize,
                         PROJ_SMEM);

    transpose_dist<<<(RV_ * NH_ + 255) / 256, 256>>>(de);
    cvt_x<<<4096, 256>>>(X);
    cvt_w<<<1024, 256>>>(Wq, 0);
    cvt_w<<<1024, 256>>>(Wk, 1);
    cvt_w<<<1024, 256>>>(Wv, 2);
    qkv_proj_hmma<<<dim3(48, 32), 256, PROJ_SMEM>>>(bq, bk, bv);
    flash_hmma<<<dim3(16, NH_, B_), 256, FLASH_SMEM>>>(mask, didx, out);
}

// round 11
// speedup vs baseline: 2.9501x; 1.0341x over previous
#include <cuda_runtime.h>
#include <cuda_fp16.h>
#include <cstdint>

#define B_ 2
#define S_ 2048
#define H_ 1024
#define NH_ 16
#define DH_ 64
#define RV_ 4096

__device__ __forceinline__ uint32_t smem_u32(const void* p) {
    uint32_t a;
    asm("{ .reg .u64 t; cvta.to.shared.u64 t, %1; cvt.u32.u64 %0, t; }"
        : "=r"(a) : "l"(p));
    return a;
}
__device__ __forceinline__ void ldm_x4(uint32_t* r, uint32_t addr) {
    asm volatile("ldmatrix.sync.aligned.m8n8.x4.shared.b16 {%0,%1,%2,%3}, [%4];"
                 : "=r"(r[0]), "=r"(r[1]), "=r"(r[2]), "=r"(r[3]) : "r"(addr));
}
__device__ __forceinline__ void ldm_x4_t(uint32_t* r, uint32_t addr) {
    asm volatile("ldmatrix.sync.aligned.m8n8.x4.trans.shared.b16 {%0,%1,%2,%3}, [%4];"
                 : "=r"(r[0]), "=r"(r[1]), "=r"(r[2]), "=r"(r[3]) : "r"(addr));
}
// fp16 mma m16n8k16 row.col, fp32 accum
__device__ __forceinline__ void hmma(float* c, const uint32_t* a,
                                     uint32_t b0, uint32_t b1) {
    asm volatile(
        "mma.sync.aligned.m16n8k16.row.col.f32.f16.f16.f32 "
        "{%0,%1,%2,%3}, {%4,%5,%6,%7}, {%8,%9}, {%0,%1,%2,%3};"
        : "+f"(c[0]), "+f"(c[1]), "+f"(c[2]), "+f"(c[3])
        : "r"(a[0]), "r"(a[1]), "r"(a[2]), "r"(a[3]), "r"(b0), "r"(b1));
}
__device__ __forceinline__ uint32_t hpair(float x, float y) {
    __half2 h = __floats2half2_rn(x, y);
    return *(uint32_t*)&h;
}
__device__ __forceinline__ uint32_t hpair_lo(float x, float y, uint32_t h) {
    __half2 hh = *(__half2*)&h;
    return hpair(x - __low2float(hh), y - __high2float(hh));
}
// cp.async (sm_80 PTX, valid under compute_103)
__device__ __forceinline__ void cpa16(uint32_t dst, const void* src) {
    asm volatile("cp.async.cg.shared.global [%0], [%1], 16;"
                 :: "r"(dst), "l"(src));
}
__device__ __forceinline__ void cpa_commit() {
    asm volatile("cp.async.commit_group;" ::: "memory");
}
__device__ __forceinline__ void cpa_wait0() {
    asm volatile("cp.async.wait_group 0;" ::: "memory");
}

// Scratch (allocation-free contract)
__device__ float g_dT[NH_ * RV_];
__device__ __half g_xh[(size_t)4096 * 1024];
__device__ __half g_xl[(size_t)4096 * 1024];
__device__ __half g_wh[(size_t)3 * 1024 * 1024];
__device__ __half g_wl[(size_t)3 * 1024 * 1024];
__device__ __half g_qh[(size_t)B_ * NH_ * S_ * DH_];
__device__ __half g_ql[(size_t)B_ * NH_ * S_ * DH_];
__device__ __half g_kh[(size_t)B_ * NH_ * S_ * DH_];
__device__ __half g_vh[(size_t)B_ * NH_ * S_ * DH_];
__device__ __half g_vl[(size_t)B_ * NH_ * S_ * DH_];

// ---------------------------------------------------------------------------
// Kernel A: X fp16-split conversion + dist_emb transpose (merged so flash is
// launch index 5 for ncu -s 5).
// ---------------------------------------------------------------------------
__global__ void cvt_x_t(const float* __restrict__ src,
                        const float* __restrict__ de) {
    int i = blockIdx.x * blockDim.x + threadIdx.x;
    if (i < RV_ * NH_) {
        int v = i / NH_;
        int h = i - v * NH_;
        g_dT[h * RV_ + v] = de[i];
    }
    float4 v4 = ((const float4*)src)[i];
    uint32_t h0 = hpair(v4.x, v4.y), h1 = hpair(v4.z, v4.w);
    uint32_t l0 = hpair_lo(v4.x, v4.y, h0), l1 = hpair_lo(v4.z, v4.w, h1);
    ((uint32_t*)g_xh)[2 * i] = h0; ((uint32_t*)g_xh)[2 * i + 1] = h1;
    ((uint32_t*)g_xl)[2 * i] = l0; ((uint32_t*)g_xl)[2 * i + 1] = l1;
}
__global__ void cvt_w(const float* __restrict__ src, int w) {
    int i = blockIdx.x * blockDim.x + threadIdx.x;
    float4 v = ((const float4*)src)[i];
    uint32_t h0 = hpair(v.x, v.y), h1 = hpair(v.z, v.w);
    uint32_t l0 = hpair_lo(v.x, v.y, h0), l1 = hpair_lo(v.z, v.w, h1);
    uint32_t* dh = (uint32_t*)(g_wh + (size_t)w * 1048576);
    uint32_t* dl = (uint32_t*)(g_wl + (size_t)w * 1048576);
    dh[2 * i] = h0; dh[2 * i + 1] = h1;
    dl[2 * i] = l0; dl[2 * i + 1] = l1;
}

// ---------------------------------------------------------------------------
// Kernel 1: QKV projection, fp16 split. Q,K: 2-term; V: 3-term.
//   Stage (bytes): AH 0 (10240), AL 10240, BH 20480 (5120), BL 25600.
// ---------------------------------------------------------------------------
#define SSTR 40
#define PSTG 30720
#define PROJ_SMEM (2 * PSTG)

__global__ __launch_bounds__(256) void qkv_proj_hmma(
    const float* __restrict__ bq, const float* __restrict__ bk,
    const float* __restrict__ bv)
{
    extern __shared__ char psm[];
    const uint32_t sb = smem_u32(psm);

    const int w   = blockIdx.x >> 4;
    const int h   = blockIdx.x & 15;
    const int n0  = h * 64;
    const int m0  = blockIdx.y * 128;
    const int tid = threadIdx.x;
    const int wid = tid >> 5;
    const int lane = tid & 31;
    const bool vterm = (w == 2);     // V needs the 3rd (B-lo) term + lo output

    const float* bias = (w == 0) ? bq : (w == 1) ? bk : bv;
    __half* oh = (w == 0) ? g_qh : (w == 1) ? g_kh : g_vh;
    __half* ol = (w == 0) ? g_ql : g_vl;   // K writes no lo
    const __half* Wh = g_wh + (size_t)w * 1048576;
    const __half* Wl = g_wl + (size_t)w * 1048576;

    float acc[8][4];
#pragma unroll
    for (int i = 0; i < 8; i++)
#pragma unroll
        for (int j = 0; j < 4; j++) acc[i][j] = 0.0f;

    const uint32_t a_off = (uint32_t)(wid * 16 + (lane & 15)) * (SSTR * 2)
                         + ((lane >> 4) & 1) * 16;
    const uint32_t b_off = (uint32_t)((lane & 7) + ((lane >> 4) & 1) * 8) * (SSTR * 2)
                         + ((lane >> 3) & 1) * 16;

    const int arow0 = tid >> 2, auc = tid & 3;
    const int brow  = tid >> 2, buc = tid & 3;

    // prefetch chunk 0
    {
        uint32_t dst = sb;
#pragma unroll
        for (int rep = 0; rep < 2; rep++) {
            int row = arow0 + rep * 64;
            size_t go = (size_t)(m0 + row) * 1024 + auc * 8;
            uint32_t so = row * (SSTR * 2) + auc * 16;
            cpa16(dst + so,         g_xh + go);
            cpa16(dst + 10240 + so, g_xl + go);
        }
        size_t go = (size_t)(n0 + brow) * 1024 + buc * 8;
        uint32_t so = brow * (SSTR * 2) + buc * 16;
        cpa16(dst + 20480 + so, Wh + go);
        if (vterm) cpa16(dst + 25600 + so, Wl + go);
        cpa_commit();
    }

    for (int kc = 0; kc < 32; kc++) {
        const uint32_t cur = sb + (kc & 1) * PSTG;
        cpa_wait0();
        __syncthreads();
        if (kc < 31) {
            uint32_t dst = sb + ((kc + 1) & 1) * PSTG;
            int kn = (kc + 1) * 32;
#pragma unroll
            for (int rep = 0; rep < 2; rep++) {
                int row = arow0 + rep * 64;
                size_t go = (size_t)(m0 + row) * 1024 + kn + auc * 8;
                uint32_t so = row * (SSTR * 2) + auc * 16;
                cpa16(dst + so,         g_xh + go);
                cpa16(dst + 10240 + so, g_xl + go);
            }
            size_t go = (size_t)(n0 + brow) * 1024 + kn + buc * 8;
            uint32_t so = brow * (SSTR * 2) + buc * 16;
            cpa16(dst + 20480 + so, Wh + go);
            if (vterm) cpa16(dst + 25600 + so, Wl + go);
            cpa_commit();
        }

#pragma unroll
        for (int k16 = 0; k16 < 2; k16++) {
            const uint32_t ko = k16 * 32;
            uint32_t ah[4], al[4];
            ldm_x4(ah, cur + a_off + ko);
            ldm_x4(al, cur + 10240 + a_off + ko);
#pragma unroll
            for (int g = 0; g < 4; g++) {
                uint32_t bh[4];
                uint32_t goff = (uint32_t)(g * 16) * (SSTR * 2);
                ldm_x4(bh, cur + 20480 + b_off + goff + ko);
                hmma(acc[2 * g],     ah, bh[0], bh[1]);
                hmma(acc[2 * g],     al, bh[0], bh[1]);
                hmma(acc[2 * g + 1], ah, bh[2], bh[3]);
                hmma(acc[2 * g + 1], al, bh[2], bh[3]);
                if (vterm) {
                    uint32_t bl[4];
                    ldm_x4(bl, cur + 25600 + b_off + goff + ko);
                    hmma(acc[2 * g],     ah, bl[0], bl[1]);
                    hmma(acc[2 * g + 1], ah, bl[2], bl[3]);
                }
            }
        }
    }

    // Epilogue
    const int r0 = lane >> 2;
    const int c0 = (lane & 3) * 2;
#pragma unroll
    for (int nt = 0; nt < 8; nt++) {
        int col = nt * 8 + c0;
        float b0v = bias[n0 + col], b1v = bias[n0 + col + 1];

        int m  = m0 + wid * 16 + r0;
        int bb = m >> 11, s = m & (S_ - 1);
        size_t idx = (((size_t)bb * NH_ + h) * S_ + s) * DH_ + col;
        float v0 = acc[nt][0] + b0v, v1 = acc[nt][1] + b1v;
        uint32_t hp = hpair(v0, v1);
        *(uint32_t*)(oh + idx) = hp;
        if (w != 1) *(uint32_t*)(ol + idx) = hpair_lo(v0, v1, hp);

        m  = m0 + wid * 16 + r0 + 8;
        bb = m >> 11; s = m & (S_ - 1);
        idx = (((size_t)bb * NH_ + h) * S_ + s) * DH_ + col;
        v0 = acc[nt][2] + b0v; v1 = acc[nt][3] + b1v;
        hp = hpair(v0, v1);
        *(uint32_t*)(oh + idx) = hp;
        if (w != 1) *(uint32_t*)(ol + idx) = hpair_lo(v0, v1, hp);
    }
}

// ---------------------------------------------------------------------------
// Kernel 2: flash attention, fp16. QK: (Qh+Ql)*Kh (2-term); PV 3-term.
//   Per-stage: KH 0, VH 9216, VL 18432 (27648 B/stage).
// ---------------------------------------------------------------------------
#define SQB 144
#define FSTG 27648
#define O_DIST (2 * FSTG)                  // 55296
#define FLASH_SMEM (O_DIST + RV_ * 4)      // 71680

__global__ __launch_bounds__(256) void flash_hmma(
    const float* __restrict__ mask,       // [B,1,1,S]
    const int*   __restrict__ dist_idx,   // [S,S]
    float*       __restrict__ out)        // [B,S,H]
{
    extern __shared__ char fsm[];
    float* distcol = (float*)(fsm + O_DIST);
    const uint32_t sb = smem_u32(fsm);

    const int tid  = threadIdx.x;
    const int wid  = tid >> 5;
    const int lane = tid & 31;
    const int q0 = blockIdx.x * 128;
    const int h  = blockIdx.y;
    const int b  = blockIdx.z;
    const size_t base = ((size_t)b * NH_ + h) * S_;
    const float* maskrow = mask + (size_t)b * S_;

    // Phase 1: stage Q hi/lo (fits in the 2 K/V stages: 36864 < 55296)
#pragma unroll
    for (int rep = 0; rep < 4; rep++) {
        int u = tid + rep * 256;
        int row = u >> 3, uc = u & 7;
        size_t go = (base + q0 + row) * DH_ + uc * 8;
        *(uint4*)(fsm + row * SQB + uc * 16)         = *(const uint4*)(g_qh + go);
        *(uint4*)(fsm + 18432 + row * SQB + uc * 16) = *(const uint4*)(g_ql + go);
    }
    for (int i = tid; i < RV_; i += 256) distcol[i] = g_dT[h * RV_ + i];
    __syncthreads();

    // Phase 2: hoist Q fragments
    const uint32_t a_off = (uint32_t)(wid * 16 + (lane & 15)) * SQB
                         + ((lane >> 4) & 1) * 16;
    uint32_t qah[4][4], qal[4][4];
#pragma unroll
    for (int kk = 0; kk < 4; kk++) {
        ldm_x4(qah[kk], sb + a_off + kk * 32);
        ldm_x4(qal[kk], sb + 18432 + a_off + kk * 32);
    }
    __syncthreads();

    const uint32_t b_off = (uint32_t)((lane & 7) + ((lane >> 4) & 1) * 8) * SQB
                         + ((lane >> 3) & 1) * 16;
    const int v_m = lane >> 3, v_r = lane & 7;
    const uint32_t v_off = (uint32_t)((v_m & 1) * 8 + v_r) * SQB + (v_m >> 1) * 16;

    const int r_q = lane >> 2;
    const int c_q = (lane & 3) * 2;
    const int qrt = q0 + wid * 16 + r_q;
    const int qrb = qrt + 8;

    float m_t = -1e30f, m_b = -1e30f, l_t = 0.0f, l_b = 0.0f;
    float O[8][4];
#pragma unroll
    for (int i = 0; i < 8; i++)
#pragma unroll
        for (int j = 0; j < 4; j++) O[i][j] = 0.0f;

    const int prow0 = tid >> 3, puc = tid & 7;

    // prefetch tile 0
    {
        uint32_t dst = sb;
#pragma unroll
        for (int rep = 0; rep < 2; rep++) {
            int row = prow0 + rep * 32;
            size_t go = (base + row) * DH_ + puc * 8;
            uint32_t so = row * SQB + puc * 16;
            cpa16(dst + so,         g_kh + go);
            cpa16(dst + 9216  + so, g_vh + go);
            cpa16(dst + 18432 + so, g_vl + go);
        }
        cpa_commit();
    }

    for (int kt = 0; kt < 32; kt++) {
        const int k0 = kt * 64;
        const uint32_t cur = sb + (kt & 1) * FSTG;
        cpa_wait0();
        __syncthreads();
        if (kt < 31) {
            uint32_t dst = sb + ((kt + 1) & 1) * FSTG;
            int kn = (kt + 1) * 64;
#pragma unroll
            for (int rep = 0; rep < 2; rep++) {
                int row = prow0 + rep * 32;
                size_t go = (base + kn + row) * DH_ + puc * 8;
                uint32_t so = row * SQB + puc * 16;
                cpa16(dst + so,         g_kh + go);
                cpa16(dst + 9216  + so, g_vh + go);
                cpa16(dst + 18432 + so, g_vl + go);
            }
            cpa_commit();
        }

        // ---- S = (Qh+Ql) Kh^T ----
        float sfr[8][4];
#pragma unroll
        for (int i = 0; i < 8; i++)
#pragma unroll
            for (int j = 0; j < 4; j++) sfr[i][j] = 0.0f;

#pragma unroll
        for (int kk = 0; kk < 4; kk++) {
            const uint32_t ko = kk * 32;
#pragma unroll
            for (int np = 0; np < 4; np++) {
                uint32_t bh[4];
                uint32_t noff = (uint32_t)np * 16 * SQB;
                ldm_x4(bh, cur + b_off + noff + ko);
                hmma(sfr[2 * np],     qah[kk], bh[0], bh[1]);
                hmma(sfr[2 * np],     qal[kk], bh[0], bh[1]);
                hmma(sfr[2 * np + 1], qah[kk], bh[2], bh[3]);
                hmma(sfr[2 * np + 1], qal[kk], bh[2], bh[3]);
            }
        }

        // ---- scale + bias + mask ----
#pragma unroll
        for (int nt = 0; nt < 8; nt++) {
            int c = nt * 8 + c_q;
            int2 it = *(const int2*)(dist_idx + (size_t)qrt * S_ + k0 + c);
            int2 ib = *(const int2*)(dist_idx + (size_t)qrb * S_ + k0 + c);
            float mk0 = __ldg(maskrow + k0 + c);
            float mk1 = __ldg(maskrow + k0 + c + 1);
            sfr[nt][0] = sfr[nt][0] * 0.125f + distcol[it.x] + mk0;
            sfr[nt][1] = sfr[nt][1] * 0.125f + distcol[it.y] + mk1;
            sfr[nt][2] = sfr[nt][2] * 0.125f + distcol[ib.x] + mk0;
            sfr[nt][3] = sfr[nt][3] * 0.125f + distcol[ib.y] + mk1;
        }

        // ---- online softmax ----
        float vt = -1e30f, vb = -1e30f;
#pragma unroll
        for (int nt = 0; nt < 8; nt++) {
            vt = fmaxf(vt, fmaxf(sfr[nt][0], sfr[nt][1]));
            vb = fmaxf(vb, fmaxf(sfr[nt][2], sfr[nt][3]));
        }
        vt = fmaxf(vt, __shfl_xor_sync(0xffffffffu, vt, 1));
        vt = fmaxf(vt, __shfl_xor_sync(0xffffffffu, vt, 2));
        vb = fmaxf(vb, __shfl_xor_sync(0xffffffffu, vb, 1));
        vb = fmaxf(vb, __shfl_xor_sync(0xffffffffu, vb, 2));
        float mnt = fmaxf(m_t, vt), mnb = fmaxf(m_b, vb);
        float sct = __expf(m_t - mnt), scb = __expf(m_b - mnb);
        float rst = 0.0f, rsb = 0.0f;
#pragma unroll
        for (int nt = 0; nt < 8; nt++) {
            sfr[nt][0] = __expf(sfr[nt][0] - mnt);
            sfr[nt][1] = __expf(sfr[nt][1] - mnt);
            sfr[nt][2] = __expf(sfr[nt][2] - mnb);
            sfr[nt][3] = __expf(sfr[nt][3] - mnb);
            rst += sfr[nt][0] + sfr[nt][1];
            rsb += sfr[nt][2] + sfr[nt][3];
        }
        rst += __shfl_xor_sync(0xffffffffu, rst, 1);
        rst += __shfl_xor_sync(0xffffffffu, rst, 2);
        rsb += __shfl_xor_sync(0xffffffffu, rsb, 1);
        rsb += __shfl_xor_sync(0xffffffffu, rsb, 2);
        l_t = l_t * sct + rst;
        l_b = l_b * scb + rsb;
        m_t = mnt; m_b = mnb;
#pragma unroll
        for (int nt = 0; nt < 8; nt++) {
            O[nt][0] *= sct; O[nt][1] *= sct;
            O[nt][2] *= scb; O[nt][3] *= scb;
        }

        // ---- O += P V (P hi/lo fp16, V hi/lo) ----
#pragma unroll
        for (int kk = 0; kk < 4; kk++) {
            uint32_t aph[4], apl[4];
            aph[0] = hpair(sfr[2 * kk][0], sfr[2 * kk][1]);
            apl[0] = hpair_lo(sfr[2 * kk][0], sfr[2 * kk][1], aph[0]);
            aph[1] = hpair(sfr[2 * kk][2], sfr[2 * kk][3]);
            apl[1] = hpair_lo(sfr[2 * kk][2], sfr[2 * kk][3], aph[1]);
            aph[2] = hpair(sfr[2 * kk + 1][0], sfr[2 * kk + 1][1]);
            apl[2] = hpair_lo(sfr[2 * kk + 1][0], sfr[2 * kk + 1][1], aph[2]);
            aph[3] = hpair(sfr[2 * kk + 1][2], sfr[2 * kk + 1][3]);
            apl[3] = hpair_lo(sfr[2 * kk + 1][2], sfr[2 * kk + 1][3], aph[3]);
#pragma unroll
            for (int np = 0; np < 4; np++) {
                uint32_t vh[4], vl[4];
                uint32_t va = v_off + (uint32_t)kk * 16 * SQB + np * 32;
                ldm_x4_t(vh, cur + 9216  + va);
                ldm_x4_t(vl, cur + 18432 + va);
                hmma(O[2 * np],     aph, vh[0], vh[1]);
                hmma(O[2 * np],     apl, vh[0], vh[1]);
                hmma(O[2 * np],     aph, vl[0], vl[1]);
                hmma(O[2 * np + 1], aph, vh[2], vh[3]);
                hmma(O[2 * np + 1], apl, vh[2], vh[3]);
                hmma(O[2 * np + 1], aph, vl[2], vl[3]);
            }
        }
    }

    // ---- epilogue ----
    float ilt = 1.0f / l_t, ilb = 1.0f / l_b;
#pragma unroll
    for (int nt = 0; nt < 8; nt++) {
        int c = nt * 8 + c_q;
        float* pt = out + ((size_t)b * S_ + qrt) * H_ + h * DH_ + c;
        ((float2*)pt)[0] = make_float2(O[nt][0] * ilt, O[nt][1] * ilt);
        float* pb = out + ((size_t)b * S_ + qrb) * H_ + h * DH_ + c;
        ((float2*)pb)[0] = make_float2(O[nt][2] * ilb, O[nt][3] * ilb);
    }
}

// ---------------------------------------------------------------------------
extern "C" void kernel_launch(void* const* d_in, const int* in_sizes, int n_in,
                              void* d_out, int out_size)
{
    const float* X    = (const float*)d_in[0];
    const float* mask = (const float*)d_in[1];
    const int*   didx = (const int*)d_in[2];
    const float* Wq   = (const float*)d_in[3];
    const float* bq   = (const float*)d_in[4];
    const float* Wk   = (const float*)d_in[5];
    const float* bk   = (const float*)d_in[6];
    const float* Wv   = (const float*)d_in[7];
    const float* bv   = (const float*)d_in[8];
    const float* de   = (const float*)d_in[9];
    float* out = (float*)d_out;

    cudaFuncSetAttribute(flash_hmma,
                         cudaFuncAttributeMaxDynamicSharedMemorySize,
                         FLASH_SMEM);
    cudaFuncSetAttribute(qkv_proj_hmma,
                         cudaFuncAttributeMaxDynamicSharedMemorySize,
                         PROJ_SMEM);

    cvt_x_t<<<4096, 256>>>(X, de);                 // launch 0 (incl. transpose)
    cvt_w<<<1024, 256>>>(Wq, 0);                   // 1
    cvt_w<<<1024, 256>>>(Wk, 1);                   // 2
    cvt_w<<<1024, 256>>>(Wv, 2);                   // 3
    qkv_proj_hmma<<<dim3(48, 32), 256, PROJ_SMEM>>>(bq, bk, bv);   // 4
    flash_hmma<<<dim3(16, NH_, B_), 256, FLASH_SMEM>>>(mask, didx, out); // 5 (profiled)
}

// round 12
// speedup vs baseline: 4.3730x; 1.4823x over previous
#include <cuda_runtime.h>
#include <cuda_fp16.h>
#include <cstdint>

#define B_ 2
#define S_ 2048
#define H_ 1024
#define NH_ 16
#define DH_ 64
#define RV_ 4096

__device__ __forceinline__ uint32_t smem_u32(const void* p) {
    uint32_t a;
    asm("{ .reg .u64 t; cvta.to.shared.u64 t, %1; cvt.u32.u64 %0, t; }"
        : "=r"(a) : "l"(p));
    return a;
}
__device__ __forceinline__ void ldm_x4(uint32_t* r, uint32_t addr) {
    asm volatile("ldmatrix.sync.aligned.m8n8.x4.shared.b16 {%0,%1,%2,%3}, [%4];"
                 : "=r"(r[0]), "=r"(r[1]), "=r"(r[2]), "=r"(r[3]) : "r"(addr));
}
__device__ __forceinline__ void ldm_x4_t(uint32_t* r, uint32_t addr) {
    asm volatile("ldmatrix.sync.aligned.m8n8.x4.trans.shared.b16 {%0,%1,%2,%3}, [%4];"
                 : "=r"(r[0]), "=r"(r[1]), "=r"(r[2]), "=r"(r[3]) : "r"(addr));
}
// fp16 mma m16n8k16 row.col, fp32 accum
__device__ __forceinline__ void hmma(float* c, const uint32_t* a,
                                     uint32_t b0, uint32_t b1) {
    asm volatile(
        "mma.sync.aligned.m16n8k16.row.col.f32.f16.f16.f32 "
        "{%0,%1,%2,%3}, {%4,%5,%6,%7}, {%8,%9}, {%0,%1,%2,%3};"
        : "+f"(c[0]), "+f"(c[1]), "+f"(c[2]), "+f"(c[3])
        : "r"(a[0]), "r"(a[1]), "r"(a[2]), "r"(a[3]), "r"(b0), "r"(b1));
}
__device__ __forceinline__ uint32_t hpair(float x, float y) {
    __half2 h = __floats2half2_rn(x, y);
    return *(uint32_t*)&h;
}
__device__ __forceinline__ uint32_t hpair_lo(float x, float y, uint32_t h) {
    __half2 hh = *(__half2*)&h;
    return hpair(x - __low2float(hh), y - __high2float(hh));
}
// cp.async (sm_80 PTX, valid under compute_103)
__device__ __forceinline__ void cpa16(uint32_t dst, const void* src) {
    asm volatile("cp.async.cg.shared.global [%0], [%1], 16;"
                 :: "r"(dst), "l"(src));
}
__device__ __forceinline__ void cpa_commit() {
    asm volatile("cp.async.commit_group;" ::: "memory");
}
__device__ __forceinline__ void cpa_wait0() {
    asm volatile("cp.async.wait_group 0;" ::: "memory");
}

// Scratch (allocation-free contract)
__device__ float g_dT[NH_ * RV_];
__device__ __half g_xh[(size_t)4096 * 1024];
__device__ __half g_xl[(size_t)4096 * 1024];
__device__ __half g_wh[(size_t)3 * 1024 * 1024];
__device__ __half g_wl[(size_t)3 * 1024 * 1024];
__device__ __half g_qh[(size_t)B_ * NH_ * S_ * DH_];
__device__ __half g_kh[(size_t)B_ * NH_ * S_ * DH_];
__device__ __half g_vh[(size_t)B_ * NH_ * S_ * DH_];
__device__ __half g_vl[(size_t)B_ * NH_ * S_ * DH_];

// ---------------------------------------------------------------------------
// Kernel A: X fp16-split conversion + dist_emb transpose.
// ---------------------------------------------------------------------------
__global__ void cvt_x_t(const float* __restrict__ src,
                        const float* __restrict__ de) {
    int i = blockIdx.x * blockDim.x + threadIdx.x;
    if (i < RV_ * NH_) {
        int v = i / NH_;
        int h = i - v * NH_;
        g_dT[h * RV_ + v] = de[i];
    }
    float4 v4 = ((const float4*)src)[i];
    uint32_t h0 = hpair(v4.x, v4.y), h1 = hpair(v4.z, v4.w);
    uint32_t l0 = hpair_lo(v4.x, v4.y, h0), l1 = hpair_lo(v4.z, v4.w, h1);
    ((uint32_t*)g_xh)[2 * i] = h0; ((uint32_t*)g_xh)[2 * i + 1] = h1;
    ((uint32_t*)g_xl)[2 * i] = l0; ((uint32_t*)g_xl)[2 * i + 1] = l1;
}
// Kernel B: all three W conversions in ONE launch (grid 3072).
__global__ void cvt_w_all(const float* __restrict__ Wq,
                          const float* __restrict__ Wk,
                          const float* __restrict__ Wv) {
    int w = blockIdx.x >> 10;
    const float* src = (w == 0) ? Wq : (w == 1) ? Wk : Wv;
    int i = (blockIdx.x & 1023) * blockDim.x + threadIdx.x;
    float4 v = ((const float4*)src)[i];
    uint32_t h0 = hpair(v.x, v.y), h1 = hpair(v.z, v.w);
    uint32_t l0 = hpair_lo(v.x, v.y, h0), l1 = hpair_lo(v.z, v.w, h1);
    uint32_t* dh = (uint32_t*)(g_wh + (size_t)w * 1048576);
    uint32_t* dl = (uint32_t*)(g_wl + (size_t)w * 1048576);
    dh[2 * i] = h0; dh[2 * i + 1] = h1;
    dl[2 * i] = l0; dl[2 * i + 1] = l1;
}

// ---------------------------------------------------------------------------
// Kernel 1: QKV projection. Q,K: 1-term (Ah*Bh); V: 3-term.
//   Stage (bytes): AH 0 (10240), AL 10240, BH 20480 (5120), BL 25600.
// ---------------------------------------------------------------------------
#define SSTR 40
#define PSTG 30720
#define PROJ_SMEM (2 * PSTG)

__global__ __launch_bounds__(256) void qkv_proj_hmma(
    const float* __restrict__ bq, const float* __restrict__ bk,
    const float* __restrict__ bv)
{
    extern __shared__ char psm[];
    const uint32_t sb = smem_u32(psm);

    const int w   = blockIdx.x >> 4;
    const int h   = blockIdx.x & 15;
    const int n0  = h * 64;
    const int m0  = blockIdx.y * 128;
    const int tid = threadIdx.x;
    const int wid = tid >> 5;
    const int lane = tid & 31;
    const bool vterm = (w == 2);     // V: extra terms + lo output

    const float* bias = (w == 0) ? bq : (w == 1) ? bk : bv;
    __half* oh = (w == 0) ? g_qh : (w == 1) ? g_kh : g_vh;
    const __half* Wh = g_wh + (size_t)w * 1048576;
    const __half* Wl = g_wl + (size_t)w * 1048576;

    float acc[8][4];
#pragma unroll
    for (int i = 0; i < 8; i++)
#pragma unroll
        for (int j = 0; j < 4; j++) acc[i][j] = 0.0f;

    const uint32_t a_off = (uint32_t)(wid * 16 + (lane & 15)) * (SSTR * 2)
                         + ((lane >> 4) & 1) * 16;
    const uint32_t b_off = (uint32_t)((lane & 7) + ((lane >> 4) & 1) * 8) * (SSTR * 2)
                         + ((lane >> 3) & 1) * 16;

    const int arow0 = tid >> 2, auc = tid & 3;
    const int brow  = tid >> 2, buc = tid & 3;

    // prefetch chunk 0
    {
        uint32_t dst = sb;
#pragma unroll
        for (int rep = 0; rep < 2; rep++) {
            int row = arow0 + rep * 64;
            size_t go = (size_t)(m0 + row) * 1024 + auc * 8;
            uint32_t so = row * (SSTR * 2) + auc * 16;
            cpa16(dst + so, g_xh + go);
            if (vterm) cpa16(dst + 10240 + so, g_xl + go);
        }
        size_t go = (size_t)(n0 + brow) * 1024 + buc * 8;
        uint32_t so = brow * (SSTR * 2) + buc * 16;
        cpa16(dst + 20480 + so, Wh + go);
        if (vterm) cpa16(dst + 25600 + so, Wl + go);
        cpa_commit();
    }

    for (int kc = 0; kc < 32; kc++) {
        const uint32_t cur = sb + (kc & 1) * PSTG;
        cpa_wait0();
        __syncthreads();
        if (kc < 31) {
            uint32_t dst = sb + ((kc + 1) & 1) * PSTG;
            int kn = (kc + 1) * 32;
#pragma unroll
            for (int rep = 0; rep < 2; rep++) {
                int row = arow0 + rep * 64;
                size_t go = (size_t)(m0 + row) * 1024 + kn + auc * 8;
                uint32_t so = row * (SSTR * 2) + auc * 16;
                cpa16(dst + so, g_xh + go);
                if (vterm) cpa16(dst + 10240 + so, g_xl + go);
            }
            size_t go = (size_t)(n0 + brow) * 1024 + kn + buc * 8;
            uint32_t so = brow * (SSTR * 2) + buc * 16;
            cpa16(dst + 20480 + so, Wh + go);
            if (vterm) cpa16(dst + 25600 + so, Wl + go);
            cpa_commit();
        }

#pragma unroll
        for (int k16 = 0; k16 < 2; k16++) {
            const uint32_t ko = k16 * 32;
            uint32_t ah[4];
            ldm_x4(ah, cur + a_off + ko);
            uint32_t al[4];
            if (vterm) ldm_x4(al, cur + 10240 + a_off + ko);
#pragma unroll
            for (int g = 0; g < 4; g++) {
                uint32_t bh[4];
                uint32_t goff = (uint32_t)(g * 16) * (SSTR * 2);
                ldm_x4(bh, cur + 20480 + b_off + goff + ko);
                hmma(acc[2 * g],     ah, bh[0], bh[1]);
                hmma(acc[2 * g + 1], ah, bh[2], bh[3]);
                if (vterm) {
                    uint32_t bl[4];
                    ldm_x4(bl, cur + 25600 + b_off + goff + ko);
                    hmma(acc[2 * g],     al, bh[0], bh[1]);
                    hmma(acc[2 * g + 1], al, bh[2], bh[3]);
                    hmma(acc[2 * g],     ah, bl[0], bl[1]);
                    hmma(acc[2 * g + 1], ah, bl[2], bl[3]);
                }
            }
        }
    }

    // Epilogue
    const int r0 = lane >> 2;
    const int c0 = (lane & 3) * 2;
#pragma unroll
    for (int nt = 0; nt < 8; nt++) {
        int col = nt * 8 + c0;
        float b0v = bias[n0 + col], b1v = bias[n0 + col + 1];

        int m  = m0 + wid * 16 + r0;
        int bb = m >> 11, s = m & (S_ - 1);
        size_t idx = (((size_t)bb * NH_ + h) * S_ + s) * DH_ + col;
        float v0 = acc[nt][0] + b0v, v1 = acc[nt][1] + b1v;
        uint32_t hp = hpair(v0, v1);
        *(uint32_t*)(oh + idx) = hp;
        if (vterm) *(uint32_t*)(g_vl + idx) = hpair_lo(v0, v1, hp);

        m  = m0 + wid * 16 + r0 + 8;
        bb = m >> 11; s = m & (S_ - 1);
        idx = (((size_t)bb * NH_ + h) * S_ + s) * DH_ + col;
        v0 = acc[nt][2] + b0v; v1 = acc[nt][3] + b1v;
        hp = hpair(v0, v1);
        *(uint32_t*)(oh + idx) = hp;
        if (vterm) *(uint32_t*)(g_vl + idx) = hpair_lo(v0, v1, hp);
    }
}

// ---------------------------------------------------------------------------
// Kernel 2: flash attention. QK: Qh*Kh (1-term); PV: Ph*(Vh+Vl) (2-term).
//   Per-stage: KH 0, VH 9216, VL 18432 (27648 B/stage).
// ---------------------------------------------------------------------------
#define SQB 144
#define FSTG 27648
#define O_DIST (2 * FSTG)                  // 55296
#define FLASH_SMEM (O_DIST + RV_ * 4)      // 71680

__global__ __launch_bounds__(256) void flash_hmma(
    const float* __restrict__ mask,       // [B,1,1,S]
    const int*   __restrict__ dist_idx,   // [S,S]
    float*       __restrict__ out)        // [B,S,H]
{
    extern __shared__ char fsm[];
    float* distcol = (float*)(fsm + O_DIST);
    const uint32_t sb = smem_u32(fsm);

    const int tid  = threadIdx.x;
    const int wid  = tid >> 5;
    const int lane = tid & 31;
    const int q0 = blockIdx.x * 128;
    const int h  = blockIdx.y;
    const int b  = blockIdx.z;
    const size_t base = ((size_t)b * NH_ + h) * S_;
    const float* maskrow = mask + (size_t)b * S_;

    // Phase 1: stage Qh (18432 B fits the 2 K/V stages region)
#pragma unroll
    for (int rep = 0; rep < 4; rep++) {
        int u = tid + rep * 256;
        int row = u >> 3, uc = u & 7;
        size_t go = (base + q0 + row) * DH_ + uc * 8;
        *(uint4*)(fsm + row * SQB + uc * 16) = *(const uint4*)(g_qh + go);
    }
    for (int i = tid; i < RV_; i += 256) distcol[i] = g_dT[h * RV_ + i];
    __syncthreads();

    // Phase 2: hoist Q fragments
    const uint32_t a_off = (uint32_t)(wid * 16 + (lane & 15)) * SQB
                         + ((lane >> 4) & 1) * 16;
    uint32_t qah[4][4];
#pragma unroll
    for (int kk = 0; kk < 4; kk++)
        ldm_x4(qah[kk], sb + a_off + kk * 32);
    __syncthreads();

    const uint32_t b_off = (uint32_t)((lane & 7) + ((lane >> 4) & 1) * 8) * SQB
                         + ((lane >> 3) & 1) * 16;
    const int v_m = lane >> 3, v_r = lane & 7;
    const uint32_t v_off = (uint32_t)((v_m & 1) * 8 + v_r) * SQB + (v_m >> 1) * 16;

    const int r_q = lane >> 2;
    const int c_q = (lane & 3) * 2;
    const int qrt = q0 + wid * 16 + r_q;
    const int qrb = qrt + 8;

    float m_t = -1e30f, m_b = -1e30f, l_t = 0.0f, l_b = 0.0f;
    float O[8][4];
#pragma unroll
    for (int i = 0; i < 8; i++)
#pragma unroll
        for (int j = 0; j < 4; j++) O[i][j] = 0.0f;

    const int prow0 = tid >> 3, puc = tid & 7;

    // prefetch tile 0
    {
        uint32_t dst = sb;
#pragma unroll
        for (int rep = 0; rep < 2; rep++) {
            int row = prow0 + rep * 32;
            size_t go = (base + row) * DH_ + puc * 8;
            uint32_t so = row * SQB + puc * 16;
            cpa16(dst + so,         g_kh + go);
            cpa16(dst + 9216  + so, g_vh + go);
            cpa16(dst + 18432 + so, g_vl + go);
        }
        cpa_commit();
    }

    for (int kt = 0; kt < 32; kt++) {
        const int k0 = kt * 64;
        const uint32_t cur = sb + (kt & 1) * FSTG;
        cpa_wait0();
        __syncthreads();
        if (kt < 31) {
            uint32_t dst = sb + ((kt + 1) & 1) * FSTG;
            int kn = (kt + 1) * 64;
#pragma unroll
            for (int rep = 0; rep < 2; rep++) {
                int row = prow0 + rep * 32;
                size_t go = (base + kn + row) * DH_ + puc * 8;
                uint32_t so = row * SQB + puc * 16;
                cpa16(dst + so,         g_kh + go);
                cpa16(dst + 9216  + so, g_vh + go);
                cpa16(dst + 18432 + so, g_vl + go);
            }
            cpa_commit();
        }

        // ---- S = Qh Kh^T ----
        float sfr[8][4];
#pragma unroll
        for (int i = 0; i < 8; i++)
#pragma unroll
            for (int j = 0; j < 4; j++) sfr[i][j] = 0.0f;

#pragma unroll
        for (int kk = 0; kk < 4; kk++) {
            const uint32_t ko = kk * 32;
#pragma unroll
            for (int np = 0; np < 4; np++) {
                uint32_t bh[4];
                uint32_t noff = (uint32_t)np * 16 * SQB;
                ldm_x4(bh, cur + b_off + noff + ko);
                hmma(sfr[2 * np],     qah[kk], bh[0], bh[1]);
                hmma(sfr[2 * np + 1], qah[kk], bh[2], bh[3]);
            }
        }

        // ---- scale + bias + mask ----
#pragma unroll
        for (int nt = 0; nt < 8; nt++) {
            int c = nt * 8 + c_q;
            int2 it = *(const int2*)(dist_idx + (size_t)qrt * S_ + k0 + c);
            int2 ib = *(const int2*)(dist_idx + (size_t)qrb * S_ + k0 + c);
            float mk0 = __ldg(maskrow + k0 + c);
            float mk1 = __ldg(maskrow + k0 + c + 1);
            sfr[nt][0] = sfr[nt][0] * 0.125f + distcol[it.x] + mk0;
            sfr[nt][1] = sfr[nt][1] * 0.125f + distcol[it.y] + mk1;
            sfr[nt][2] = sfr[nt][2] * 0.125f + distcol[ib.x] + mk0;
            sfr[nt][3] = sfr[nt][3] * 0.125f + distcol[ib.y] + mk1;
        }

        // ---- online softmax ----
        float vt = -1e30f, vb = -1e30f;
#pragma unroll
        for (int nt = 0; nt < 8; nt++) {
            vt = fmaxf(vt, fmaxf(sfr[nt][0], sfr[nt][1]));
            vb = fmaxf(vb, fmaxf(sfr[nt][2], sfr[nt][3]));
        }
        vt = fmaxf(vt, __shfl_xor_sync(0xffffffffu, vt, 1));
        vt = fmaxf(vt, __shfl_xor_sync(0xffffffffu, vt, 2));
        vb = fmaxf(vb, __shfl_xor_sync(0xffffffffu, vb, 1));
        vb = fmaxf(vb, __shfl_xor_sync(0xffffffffu, vb, 2));
        float mnt = fmaxf(m_t, vt), mnb = fmaxf(m_b, vb);
        float sct = __expf(m_t - mnt), scb = __expf(m_b - mnb);
        float rst = 0.0f, rsb = 0.0f;
#pragma unroll
        for (int nt = 0; nt < 8; nt++) {
            sfr[nt][0] = __expf(sfr[nt][0] - mnt);
            sfr[nt][1] = __expf(sfr[nt][1] - mnt);
            sfr[nt][2] = __expf(sfr[nt][2] - mnb);
            sfr[nt][3] = __expf(sfr[nt][3] - mnb);
            rst += sfr[nt][0] + sfr[nt][1];
            rsb += sfr[nt][2] + sfr[nt][3];
        }
        rst += __shfl_xor_sync(0xffffffffu, rst, 1);
        rst += __shfl_xor_sync(0xffffffffu, rst, 2);
        rsb += __shfl_xor_sync(0xffffffffu, rsb, 1);
        rsb += __shfl_xor_sync(0xffffffffu, rsb, 2);
        l_t = l_t * sct + rst;
        l_b = l_b * scb + rsb;
        m_t = mnt; m_b = mnb;
#pragma unroll
        for (int nt = 0; nt < 8; nt++) {
            O[nt][0] *= sct; O[nt][1] *= sct;
            O[nt][2] *= scb; O[nt][3] *= scb;
        }

        // ---- O += Ph (Vh + Vl) ----
#pragma unroll
        for (int kk = 0; kk < 4; kk++) {
            uint32_t aph[4];
            aph[0] = hpair(sfr[2 * kk][0], sfr[2 * kk][1]);
            aph[1] = hpair(sfr[2 * kk][2], sfr[2 * kk][3]);
            aph[2] = hpair(sfr[2 * kk + 1][0], sfr[2 * kk + 1][1]);
            aph[3] = hpair(sfr[2 * kk + 1][2], sfr[2 * kk + 1][3]);
#pragma unroll
            for (int np = 0; np < 4; np++) {
                uint32_t vh[4], vl[4];
                uint32_t va = v_off + (uint32_t)kk * 16 * SQB + np * 32;
                ldm_x4_t(vh, cur + 9216  + va);
                ldm_x4_t(vl, cur + 18432 + va);
                hmma(O[2 * np],     aph, vh[0], vh[1]);
                hmma(O[2 * np],     aph, vl[0], vl[1]);
                hmma(O[2 * np + 1], aph, vh[2], vh[3]);
                hmma(O[2 * np + 1], aph, vl[2], vl[3]);
            }
        }
    }

    // ---- epilogue ----
    float ilt = 1.0f / l_t, ilb = 1.0f / l_b;
#pragma unroll
    for (int nt = 0; nt < 8; nt++) {
        int c = nt * 8 + c_q;
        float* pt = out + ((size_t)b * S_ + qrt) * H_ + h * DH_ + c;
        ((float2*)pt)[0] = make_float2(O[nt][0] * ilt, O[nt][1] * ilt);
        float* pb = out + ((size_t)b * S_ + qrb) * H_ + h * DH_ + c;
        ((float2*)pb)[0] = make_float2(O[nt][2] * ilb, O[nt][3] * ilb);
    }
}

// ---------------------------------------------------------------------------
extern "C" void kernel_launch(void* const* d_in, const int* in_sizes, int n_in,
                              void* d_out, int out_size)
{
    const float* X    = (const float*)d_in[0];
    const float* mask = (const float*)d_in[1];
    const int*   didx = (const int*)d_in[2];
    const float* Wq   = (const float*)d_in[3];
    const float* bq   = (const float*)d_in[4];
    const float* Wk   = (const float*)d_in[5];
    const float* bk   = (const float*)d_in[6];
    const float* Wv   = (const float*)d_in[7];
    const float* bv   = (const float*)d_in[8];
    const float* de   = (const float*)d_in[9];
    float* out = (float*)d_out;

    cudaFuncSetAttribute(flash_hmma,
                         cudaFuncAttributeMaxDynamicSharedMemorySize,
                         FLASH_SMEM);
    cudaFuncSetAttribute(qkv_proj_hmma,
                         cudaFuncAttributeMaxDynamicSharedMemorySize,
                         PROJ_SMEM);

    cvt_x_t<<<4096, 256>>>(X, de);
    cvt_w_all<<<3072, 256>>>(Wq, Wk, Wv);
    qkv_proj_hmma<<<dim3(48, 32), 256, PROJ_SMEM>>>(bq, bk, bv);
    flash_hmma<<<dim3(16, NH_, B_), 256, FLASH_SMEM>>>(mask, didx, out);
}

// round 13
// speedup vs baseline: 4.7630x; 1.0892x over previous
#include <cuda_runtime.h>
#include <cuda_fp16.h>
#include <cstdint>

#define B_ 2
#define S_ 2048
#define H_ 1024
#define NH_ 16
#define DH_ 64
#define RV_ 4096

__device__ __forceinline__ uint32_t smem_u32(const void* p) {
    uint32_t a;
    asm("{ .reg .u64 t; cvta.to.shared.u64 t, %1; cvt.u32.u64 %0, t; }"
        : "=r"(a) : "l"(p));
    return a;
}
__device__ __forceinline__ void ldm_x4(uint32_t* r, uint32_t addr) {
    asm volatile("ldmatrix.sync.aligned.m8n8.x4.shared.b16 {%0,%1,%2,%3}, [%4];"
                 : "=r"(r[0]), "=r"(r[1]), "=r"(r[2]), "=r"(r[3]) : "r"(addr));
}
__device__ __forceinline__ void ldm_x4_t(uint32_t* r, uint32_t addr) {
    asm volatile("ldmatrix.sync.aligned.m8n8.x4.trans.shared.b16 {%0,%1,%2,%3}, [%4];"
                 : "=r"(r[0]), "=r"(r[1]), "=r"(r[2]), "=r"(r[3]) : "r"(addr));
}
// fp16 mma m16n8k16 row.col, fp32 accum
__device__ __forceinline__ void hmma(float* c, const uint32_t* a,
                                     uint32_t b0, uint32_t b1) {
    asm volatile(
        "mma.sync.aligned.m16n8k16.row.col.f32.f16.f16.f32 "
        "{%0,%1,%2,%3}, {%4,%5,%6,%7}, {%8,%9}, {%0,%1,%2,%3};"
        : "+f"(c[0]), "+f"(c[1]), "+f"(c[2]), "+f"(c[3])
        : "r"(a[0]), "r"(a[1]), "r"(a[2]), "r"(a[3]), "r"(b0), "r"(b1));
}
__device__ __forceinline__ uint32_t hpair(float x, float y) {
    __half2 h = __floats2half2_rn(x, y);
    return *(uint32_t*)&h;
}
__device__ __forceinline__ uint32_t hpair_lo(float x, float y, uint32_t h) {
    __half2 hh = *(__half2*)&h;
    return hpair(x - __low2float(hh), y - __high2float(hh));
}
// cp.async (sm_80 PTX, valid under compute_103)
__device__ __forceinline__ void cpa16(uint32_t dst, const void* src) {
    asm volatile("cp.async.cg.shared.global [%0], [%1], 16;"
                 :: "r"(dst), "l"(src));
}
__device__ __forceinline__ void cpa_commit() {
    asm volatile("cp.async.commit_group;" ::: "memory");
}
__device__ __forceinline__ void cpa_wait0() {
    asm volatile("cp.async.wait_group 0;" ::: "memory");
}

// Scratch (allocation-free contract)
__device__ float g_dT[NH_ * RV_];
__device__ __half g_xh[(size_t)4096 * 1024];
__device__ __half g_xl[(size_t)4096 * 1024];
__device__ __half g_wh[(size_t)3 * 1024 * 1024];
__device__ __half g_wl[(size_t)3 * 1024 * 1024];
__device__ __half g_qh[(size_t)B_ * NH_ * S_ * DH_];
__device__ __half g_kh[(size_t)B_ * NH_ * S_ * DH_];
__device__ __half g_vh[(size_t)B_ * NH_ * S_ * DH_];

// ---------------------------------------------------------------------------
// Kernel A: X fp16-split conversion + dist_emb transpose.
// ---------------------------------------------------------------------------
__global__ void cvt_x_t(const float* __restrict__ src,
                        const float* __restrict__ de) {
    int i = blockIdx.x * blockDim.x + threadIdx.x;
    if (i < RV_ * NH_) {
        int v = i / NH_;
        int h = i - v * NH_;
        g_dT[h * RV_ + v] = de[i];
    }
    float4 v4 = ((const float4*)src)[i];
    uint32_t h0 = hpair(v4.x, v4.y), h1 = hpair(v4.z, v4.w);
    uint32_t l0 = hpair_lo(v4.x, v4.y, h0), l1 = hpair_lo(v4.z, v4.w, h1);
    ((uint32_t*)g_xh)[2 * i] = h0; ((uint32_t*)g_xh)[2 * i + 1] = h1;
    ((uint32_t*)g_xl)[2 * i] = l0; ((uint32_t*)g_xl)[2 * i + 1] = l1;
}
// Kernel B: all three W conversions in ONE launch (grid 3072).
__global__ void cvt_w_all(const float* __restrict__ Wq,
                          const float* __restrict__ Wk,
                          const float* __restrict__ Wv) {
    int w = blockIdx.x >> 10;
    const float* src = (w == 0) ? Wq : (w == 1) ? Wk : Wv;
    int i = (blockIdx.x & 1023) * blockDim.x + threadIdx.x;
    float4 v = ((const float4*)src)[i];
    uint32_t h0 = hpair(v.x, v.y), h1 = hpair(v.z, v.w);
    uint32_t l0 = hpair_lo(v.x, v.y, h0), l1 = hpair_lo(v.z, v.w, h1);
    uint32_t* dh = (uint32_t*)(g_wh + (size_t)w * 1048576);
    uint32_t* dl = (uint32_t*)(g_wl + (size_t)w * 1048576);
    dh[2 * i] = h0; dh[2 * i + 1] = h1;
    dl[2 * i] = l0; dl[2 * i + 1] = l1;
}

// ---------------------------------------------------------------------------
// Kernel 1: QKV projection. Q,K: 1-term (Ah*Bh); V: 3-term (accurate Vh).
//   Stage (bytes): AH 0 (10240), AL 10240, BH 20480 (5120), BL 25600.
// ---------------------------------------------------------------------------
#define SSTR 40
#define PSTG 30720
#define PROJ_SMEM (2 * PSTG)

__global__ __launch_bounds__(256) void qkv_proj_hmma(
    const float* __restrict__ bq, const float* __restrict__ bk,
    const float* __restrict__ bv)
{
    extern __shared__ char psm[];
    const uint32_t sb = smem_u32(psm);

    const int w   = blockIdx.x >> 4;
    const int h   = blockIdx.x & 15;
    const int n0  = h * 64;
    const int m0  = blockIdx.y * 128;
    const int tid = threadIdx.x;
    const int wid = tid >> 5;
    const int lane = tid & 31;
    const bool vterm = (w == 2);     // V: extra split terms for accurate Vh

    const float* bias = (w == 0) ? bq : (w == 1) ? bk : bv;
    __half* oh = (w == 0) ? g_qh : (w == 1) ? g_kh : g_vh;
    const __half* Wh = g_wh + (size_t)w * 1048576;
    const __half* Wl = g_wl + (size_t)w * 1048576;

    float acc[8][4];
#pragma unroll
    for (int i = 0; i < 8; i++)
#pragma unroll
        for (int j = 0; j < 4; j++) acc[i][j] = 0.0f;

    const uint32_t a_off = (uint32_t)(wid * 16 + (lane & 15)) * (SSTR * 2)
                         + ((lane >> 4) & 1) * 16;
    const uint32_t b_off = (uint32_t)((lane & 7) + ((lane >> 4) & 1) * 8) * (SSTR * 2)
                         + ((lane >> 3) & 1) * 16;

    const int arow0 = tid >> 2, auc = tid & 3;
    const int brow  = tid >> 2, buc = tid & 3;

    // prefetch chunk 0
    {
        uint32_t dst = sb;
#pragma unroll
        for (int rep = 0; rep < 2; rep++) {
            int row = arow0 + rep * 64;
            size_t go = (size_t)(m0 + row) * 1024 + auc * 8;
            uint32_t so = row * (SSTR * 2) + auc * 16;
            cpa16(dst + so, g_xh + go);
            if (vterm) cpa16(dst + 10240 + so, g_xl + go);
        }
        size_t go = (size_t)(n0 + brow) * 1024 + buc * 8;
        uint32_t so = brow * (SSTR * 2) + buc * 16;
        cpa16(dst + 20480 + so, Wh + go);
        if (vterm) cpa16(dst + 25600 + so, Wl + go);
        cpa_commit();
    }

    for (int kc = 0; kc < 32; kc++) {
        const uint32_t cur = sb + (kc & 1) * PSTG;
        cpa_wait0();
        __syncthreads();
        if (kc < 31) {
            uint32_t dst = sb + ((kc + 1) & 1) * PSTG;
            int kn = (kc + 1) * 32;
#pragma unroll
            for (int rep = 0; rep < 2; rep++) {
                int row = arow0 + rep * 64;
                size_t go = (size_t)(m0 + row) * 1024 + kn + auc * 8;
                uint32_t so = row * (SSTR * 2) + auc * 16;
                cpa16(dst + so, g_xh + go);
                if (vterm) cpa16(dst + 10240 + so, g_xl + go);
            }
            size_t go = (size_t)(n0 + brow) * 1024 + kn + buc * 8;
            uint32_t so = brow * (SSTR * 2) + buc * 16;
            cpa16(dst + 20480 + so, Wh + go);
            if (vterm) cpa16(dst + 25600 + so, Wl + go);
            cpa_commit();
        }

#pragma unroll
        for (int k16 = 0; k16 < 2; k16++) {
            const uint32_t ko = k16 * 32;
            uint32_t ah[4];
            ldm_x4(ah, cur + a_off + ko);
            uint32_t al[4];
            if (vterm) ldm_x4(al, cur + 10240 + a_off + ko);
#pragma unroll
            for (int g = 0; g < 4; g++) {
                uint32_t bh[4];
                uint32_t goff = (uint32_t)(g * 16) * (SSTR * 2);
                ldm_x4(bh, cur + 20480 + b_off + goff + ko);
                hmma(acc[2 * g],     ah, bh[0], bh[1]);
                hmma(acc[2 * g + 1], ah, bh[2], bh[3]);
                if (vterm) {
                    uint32_t bl[4];
                    ldm_x4(bl, cur + 25600 + b_off + goff + ko);
                    hmma(acc[2 * g],     al, bh[0], bh[1]);
                    hmma(acc[2 * g + 1], al, bh[2], bh[3]);
                    hmma(acc[2 * g],     ah, bl[0], bl[1]);
                    hmma(acc[2 * g + 1], ah, bl[2], bl[3]);
                }
            }
        }
    }

    // Epilogue (hi only — V stored as correctly-rounded fp16 of exact V)
    const int r0 = lane >> 2;
    const int c0 = (lane & 3) * 2;
#pragma unroll
    for (int nt = 0; nt < 8; nt++) {
        int col = nt * 8 + c0;
        float b0v = bias[n0 + col], b1v = bias[n0 + col + 1];

        int m  = m0 + wid * 16 + r0;
        int bb = m >> 11, s = m & (S_ - 1);
        size_t idx = (((size_t)bb * NH_ + h) * S_ + s) * DH_ + col;
        *(uint32_t*)(oh + idx) = hpair(acc[nt][0] + b0v, acc[nt][1] + b1v);

        m  = m0 + wid * 16 + r0 + 8;
        bb = m >> 11; s = m & (S_ - 1);
        idx = (((size_t)bb * NH_ + h) * S_ + s) * DH_ + col;
        *(uint32_t*)(oh + idx) = hpair(acc[nt][2] + b0v, acc[nt][3] + b1v);
    }
}

// ---------------------------------------------------------------------------
// Kernel 2: flash attention. QK: Qh*Kh; PV: Ph*Vh (single-fp16 V).
//   Per-stage: KH 0, VH 9216 (18432 B/stage).
// ---------------------------------------------------------------------------
#define SQB 144
#define FSTG 18432
#define O_DIST (2 * FSTG)                  // 36864
#define FLASH_SMEM (O_DIST + RV_ * 4)      // 53248

__global__ __launch_bounds__(256) void flash_hmma(
    const float* __restrict__ mask,       // [B,1,1,S]
    const int*   __restrict__ dist_idx,   // [S,S]
    float*       __restrict__ out)        // [B,S,H]
{
    extern __shared__ char fsm[];
    float* distcol = (float*)(fsm + O_DIST);
    const uint32_t sb = smem_u32(fsm);

    const int tid  = threadIdx.x;
    const int wid  = tid >> 5;
    const int lane = tid & 31;
    const int q0 = blockIdx.x * 128;
    const int h  = blockIdx.y;
    const int b  = blockIdx.z;
    const size_t base = ((size_t)b * NH_ + h) * S_;
    const float* maskrow = mask + (size_t)b * S_;

    // Phase 1: stage Qh (18432 B = stage 0)
#pragma unroll
    for (int rep = 0; rep < 4; rep++) {
        int u = tid + rep * 256;
        int row = u >> 3, uc = u & 7;
        size_t go = (base + q0 + row) * DH_ + uc * 8;
        *(uint4*)(fsm + row * SQB + uc * 16) = *(const uint4*)(g_qh + go);
    }
    for (int i = tid; i < RV_; i += 256) distcol[i] = g_dT[h * RV_ + i];
    __syncthreads();

    // Phase 2: hoist Q fragments
    const uint32_t a_off = (uint32_t)(wid * 16 + (lane & 15)) * SQB
                         + ((lane >> 4) & 1) * 16;
    uint32_t qah[4][4];
#pragma unroll
    for (int kk = 0; kk < 4; kk++)
        ldm_x4(qah[kk], sb + a_off + kk * 32);
    __syncthreads();

    const uint32_t b_off = (uint32_t)((lane & 7) + ((lane >> 4) & 1) * 8) * SQB
                         + ((lane >> 3) & 1) * 16;
    const int v_m = lane >> 3, v_r = lane & 7;
    const uint32_t v_off = (uint32_t)((v_m & 1) * 8 + v_r) * SQB + (v_m >> 1) * 16;

    const int r_q = lane >> 2;
    const int c_q = (lane & 3) * 2;
    const int qrt = q0 + wid * 16 + r_q;
    const int qrb = qrt + 8;

    float m_t = -1e30f, m_b = -1e30f, l_t = 0.0f, l_b = 0.0f;
    float O[8][4];
#pragma unroll
    for (int i = 0; i < 8; i++)
#pragma unroll
        for (int j = 0; j < 4; j++) O[i][j] = 0.0f;

    const int prow0 = tid >> 3, puc = tid & 7;

    // prefetch tile 0
    {
        uint32_t dst = sb;
#pragma unroll
        for (int rep = 0; rep < 2; rep++) {
            int row = prow0 + rep * 32;
            size_t go = (base + row) * DH_ + puc * 8;
            uint32_t so = row * SQB + puc * 16;
            cpa16(dst + so,        g_kh + go);
            cpa16(dst + 9216 + so, g_vh + go);
        }
        cpa_commit();
    }

    for (int kt = 0; kt < 32; kt++) {
        const int k0 = kt * 64;
        const uint32_t cur = sb + (kt & 1) * FSTG;
        cpa_wait0();
        __syncthreads();
        if (kt < 31) {
            uint32_t dst = sb + ((kt + 1) & 1) * FSTG;
            int kn = (kt + 1) * 64;
#pragma unroll
            for (int rep = 0; rep < 2; rep++) {
                int row = prow0 + rep * 32;
                size_t go = (base + kn + row) * DH_ + puc * 8;
                uint32_t so = row * SQB + puc * 16;
                cpa16(dst + so,        g_kh + go);
                cpa16(dst + 9216 + so, g_vh + go);
            }
            cpa_commit();
        }

        // ---- S = Qh Kh^T ----
        float sfr[8][4];
#pragma unroll
        for (int i = 0; i < 8; i++)
#pragma unroll
            for (int j = 0; j < 4; j++) sfr[i][j] = 0.0f;

#pragma unroll
        for (int kk = 0; kk < 4; kk++) {
            const uint32_t ko = kk * 32;
#pragma unroll
            for (int np = 0; np < 4; np++) {
                uint32_t bh[4];
                uint32_t noff = (uint32_t)np * 16 * SQB;
                ldm_x4(bh, cur + b_off + noff + ko);
                hmma(sfr[2 * np],     qah[kk], bh[0], bh[1]);
                hmma(sfr[2 * np + 1], qah[kk], bh[2], bh[3]);
            }
        }

        // ---- scale + bias + mask ----
#pragma unroll
        for (int nt = 0; nt < 8; nt++) {
            int c = nt * 8 + c_q;
            int2 it = *(const int2*)(dist_idx + (size_t)qrt * S_ + k0 + c);
            int2 ib = *(const int2*)(dist_idx + (size_t)qrb * S_ + k0 + c);
            float mk0 = __ldg(maskrow + k0 + c);
            float mk1 = __ldg(maskrow + k0 + c + 1);
            sfr[nt][0] = sfr[nt][0] * 0.125f + distcol[it.x] + mk0;
            sfr[nt][1] = sfr[nt][1] * 0.125f + distcol[it.y] + mk1;
            sfr[nt][2] = sfr[nt][2] * 0.125f + distcol[ib.x] + mk0;
            sfr[nt][3] = sfr[nt][3] * 0.125f + distcol[ib.y] + mk1;
        }

        // ---- online softmax ----
        float vt = -1e30f, vb = -1e30f;
#pragma unroll
        for (int nt = 0; nt < 8; nt++) {
            vt = fmaxf(vt, fmaxf(sfr[nt][0], sfr[nt][1]));
            vb = fmaxf(vb, fmaxf(sfr[nt][2], sfr[nt][3]));
        }
        vt = fmaxf(vt, __shfl_xor_sync(0xffffffffu, vt, 1));
        vt = fmaxf(vt, __shfl_xor_sync(0xffffffffu, vt, 2));
        vb = fmaxf(vb, __shfl_xor_sync(0xffffffffu, vb, 1));
        vb = fmaxf(vb, __shfl_xor_sync(0xffffffffu, vb, 2));
        float mnt = fmaxf(m_t, vt), mnb = fmaxf(m_b, vb);
        float sct = __expf(m_t - mnt), scb = __expf(m_b - mnb);
        float rst = 0.0f, rsb = 0.0f;
#pragma unroll
        for (int nt = 0; nt < 8; nt++) {
            sfr[nt][0] = __expf(sfr[nt][0] - mnt);
            sfr[nt][1] = __expf(sfr[nt][1] - mnt);
            sfr[nt][2] = __expf(sfr[nt][2] - mnb);
            sfr[nt][3] = __expf(sfr[nt][3] - mnb);
            rst += sfr[nt][0] + sfr[nt][1];
            rsb += sfr[nt][2] + sfr[nt][3];
        }
        rst += __shfl_xor_sync(0xffffffffu, rst, 1);
        rst += __shfl_xor_sync(0xffffffffu, rst, 2);
        rsb += __shfl_xor_sync(0xffffffffu, rsb, 1);
        rsb += __shfl_xor_sync(0xffffffffu, rsb, 2);
        l_t = l_t * sct + rst;
        l_b = l_b * scb + rsb;
        m_t = mnt; m_b = mnb;
#pragma unroll
        for (int nt = 0; nt < 8; nt++) {
            O[nt][0] *= sct; O[nt][1] *= sct;
            O[nt][2] *= scb; O[nt][3] *= scb;
        }

        // ---- O += Ph Vh ----
#pragma unroll
        for (int kk = 0; kk < 4; kk++) {
            uint32_t aph[4];
            aph[0] = hpair(sfr[2 * kk][0], sfr[2 * kk][1]);
            aph[1] = hpair(sfr[2 * kk][2], sfr[2 * kk][3]);
            aph[2] = hpair(sfr[2 * kk + 1][0], sfr[2 * kk + 1][1]);
            aph[3] = hpair(sfr[2 * kk + 1][2], sfr[2 * kk + 1][3]);
#pragma unroll
            for (int np = 0; np < 4; np++) {
                uint32_t vh[4];
                uint32_t va = v_off + (uint32_t)kk * 16 * SQB + np * 32;
                ldm_x4_t(vh, cur + 9216 + va);
                hmma(O[2 * np],     aph, vh[0], vh[1]);
                hmma(O[2 * np + 1], aph, vh[2], vh[3]);
            }
        }
    }

    // ---- epilogue ----
    float ilt = 1.0f / l_t, ilb = 1.0f / l_b;
#pragma unroll
    for (int nt = 0; nt < 8; nt++) {
        int c = nt * 8 + c_q;
        float* pt = out + ((size_t)b * S_ + qrt) * H_ + h * DH_ + c;
        ((float2*)pt)[0] = make_float2(O[nt][0] * ilt, O[nt][1] * ilt);
        float* pb = out + ((size_t)b * S_ + qrb) * H_ + h * DH_ + c;
        ((float2*)pb)[0] = make_float2(O[nt][2] * ilb, O[nt][3] * ilb);
    }
}

// ---------------------------------------------------------------------------
extern "C" void kernel_launch(void* const* d_in, const int* in_sizes, int n_in,
                              void* d_out, int out_size)
{
    const float* X    = (const float*)d_in[0];
    const float* mask = (const float*)d_in[1];
    const int*   didx = (const int*)d_in[2];
    const float* Wq   = (const float*)d_in[3];
    const float* bq   = (const float*)d_in[4];
    const float* Wk   = (const float*)d_in[5];
    const float* bk   = (const float*)d_in[6];
    const float* Wv   = (const float*)d_in[7];
    const float* bv   = (const float*)d_in[8];
    const float* de   = (const float*)d_in[9];
    float* out = (float*)d_out;

    cudaFuncSetAttribute(flash_hmma,
                         cudaFuncAttributeMaxDynamicSharedMemorySize,
                         FLASH_SMEM);
    cudaFuncSetAttribute(qkv_proj_hmma,
                         cudaFuncAttributeMaxDynamicSharedMemorySize,
                         PROJ_SMEM);

    cvt_x_t<<<4096, 256>>>(X, de);
    cvt_w_all<<<3072, 256>>>(Wq, Wk, Wv);
    qkv_proj_hmma<<<dim3(48, 32), 256, PROJ_SMEM>>>(bq, bk, bv);
    flash_hmma<<<dim3(16, NH_, B_), 256, FLASH_SMEM>>>(mask, didx, out);
}

// round 14
// speedup vs baseline: 4.9407x; 1.0373x over previous
#include <cuda_runtime.h>
#include <cuda_fp16.h>
#include <cstdint>

#define B_ 2
#define S_ 2048
#define H_ 1024
#define NH_ 16
#define DH_ 64
#define RV_ 4096

__device__ __forceinline__ uint32_t smem_u32(const void* p) {
    uint32_t a;
    asm("{ .reg .u64 t; cvta.to.shared.u64 t, %1; cvt.u32.u64 %0, t; }"
        : "=r"(a) : "l"(p));
    return a;
}
__device__ __forceinline__ void ldm_x4(uint32_t* r, uint32_t addr) {
    asm volatile("ldmatrix.sync.aligned.m8n8.x4.shared.b16 {%0,%1,%2,%3}, [%4];"
                 : "=r"(r[0]), "=r"(r[1]), "=r"(r[2]), "=r"(r[3]) : "r"(addr));
}
__device__ __forceinline__ void ldm_x4_t(uint32_t* r, uint32_t addr) {
    asm volatile("ldmatrix.sync.aligned.m8n8.x4.trans.shared.b16 {%0,%1,%2,%3}, [%4];"
                 : "=r"(r[0]), "=r"(r[1]), "=r"(r[2]), "=r"(r[3]) : "r"(addr));
}
// fp16 mma m16n8k16 row.col, fp32 accum
__device__ __forceinline__ void hmma(float* c, const uint32_t* a,
                                     uint32_t b0, uint32_t b1) {
    asm volatile(
        "mma.sync.aligned.m16n8k16.row.col.f32.f16.f16.f32 "
        "{%0,%1,%2,%3}, {%4,%5,%6,%7}, {%8,%9}, {%0,%1,%2,%3};"
        : "+f"(c[0]), "+f"(c[1]), "+f"(c[2]), "+f"(c[3])
        : "r"(a[0]), "r"(a[1]), "r"(a[2]), "r"(a[3]), "r"(b0), "r"(b1));
}
__device__ __forceinline__ uint32_t hpair(float x, float y) {
    __half2 h = __floats2half2_rn(x, y);
    return *(uint32_t*)&h;
}
__device__ __forceinline__ uint32_t hpair_lo(float x, float y, uint32_t h) {
    __half2 hh = *(__half2*)&h;
    return hpair(x - __low2float(hh), y - __high2float(hh));
}
// cp.async (sm_80 PTX, valid under compute_103)
__device__ __forceinline__ void cpa16(uint32_t dst, const void* src) {
    asm volatile("cp.async.cg.shared.global [%0], [%1], 16;"
                 :: "r"(dst), "l"(src));
}
__device__ __forceinline__ void cpa_commit() {
    asm volatile("cp.async.commit_group;" ::: "memory");
}
__device__ __forceinline__ void cpa_wait0() {
    asm volatile("cp.async.wait_group 0;" ::: "memory");
}

// Scratch (allocation-free contract)
__device__ float g_dT[NH_ * RV_];
__device__ __half g_xh[(size_t)4096 * 1024];
__device__ __half g_xl[(size_t)4096 * 1024];
__device__ __half g_wh[(size_t)3 * 1024 * 1024];
__device__ __half g_wl[(size_t)3 * 1024 * 1024];
__device__ __half g_qh[(size_t)B_ * NH_ * S_ * DH_];
__device__ __half g_kh[(size_t)B_ * NH_ * S_ * DH_];
__device__ __half g_vh[(size_t)B_ * NH_ * S_ * DH_];

// ---------------------------------------------------------------------------
// Kernel A: X fp16-split conversion + dist_emb transpose.
// ---------------------------------------------------------------------------
__global__ void cvt_x_t(const float* __restrict__ src,
                        const float* __restrict__ de) {
    int i = blockIdx.x * blockDim.x + threadIdx.x;
    if (i < RV_ * NH_) {
        int v = i / NH_;
        int h = i - v * NH_;
        g_dT[h * RV_ + v] = de[i];
    }
    float4 v4 = ((const float4*)src)[i];
    uint32_t h0 = hpair(v4.x, v4.y), h1 = hpair(v4.z, v4.w);
    uint32_t l0 = hpair_lo(v4.x, v4.y, h0), l1 = hpair_lo(v4.z, v4.w, h1);
    ((uint32_t*)g_xh)[2 * i] = h0; ((uint32_t*)g_xh)[2 * i + 1] = h1;
    ((uint32_t*)g_xl)[2 * i] = l0; ((uint32_t*)g_xl)[2 * i + 1] = l1;
}
// Kernel B: all three W conversions in ONE launch (grid 3072).
__global__ void cvt_w_all(const float* __restrict__ Wq,
                          const float* __restrict__ Wk,
                          const float* __restrict__ Wv) {
    int w = blockIdx.x >> 10;
    const float* src = (w == 0) ? Wq : (w == 1) ? Wk : Wv;
    int i = (blockIdx.x & 1023) * blockDim.x + threadIdx.x;
    float4 v = ((const float4*)src)[i];
    uint32_t h0 = hpair(v.x, v.y), h1 = hpair(v.z, v.w);
    uint32_t l0 = hpair_lo(v.x, v.y, h0), l1 = hpair_lo(v.z, v.w, h1);
    uint32_t* dh = (uint32_t*)(g_wh + (size_t)w * 1048576);
    uint32_t* dl = (uint32_t*)(g_wl + (size_t)w * 1048576);
    dh[2 * i] = h0; dh[2 * i + 1] = h1;
    dl[2 * i] = l0; dl[2 * i + 1] = l1;
}

// ---------------------------------------------------------------------------
// Kernel 1: QKV projection. 128 threads = 4 warps, each warp 32 rows
//   (2 m16 groups) -> B-fragment ldmatrix amortized 2x.
//   Q,K: 1-term; V: 3-term. Stage: AH 0, AL 10240, BH 20480, BL 25600.
// ---------------------------------------------------------------------------
#define SSTR 40
#define PSTG 30720
#define PROJ_SMEM (2 * PSTG)

__global__ __launch_bounds__(128) void qkv_proj_hmma(
    const float* __restrict__ bq, const float* __restrict__ bk,
    const float* __restrict__ bv)
{
    extern __shared__ char psm[];
    const uint32_t sb = smem_u32(psm);

    const int w   = blockIdx.x >> 4;
    const int h   = blockIdx.x & 15;
    const int n0  = h * 64;
    const int m0  = blockIdx.y * 128;
    const int tid = threadIdx.x;
    const int wid = tid >> 5;
    const int lane = tid & 31;
    const bool vterm = (w == 2);

    const float* bias = (w == 0) ? bq : (w == 1) ? bk : bv;
    __half* oh = (w == 0) ? g_qh : (w == 1) ? g_kh : g_vh;
    const __half* Wh = g_wh + (size_t)w * 1048576;
    const __half* Wl = g_wl + (size_t)w * 1048576;

    float acc[2][8][4];
#pragma unroll
    for (int mg = 0; mg < 2; mg++)
#pragma unroll
        for (int i = 0; i < 8; i++)
#pragma unroll
            for (int j = 0; j < 4; j++) acc[mg][i][j] = 0.0f;

    const uint32_t a_off0 = (uint32_t)(wid * 32 + (lane & 15)) * (SSTR * 2)
                          + ((lane >> 4) & 1) * 16;
    const uint32_t b_off = (uint32_t)((lane & 7) + ((lane >> 4) & 1) * 8) * (SSTR * 2)
                         + ((lane >> 3) & 1) * 16;

    const int arow0 = tid >> 2, auc = tid & 3;   // rows 0..31
    const int brow0 = tid >> 2, buc = tid & 3;

    // prefetch chunk 0
    {
        uint32_t dst = sb;
#pragma unroll
        for (int rep = 0; rep < 4; rep++) {
            int row = arow0 + rep * 32;
            size_t go = (size_t)(m0 + row) * 1024 + auc * 8;
            uint32_t so = row * (SSTR * 2) + auc * 16;
            cpa16(dst + so, g_xh + go);
            if (vterm) cpa16(dst + 10240 + so, g_xl + go);
        }
#pragma unroll
        for (int rep = 0; rep < 2; rep++) {
            int row = brow0 + rep * 32;
            size_t go = (size_t)(n0 + row) * 1024 + buc * 8;
            uint32_t so = row * (SSTR * 2) + buc * 16;
            cpa16(dst + 20480 + so, Wh + go);
            if (vterm) cpa16(dst + 25600 + so, Wl + go);
        }
        cpa_commit();
    }

    for (int kc = 0; kc < 32; kc++) {
        const uint32_t cur = sb + (kc & 1) * PSTG;
        cpa_wait0();
        __syncthreads();
        if (kc < 31) {
            uint32_t dst = sb + ((kc + 1) & 1) * PSTG;
            int kn = (kc + 1) * 32;
#pragma unroll
            for (int rep = 0; rep < 4; rep++) {
                int row = arow0 + rep * 32;
                size_t go = (size_t)(m0 + row) * 1024 + kn + auc * 8;
                uint32_t so = row * (SSTR * 2) + auc * 16;
                cpa16(dst + so, g_xh + go);
                if (vterm) cpa16(dst + 10240 + so, g_xl + go);
            }
#pragma unroll
            for (int rep = 0; rep < 2; rep++) {
                int row = brow0 + rep * 32;
                size_t go = (size_t)(n0 + row) * 1024 + kn + buc * 8;
                uint32_t so = row * (SSTR * 2) + buc * 16;
                cpa16(dst + 20480 + so, Wh + go);
                if (vterm) cpa16(dst + 25600 + so, Wl + go);
            }
            cpa_commit();
        }

#pragma unroll
        for (int k16 = 0; k16 < 2; k16++) {
            const uint32_t ko = k16 * 32;
            uint32_t ah[2][4], al[2][4];
#pragma unroll
            for (int mg = 0; mg < 2; mg++) {
                ldm_x4(ah[mg], cur + a_off0 + mg * 16 * (SSTR * 2) + ko);
                if (vterm)
                    ldm_x4(al[mg], cur + 10240 + a_off0 + mg * 16 * (SSTR * 2) + ko);
            }
#pragma unroll
            for (int g = 0; g < 4; g++) {
                uint32_t bh[4];
                uint32_t goff = (uint32_t)(g * 16) * (SSTR * 2);
                ldm_x4(bh, cur + 20480 + b_off + goff + ko);
#pragma unroll
                for (int mg = 0; mg < 2; mg++) {
                    hmma(acc[mg][2 * g],     ah[mg], bh[0], bh[1]);
                    hmma(acc[mg][2 * g + 1], ah[mg], bh[2], bh[3]);
                }
                if (vterm) {
                    uint32_t bl[4];
                    ldm_x4(bl, cur + 25600 + b_off + goff + ko);
#pragma unroll
                    for (int mg = 0; mg < 2; mg++) {
                        hmma(acc[mg][2 * g],     al[mg], bh[0], bh[1]);
                        hmma(acc[mg][2 * g + 1], al[mg], bh[2], bh[3]);
                        hmma(acc[mg][2 * g],     ah[mg], bl[0], bl[1]);
                        hmma(acc[mg][2 * g + 1], ah[mg], bl[2], bl[3]);
                    }
                }
            }
        }
    }

    // Epilogue
    const int r0 = lane >> 2;
    const int c0 = (lane & 3) * 2;
#pragma unroll
    for (int mg = 0; mg < 2; mg++) {
#pragma unroll
        for (int nt = 0; nt < 8; nt++) {
            int col = nt * 8 + c0;
            float b0v = bias[n0 + col], b1v = bias[n0 + col + 1];

            int m  = m0 + wid * 32 + mg * 16 + r0;
            int bb = m >> 11, s = m & (S_ - 1);
            size_t idx = (((size_t)bb * NH_ + h) * S_ + s) * DH_ + col;
            *(uint32_t*)(oh + idx) = hpair(acc[mg][nt][0] + b0v, acc[mg][nt][1] + b1v);

            m  = m0 + wid * 32 + mg * 16 + r0 + 8;
            bb = m >> 11; s = m & (S_ - 1);
            idx = (((size_t)bb * NH_ + h) * S_ + s) * DH_ + col;
            *(uint32_t*)(oh + idx) = hpair(acc[mg][nt][2] + b0v, acc[mg][nt][3] + b1v);
        }
    }
}

// ---------------------------------------------------------------------------
// Kernel 2: flash attention. 128 threads = 4 warps, each warp 32 q-rows
//   (2 m16 groups) -> K/V ldmatrix amortized 2x.
//   QK: Qh*Kh; PV: Ph*Vh. Per-stage: KH 0, VH 9216 (18432 B/stage).
// ---------------------------------------------------------------------------
#define SQB 144
#define FSTG 18432
#define O_DIST (2 * FSTG)                  // 36864
#define FLASH_SMEM (O_DIST + RV_ * 4)      // 53248

__global__ __launch_bounds__(128) void flash_hmma(
    const float* __restrict__ mask,       // [B,1,1,S]
    const int*   __restrict__ dist_idx,   // [S,S]
    float*       __restrict__ out)        // [B,S,H]
{
    extern __shared__ char fsm[];
    float* distcol = (float*)(fsm + O_DIST);
    const uint32_t sb = smem_u32(fsm);

    const int tid  = threadIdx.x;
    const int wid  = tid >> 5;
    const int lane = tid & 31;
    const int q0 = blockIdx.x * 128;
    const int h  = blockIdx.y;
    const int b  = blockIdx.z;
    const size_t base = ((size_t)b * NH_ + h) * S_;
    const float* maskrow = mask + (size_t)b * S_;

    // Phase 1: stage Qh (18432 B = stage 0 region)
#pragma unroll
    for (int rep = 0; rep < 8; rep++) {
        int u = tid + rep * 128;
        int row = u >> 3, uc = u & 7;
        size_t go = (base + q0 + row) * DH_ + uc * 8;
        *(uint4*)(fsm + row * SQB + uc * 16) = *(const uint4*)(g_qh + go);
    }
    for (int i = tid; i < RV_; i += 128) distcol[i] = g_dT[h * RV_ + i];
    __syncthreads();

    // Phase 2: hoist Q fragments (both m-groups)
    const uint32_t a_off0 = (uint32_t)(wid * 32 + (lane & 15)) * SQB
                          + ((lane >> 4) & 1) * 16;
    uint32_t qah[4][2][4];
#pragma unroll
    for (int kk = 0; kk < 4; kk++) {
        ldm_x4(qah[kk][0], sb + a_off0 + kk * 32);
        ldm_x4(qah[kk][1], sb + a_off0 + 16 * SQB + kk * 32);
    }
    __syncthreads();

    const uint32_t b_off = (uint32_t)((lane & 7) + ((lane >> 4) & 1) * 8) * SQB
                         + ((lane >> 3) & 1) * 16;
    const int v_m = lane >> 3, v_r = lane & 7;
    const uint32_t v_off = (uint32_t)((v_m & 1) * 8 + v_r) * SQB + (v_m >> 1) * 16;

    const int r_q = lane >> 2;
    const int c_q = (lane & 3) * 2;
    int qrt[2], qrb[2];
    qrt[0] = q0 + wid * 32 + r_q;      qrb[0] = qrt[0] + 8;
    qrt[1] = qrt[0] + 16;              qrb[1] = qrt[0] + 24;

    float m_t[2], m_b[2], l_t[2], l_b[2];
    float O[2][8][4];
#pragma unroll
    for (int mg = 0; mg < 2; mg++) {
        m_t[mg] = -1e30f; m_b[mg] = -1e30f; l_t[mg] = 0.0f; l_b[mg] = 0.0f;
#pragma unroll
        for (int i = 0; i < 8; i++)
#pragma unroll
            for (int j = 0; j < 4; j++) O[mg][i][j] = 0.0f;
    }

    const int prow0 = tid >> 3, puc = tid & 7;   // rows 0..15

    // prefetch tile 0
    {
        uint32_t dst = sb;
#pragma unroll
        for (int rep = 0; rep < 4; rep++) {
            int row = prow0 + rep * 16;
            size_t go = (base + row) * DH_ + puc * 8;
            uint32_t so = row * SQB + puc * 16;
            cpa16(dst + so,        g_kh + go);
            cpa16(dst + 9216 + so, g_vh + go);
        }
        cpa_commit();
    }

    for (int kt = 0; kt < 32; kt++) {
        const int k0 = kt * 64;
        const uint32_t cur = sb + (kt & 1) * FSTG;
        cpa_wait0();
        __syncthreads();
        if (kt < 31) {
            uint32_t dst = sb + ((kt + 1) & 1) * FSTG;
            int kn = (kt + 1) * 64;
#pragma unroll
            for (int rep = 0; rep < 4; rep++) {
                int row = prow0 + rep * 16;
                size_t go = (base + kn + row) * DH_ + puc * 8;
                uint32_t so = row * SQB + puc * 16;
                cpa16(dst + so,        g_kh + go);
                cpa16(dst + 9216 + so, g_vh + go);
            }
            cpa_commit();
        }

        // ---- S = Qh Kh^T (both m-groups share each K fragment) ----
        float sfr[2][8][4];
#pragma unroll
        for (int mg = 0; mg < 2; mg++)
#pragma unroll
            for (int i = 0; i < 8; i++)
#pragma unroll
                for (int j = 0; j < 4; j++) sfr[mg][i][j] = 0.0f;

#pragma unroll
        for (int kk = 0; kk < 4; kk++) {
            const uint32_t ko = kk * 32;
#pragma unroll
            for (int np = 0; np < 4; np++) {
                uint32_t bh[4];
                uint32_t noff = (uint32_t)np * 16 * SQB;
                ldm_x4(bh, cur + b_off + noff + ko);
#pragma unroll
                for (int mg = 0; mg < 2; mg++) {
                    hmma(sfr[mg][2 * np],     qah[kk][mg], bh[0], bh[1]);
                    hmma(sfr[mg][2 * np + 1], qah[kk][mg], bh[2], bh[3]);
                }
            }
        }

        // ---- scale + bias + mask ----
#pragma unroll
        for (int mg = 0; mg < 2; mg++) {
#pragma unroll
            for (int nt = 0; nt < 8; nt++) {
                int c = nt * 8 + c_q;
                int2 it = *(const int2*)(dist_idx + (size_t)qrt[mg] * S_ + k0 + c);
                int2 ib = *(const int2*)(dist_idx + (size_t)qrb[mg] * S_ + k0 + c);
                float mk0 = __ldg(maskrow + k0 + c);
                float mk1 = __ldg(maskrow + k0 + c + 1);
                sfr[mg][nt][0] = sfr[mg][nt][0] * 0.125f + distcol[it.x] + mk0;
                sfr[mg][nt][1] = sfr[mg][nt][1] * 0.125f + distcol[it.y] + mk1;
                sfr[mg][nt][2] = sfr[mg][nt][2] * 0.125f + distcol[ib.x] + mk0;
                sfr[mg][nt][3] = sfr[mg][nt][3] * 0.125f + distcol[ib.y] + mk1;
            }
        }

        // ---- online softmax (per m-group) ----
#pragma unroll
        for (int mg = 0; mg < 2; mg++) {
            float vt = -1e30f, vb = -1e30f;
#pragma unroll
            for (int nt = 0; nt < 8; nt++) {
                vt = fmaxf(vt, fmaxf(sfr[mg][nt][0], sfr[mg][nt][1]));
                vb = fmaxf(vb, fmaxf(sfr[mg][nt][2], sfr[mg][nt][3]));
            }
            vt = fmaxf(vt, __shfl_xor_sync(0xffffffffu, vt, 1));
            vt = fmaxf(vt, __shfl_xor_sync(0xffffffffu, vt, 2));
            vb = fmaxf(vb, __shfl_xor_sync(0xffffffffu, vb, 1));
            vb = fmaxf(vb, __shfl_xor_sync(0xffffffffu, vb, 2));
            float mnt = fmaxf(m_t[mg], vt), mnb = fmaxf(m_b[mg], vb);
            float sct = __expf(m_t[mg] - mnt), scb = __expf(m_b[mg] - mnb);
            float rst = 0.0f, rsb = 0.0f;
#pragma unroll
            for (int nt = 0; nt < 8; nt++) {
                sfr[mg][nt][0] = __expf(sfr[mg][nt][0] - mnt);
                sfr[mg][nt][1] = __expf(sfr[mg][nt][1] - mnt);
                sfr[mg][nt][2] = __expf(sfr[mg][nt][2] - mnb);
                sfr[mg][nt][3] = __expf(sfr[mg][nt][3] - mnb);
                rst += sfr[mg][nt][0] + sfr[mg][nt][1];
                rsb += sfr[mg][nt][2] + sfr[mg][nt][3];
            }
            rst += __shfl_xor_sync(0xffffffffu, rst, 1);
            rst += __shfl_xor_sync(0xffffffffu, rst, 2);
            rsb += __shfl_xor_sync(0xffffffffu, rsb, 1);
            rsb += __shfl_xor_sync(0xffffffffu, rsb, 2);
            l_t[mg] = l_t[mg] * sct + rst;
            l_b[mg] = l_b[mg] * scb + rsb;
            m_t[mg] = mnt; m_b[mg] = mnb;
#pragma unroll
            for (int nt = 0; nt < 8; nt++) {
                O[mg][nt][0] *= sct; O[mg][nt][1] *= sct;
                O[mg][nt][2] *= scb; O[mg][nt][3] *= scb;
            }
        }

        // ---- O += Ph Vh (both m-groups share each V fragment) ----
#pragma unroll
        for (int kk = 0; kk < 4; kk++) {
            uint32_t aph[2][4];
#pragma unroll
            for (int mg = 0; mg < 2; mg++) {
                aph[mg][0] = hpair(sfr[mg][2 * kk][0], sfr[mg][2 * kk][1]);
                aph[mg][1] = hpair(sfr[mg][2 * kk][2], sfr[mg][2 * kk][3]);
                aph[mg][2] = hpair(sfr[mg][2 * kk + 1][0], sfr[mg][2 * kk + 1][1]);
                aph[mg][3] = hpair(sfr[mg][2 * kk + 1][2], sfr[mg][2 * kk + 1][3]);
            }
#pragma unroll
            for (int np = 0; np < 4; np++) {
                uint32_t vh[4];
                uint32_t va = v_off + (uint32_t)kk * 16 * SQB + np * 32;
                ldm_x4_t(vh, cur + 9216 + va);
#pragma unroll
                for (int mg = 0; mg < 2; mg++) {
                    hmma(O[mg][2 * np],     aph[mg], vh[0], vh[1]);
                    hmma(O[mg][2 * np + 1], aph[mg], vh[2], vh[3]);
                }
            }
        }
    }

    // ---- epilogue ----
#pragma unroll
    for (int mg = 0; mg < 2; mg++) {
        float ilt = 1.0f / l_t[mg], ilb = 1.0f / l_b[mg];
#pragma unroll
        for (int nt = 0; nt < 8; nt++) {
            int c = nt * 8 + c_q;
            float* pt = out + ((size_t)b * S_ + qrt[mg]) * H_ + h * DH_ + c;
            ((float2*)pt)[0] = make_float2(O[mg][nt][0] * ilt, O[mg][nt][1] * ilt);
            float* pb = out + ((size_t)b * S_ + qrb[mg]) * H_ + h * DH_ + c;
            ((float2*)pb)[0] = make_float2(O[mg][nt][2] * ilb, O[mg][nt][3] * ilb);
        }
    }
}

// ---------------------------------------------------------------------------
extern "C" void kernel_launch(void* const* d_in, const int* in_sizes, int n_in,
                              void* d_out, int out_size)
{
    const float* X    = (const float*)d_in[0];
    const float* mask = (const float*)d_in[1];
    const int*   didx = (const int*)d_in[2];
    const float* Wq   = (const float*)d_in[3];
    const float* bq   = (const float*)d_in[4];
    const float* Wk   = (const float*)d_in[5];
    const float* bk   = (const float*)d_in[6];
    const float* Wv   = (const float*)d_in[7];
    const float* bv   = (const float*)d_in[8];
    const float* de   = (const float*)d_in[9];
    float* out = (float*)d_out;

    cudaFuncSetAttribute(flash_hmma,
                         cudaFuncAttributeMaxDynamicSharedMemorySize,
                         FLASH_SMEM);
    cudaFuncSetAttribute(qkv_proj_hmma,
                         cudaFuncAttributeMaxDynamicSharedMemorySize,
                         PROJ_SMEM);

    cvt_x_t<<<4096, 256>>>(X, de);
    cvt_w_all<<<3072, 256>>>(Wq, Wk, Wv);
    qkv_proj_hmma<<<dim3(48, 32), 128, PROJ_SMEM>>>(bq, bk, bv);
    flash_hmma<<<dim3(16, NH_, B_), 128, FLASH_SMEM>>>(mask, didx, out);
}

// round 15
// speedup vs baseline: 5.1336x; 1.0391x over previous
#include <cuda_runtime.h>
#include <cuda_fp16.h>
#include <cstdint>

#define B_ 2
#define S_ 2048
#define H_ 1024
#define NH_ 16
#define DH_ 64
#define RV_ 4096

__device__ __forceinline__ uint32_t smem_u32(const void* p) {
    uint32_t a;
    asm("{ .reg .u64 t; cvta.to.shared.u64 t, %1; cvt.u32.u64 %0, t; }"
        : "=r"(a) : "l"(p));
    return a;
}
__device__ __forceinline__ void ldm_x4(uint32_t* r, uint32_t addr) {
    asm volatile("ldmatrix.sync.aligned.m8n8.x4.shared.b16 {%0,%1,%2,%3}, [%4];"
                 : "=r"(r[0]), "=r"(r[1]), "=r"(r[2]), "=r"(r[3]) : "r"(addr));
}
__device__ __forceinline__ void ldm_x4_t(uint32_t* r, uint32_t addr) {
    asm volatile("ldmatrix.sync.aligned.m8n8.x4.trans.shared.b16 {%0,%1,%2,%3}, [%4];"
                 : "=r"(r[0]), "=r"(r[1]), "=r"(r[2]), "=r"(r[3]) : "r"(addr));
}
// fp16 mma m16n8k16 row.col, fp32 accum
__device__ __forceinline__ void hmma(float* c, const uint32_t* a,
                                     uint32_t b0, uint32_t b1) {
    asm volatile(
        "mma.sync.aligned.m16n8k16.row.col.f32.f16.f16.f32 "
        "{%0,%1,%2,%3}, {%4,%5,%6,%7}, {%8,%9}, {%0,%1,%2,%3};"
        : "+f"(c[0]), "+f"(c[1]), "+f"(c[2]), "+f"(c[3])
        : "r"(a[0]), "r"(a[1]), "r"(a[2]), "r"(a[3]), "r"(b0), "r"(b1));
}
__device__ __forceinline__ uint32_t hpair(float x, float y) {
    __half2 h = __floats2half2_rn(x, y);
    return *(uint32_t*)&h;
}
__device__ __forceinline__ uint32_t hpair_lo(float x, float y, uint32_t h) {
    __half2 hh = *(__half2*)&h;
    return hpair(x - __low2float(hh), y - __high2float(hh));
}
// cp.async (sm_80 PTX, valid under compute_103)
__device__ __forceinline__ void cpa16(uint32_t dst, const void* src) {
    asm volatile("cp.async.cg.shared.global [%0], [%1], 16;"
                 :: "r"(dst), "l"(src));
}
__device__ __forceinline__ void cpa_commit() {
    asm volatile("cp.async.commit_group;" ::: "memory");
}
__device__ __forceinline__ void cpa_wait0() {
    asm volatile("cp.async.wait_group 0;" ::: "memory");
}

// Scratch (allocation-free contract)
__device__ __half g_dTh[NH_ * RV_];                      // dist_emb^T fp16
__device__ __half g_bias[(size_t)NH_ * S_ * S_];         // precomputed bias planes (128MB)
__device__ __half g_xh[(size_t)4096 * 1024];
__device__ __half g_xl[(size_t)4096 * 1024];
__device__ __half g_wh[(size_t)3 * 1024 * 1024];
__device__ __half g_wl[(size_t)3 * 1024 * 1024];
__device__ __half g_qh[(size_t)B_ * NH_ * S_ * DH_];
__device__ __half g_kh[(size_t)B_ * NH_ * S_ * DH_];
__device__ __half g_vh[(size_t)B_ * NH_ * S_ * DH_];

// ---------------------------------------------------------------------------
// Kernel A: X fp16-split conversion + dist_emb transpose (to fp16).
// ---------------------------------------------------------------------------
__global__ void cvt_x_t(const float* __restrict__ src,
                        const float* __restrict__ de) {
    int i = blockIdx.x * blockDim.x + threadIdx.x;
    if (i < RV_ * NH_) {
        int v = i / NH_;
        int h = i - v * NH_;
        g_dTh[h * RV_ + v] = __float2half(de[i]);
    }
    float4 v4 = ((const float4*)src)[i];
    uint32_t h0 = hpair(v4.x, v4.y), h1 = hpair(v4.z, v4.w);
    uint32_t l0 = hpair_lo(v4.x, v4.y, h0), l1 = hpair_lo(v4.z, v4.w, h1);
    ((uint32_t*)g_xh)[2 * i] = h0; ((uint32_t*)g_xh)[2 * i + 1] = h1;
    ((uint32_t*)g_xl)[2 * i] = l0; ((uint32_t*)g_xl)[2 * i + 1] = l1;
}
// Kernel B: all three W conversions in ONE launch (grid 3072).
__global__ void cvt_w_all(const float* __restrict__ Wq,
                          const float* __restrict__ Wk,
                          const float* __restrict__ Wv) {
    int w = blockIdx.x >> 10;
    const float* src = (w == 0) ? Wq : (w == 1) ? Wk : Wv;
    int i = (blockIdx.x & 1023) * blockDim.x + threadIdx.x;
    float4 v = ((const float4*)src)[i];
    uint32_t h0 = hpair(v.x, v.y), h1 = hpair(v.z, v.w);
    uint32_t l0 = hpair_lo(v.x, v.y, h0), l1 = hpair_lo(v.z, v.w, h1);
    uint32_t* dh = (uint32_t*)(g_wh + (size_t)w * 1048576);
    uint32_t* dl = (uint32_t*)(g_wl + (size_t)w * 1048576);
    dh[2 * i] = h0; dh[2 * i + 1] = h1;
    dl[2 * i] = l0; dl[2 * i + 1] = l1;
}

// ---------------------------------------------------------------------------
// Kernel C: bias precompute. g_bias[h][q][k] = dTh[h][dist_idx[q][k]].
//   Grid (64, 16): CTA = 32 q-rows of one head. Gathers from smem once
//   (instead of per-batch inside flash); writes coalesced fp16.
// ---------------------------------------------------------------------------
__global__ __launch_bounds__(256) void bias_pre(const int* __restrict__ didx) {
    __shared__ __half dc[RV_];
    const int h  = blockIdx.y;
    const int q0 = blockIdx.x * 32;
    const int tid = threadIdx.x;
    for (int i = tid; i < RV_; i += 256) dc[i] = g_dTh[h * RV_ + i];
    __syncthreads();
    for (int r = 0; r < 32; r++) {
        const int row = q0 + r;
        const int4* src = (const int4*)(didx + (size_t)row * S_) + tid * 2;
        int4 ia = src[0];
        int4 ib = src[1];
        __half2 p0 = __halves2half2(dc[ia.x], dc[ia.y]);
        __half2 p1 = __halves2half2(dc[ia.z], dc[ia.w]);
        __half2 p2 = __halves2half2(dc[ib.x], dc[ib.y]);
        __half2 p3 = __halves2half2(dc[ib.z], dc[ib.w]);
        uint4 o;
        o.x = *(uint32_t*)&p0; o.y = *(uint32_t*)&p1;
        o.z = *(uint32_t*)&p2; o.w = *(uint32_t*)&p3;
        *(uint4*)(g_bias + ((size_t)h * S_ + row) * S_ + tid * 8) = o;
    }
}

// ---------------------------------------------------------------------------
// Kernel 1: QKV projection (unchanged from R14 — 4 warps x 32 rows).
// ---------------------------------------------------------------------------
#define SSTR 40
#define PSTG 30720
#define PROJ_SMEM (2 * PSTG)

__global__ __launch_bounds__(128) void qkv_proj_hmma(
    const float* __restrict__ bq, const float* __restrict__ bk,
    const float* __restrict__ bv)
{
    extern __shared__ char psm[];
    const uint32_t sb = smem_u32(psm);

    const int w   = blockIdx.x >> 4;
    const int h   = blockIdx.x & 15;
    const int n0  = h * 64;
    const int m0  = blockIdx.y * 128;
    const int tid = threadIdx.x;
    const int wid = tid >> 5;
    const int lane = tid & 31;
    const bool vterm = (w == 2);

    const float* bias = (w == 0) ? bq : (w == 1) ? bk : bv;
    __half* oh = (w == 0) ? g_qh : (w == 1) ? g_kh : g_vh;
    const __half* Wh = g_wh + (size_t)w * 1048576;
    const __half* Wl = g_wl + (size_t)w * 1048576;

    float acc[2][8][4];
#pragma unroll
    for (int mg = 0; mg < 2; mg++)
#pragma unroll
        for (int i = 0; i < 8; i++)
#pragma unroll
            for (int j = 0; j < 4; j++) acc[mg][i][j] = 0.0f;

    const uint32_t a_off0 = (uint32_t)(wid * 32 + (lane & 15)) * (SSTR * 2)
                          + ((lane >> 4) & 1) * 16;
    const uint32_t b_off = (uint32_t)((lane & 7) + ((lane >> 4) & 1) * 8) * (SSTR * 2)
                         + ((lane >> 3) & 1) * 16;

    const int arow0 = tid >> 2, auc = tid & 3;
    const int brow0 = tid >> 2, buc = tid & 3;

    {
        uint32_t dst = sb;
#pragma unroll
        for (int rep = 0; rep < 4; rep++) {
            int row = arow0 + rep * 32;
            size_t go = (size_t)(m0 + row) * 1024 + auc * 8;
            uint32_t so = row * (SSTR * 2) + auc * 16;
            cpa16(dst + so, g_xh + go);
            if (vterm) cpa16(dst + 10240 + so, g_xl + go);
        }
#pragma unroll
        for (int rep = 0; rep < 2; rep++) {
            int row = brow0 + rep * 32;
            size_t go = (size_t)(n0 + row) * 1024 + buc * 8;
            uint32_t so = row * (SSTR * 2) + buc * 16;
            cpa16(dst + 20480 + so, Wh + go);
            if (vterm) cpa16(dst + 25600 + so, Wl + go);
        }
        cpa_commit();
    }

    for (int kc = 0; kc < 32; kc++) {
        const uint32_t cur = sb + (kc & 1) * PSTG;
        cpa_wait0();
        __syncthreads();
        if (kc < 31) {
            uint32_t dst = sb + ((kc + 1) & 1) * PSTG;
            int kn = (kc + 1) * 32;
#pragma unroll
            for (int rep = 0; rep < 4; rep++) {
                int row = arow0 + rep * 32;
                size_t go = (size_t)(m0 + row) * 1024 + kn + auc * 8;
                uint32_t so = row * (SSTR * 2) + auc * 16;
                cpa16(dst + so, g_xh + go);
                if (vterm) cpa16(dst + 10240 + so, g_xl + go);
            }
#pragma unroll
            for (int rep = 0; rep < 2; rep++) {
                int row = brow0 + rep * 32;
                size_t go = (size_t)(n0 + row) * 1024 + kn + buc * 8;
                uint32_t so = row * (SSTR * 2) + buc * 16;
                cpa16(dst + 20480 + so, Wh + go);
                if (vterm) cpa16(dst + 25600 + so, Wl + go);
            }
            cpa_commit();
        }

#pragma unroll
        for (int k16 = 0; k16 < 2; k16++) {
            const uint32_t ko = k16 * 32;
            uint32_t ah[2][4], al[2][4];
#pragma unroll
            for (int mg = 0; mg < 2; mg++) {
                ldm_x4(ah[mg], cur + a_off0 + mg * 16 * (SSTR * 2) + ko);
                if (vterm)
                    ldm_x4(al[mg], cur + 10240 + a_off0 + mg * 16 * (SSTR * 2) + ko);
            }
#pragma unroll
            for (int g = 0; g < 4; g++) {
                uint32_t bh[4];
                uint32_t goff = (uint32_t)(g * 16) * (SSTR * 2);
                ldm_x4(bh, cur + 20480 + b_off + goff + ko);
#pragma unroll
                for (int mg = 0; mg < 2; mg++) {
                    hmma(acc[mg][2 * g],     ah[mg], bh[0], bh[1]);
                    hmma(acc[mg][2 * g + 1], ah[mg], bh[2], bh[3]);
                }
                if (vterm) {
                    uint32_t bl[4];
                    ldm_x4(bl, cur + 25600 + b_off + goff + ko);
#pragma unroll
                    for (int mg = 0; mg < 2; mg++) {
                        hmma(acc[mg][2 * g],     al[mg], bh[0], bh[1]);
                        hmma(acc[mg][2 * g + 1], al[mg], bh[2], bh[3]);
                        hmma(acc[mg][2 * g],     ah[mg], bl[0], bl[1]);
                        hmma(acc[mg][2 * g + 1], ah[mg], bl[2], bl[3]);
                    }
                }
            }
        }
    }

    const int r0 = lane >> 2;
    const int c0 = (lane & 3) * 2;
#pragma unroll
    for (int mg = 0; mg < 2; mg++) {
#pragma unroll
        for (int nt = 0; nt < 8; nt++) {
            int col = nt * 8 + c0;
            float b0v = bias[n0 + col], b1v = bias[n0 + col + 1];

            int m  = m0 + wid * 32 + mg * 16 + r0;
            int bb = m >> 11, s = m & (S_ - 1);
            size_t idx = (((size_t)bb * NH_ + h) * S_ + s) * DH_ + col;
            *(uint32_t*)(oh + idx) = hpair(acc[mg][nt][0] + b0v, acc[mg][nt][1] + b1v);

            m  = m0 + wid * 32 + mg * 16 + r0 + 8;
            bb = m >> 11; s = m & (S_ - 1);
            idx = (((size_t)bb * NH_ + h) * S_ + s) * DH_ + col;
            *(uint32_t*)(oh + idx) = hpair(acc[mg][nt][2] + b0v, acc[mg][nt][3] + b1v);
        }
    }
}

// ---------------------------------------------------------------------------
// Kernel 2: flash attention (R13 shape: 256 thr, 8 warps x 16 q-rows).
//   Bias STREAMED from precomputed fp16 planes (no gathers, no dist_idx).
//   Per-stage: KH 0 (9216), VH 9216 (9216), BIAS 18432 (18432) = 36864 B.
// ---------------------------------------------------------------------------
#define SQB 144
#define O_VH   9216
#define O_BIAS 18432
#define FSTG   36864
#define FLASH_SMEM (2 * FSTG)              // 73728

__global__ __launch_bounds__(256) void flash_hmma(
    const float* __restrict__ mask,       // [B,1,1,S]
    float*       __restrict__ out)        // [B,S,H]
{
    extern __shared__ char fsm[];
    const uint32_t sb = smem_u32(fsm);

    const int tid  = threadIdx.x;
    const int wid  = tid >> 5;
    const int lane = tid & 31;
    const int q0 = blockIdx.x * 128;
    const int h  = blockIdx.y;
    const int b  = blockIdx.z;
    const size_t base = ((size_t)b * NH_ + h) * S_;
    const float* maskrow = mask + (size_t)b * S_;
    const __half* gb = g_bias + ((size_t)h * S_ + q0) * S_;   // this CTA's bias rows

    // Phase 1: stage Qh (18432 B in stage-0 region)
#pragma unroll
    for (int rep = 0; rep < 4; rep++) {
        int u = tid + rep * 256;
        int row = u >> 3, uc = u & 7;
        size_t go = (base + q0 + row) * DH_ + uc * 8;
        *(uint4*)(fsm + row * SQB + uc * 16) = *(const uint4*)(g_qh + go);
    }
    __syncthreads();

    // Phase 2: hoist Q fragments
    const uint32_t a_off = (uint32_t)(wid * 16 + (lane & 15)) * SQB
                         + ((lane >> 4) & 1) * 16;
    uint32_t qah[4][4];
#pragma unroll
    for (int kk = 0; kk < 4; kk++)
        ldm_x4(qah[kk], sb + a_off + kk * 32);
    __syncthreads();

    const uint32_t b_off = (uint32_t)((lane & 7) + ((lane >> 4) & 1) * 8) * SQB
                         + ((lane >> 3) & 1) * 16;
    const int v_m = lane >> 3, v_r = lane & 7;
    const uint32_t v_off = (uint32_t)((v_m & 1) * 8 + v_r) * SQB + (v_m >> 1) * 16;

    const int r_q = lane >> 2;
    const int c_q = (lane & 3) * 2;
    const int qrt = q0 + wid * 16 + r_q;
    const int qrb = qrt + 8;
    const int broff = (wid * 16 + r_q) * SQB;   // bias top-row byte offset

    float m_t = -1e30f, m_b = -1e30f, l_t = 0.0f, l_b = 0.0f;
    float O[8][4];
#pragma unroll
    for (int i = 0; i < 8; i++)
#pragma unroll
        for (int j = 0; j < 4; j++) O[i][j] = 0.0f;

    const int prow0 = tid >> 3, puc = tid & 7;   // K/V: rows 0..31; bias: rows 0..127 via reps

    // prefetch tile 0
    {
        uint32_t dst = sb;
#pragma unroll
        for (int rep = 0; rep < 2; rep++) {
            int row = prow0 + rep * 32;
            size_t go = (base + row) * DH_ + puc * 8;
            uint32_t so = row * SQB + puc * 16;
            cpa16(dst + so,        g_kh + go);
            cpa16(dst + O_VH + so, g_vh + go);
        }
#pragma unroll
        for (int rep = 0; rep < 4; rep++) {
            int u = tid + rep * 256;
            int row = u >> 3, uc = u & 7;
            cpa16(dst + O_BIAS + row * SQB + uc * 16,
                  gb + (size_t)row * S_ + uc * 8);
        }
        cpa_commit();
    }

    for (int kt = 0; kt < 32; kt++) {
        const int k0 = kt * 64;
        const uint32_t curoff = (kt & 1) * FSTG;
        const uint32_t cur = sb + curoff;
        cpa_wait0();
        __syncthreads();
        if (kt < 31) {
            uint32_t dst = sb + ((kt + 1) & 1) * FSTG;
            int kn = (kt + 1) * 64;
#pragma unroll
            for (int rep = 0; rep < 2; rep++) {
                int row = prow0 + rep * 32;
                size_t go = (base + kn + row) * DH_ + puc * 8;
                uint32_t so = row * SQB + puc * 16;
                cpa16(dst + so,        g_kh + go);
                cpa16(dst + O_VH + so, g_vh + go);
            }
#pragma unroll
            for (int rep = 0; rep < 4; rep++) {
                int u = tid + rep * 256;
                int row = u >> 3, uc = u & 7;
                cpa16(dst + O_BIAS + row * SQB + uc * 16,
                      gb + (size_t)row * S_ + kn + uc * 8);
            }
            cpa_commit();
        }

        // ---- S = Qh Kh^T ----
        float sfr[8][4];
#pragma unroll
        for (int i = 0; i < 8; i++)
#pragma unroll
            for (int j = 0; j < 4; j++) sfr[i][j] = 0.0f;

#pragma unroll
        for (int kk = 0; kk < 4; kk++) {
            const uint32_t ko = kk * 32;
#pragma unroll
            for (int np = 0; np < 4; np++) {
                uint32_t bh[4];
                uint32_t noff = (uint32_t)np * 16 * SQB;
                ldm_x4(bh, cur + b_off + noff + ko);
                hmma(sfr[2 * np],     qah[kk], bh[0], bh[1]);
                hmma(sfr[2 * np + 1], qah[kk], bh[2], bh[3]);
            }
        }

        // ---- scale + streamed bias + mask ----
#pragma unroll
        for (int nt = 0; nt < 8; nt++) {
            int c = nt * 8 + c_q;
            const char* bp = fsm + curoff + O_BIAS + broff + c * 2;
            float2 fb_t = __half22float2(*(const __half2*)bp);
            float2 fb_b = __half22float2(*(const __half2*)(bp + 8 * SQB));
            float mk0 = __ldg(maskrow + k0 + c);
            float mk1 = __ldg(maskrow + k0 + c + 1);
            sfr[nt][0] = sfr[nt][0] * 0.125f + fb_t.x + mk0;
            sfr[nt][1] = sfr[nt][1] * 0.125f + fb_t.y + mk1;
            sfr[nt][2] = sfr[nt][2] * 0.125f + fb_b.x + mk0;
            sfr[nt][3] = sfr[nt][3] * 0.125f + fb_b.y + mk1;
        }

        // ---- online softmax ----
        float vt = -1e30f, vb = -1e30f;
#pragma unroll
        for (int nt = 0; nt < 8; nt++) {
            vt = fmaxf(vt, fmaxf(sfr[nt][0], sfr[nt][1]));
            vb = fmaxf(vb, fmaxf(sfr[nt][2], sfr[nt][3]));
        }
        vt = fmaxf(vt, __shfl_xor_sync(0xffffffffu, vt, 1));
        vt = fmaxf(vt, __shfl_xor_sync(0xffffffffu, vt, 2));
        vb = fmaxf(vb, __shfl_xor_sync(0xffffffffu, vb, 1));
        vb = fmaxf(vb, __shfl_xor_sync(0xffffffffu, vb, 2));
        float mnt = fmaxf(m_t, vt), mnb = fmaxf(m_b, vb);
        float sct = __expf(m_t - mnt), scb = __expf(m_b - mnb);
        float rst = 0.0f, rsb = 0.0f;
#pragma unroll
        for (int nt = 0; nt < 8; nt++) {
            sfr[nt][0] = __expf(sfr[nt][0] - mnt);
            sfr[nt][1] = __expf(sfr[nt][1] - mnt);
            sfr[nt][2] = __expf(sfr[nt][2] - mnb);
            sfr[nt][3] = __expf(sfr[nt][3] - mnb);
            rst += sfr[nt][0] + sfr[nt][1];
            rsb += sfr[nt][2] + sfr[nt][3];
        }
        rst += __shfl_xor_sync(0xffffffffu, rst, 1);
        rst += __shfl_xor_sync(0xffffffffu, rst, 2);
        rsb += __shfl_xor_sync(0xffffffffu, rsb, 1);
        rsb += __shfl_xor_sync(0xffffffffu, rsb, 2);
        l_t = l_t * sct + rst;
        l_b = l_b * scb + rsb;
        m_t = mnt; m_b = mnb;
#pragma unroll
        for (int nt = 0; nt < 8; nt++) {
            O[nt][0] *= sct; O[nt][1] *= sct;
            O[nt][2] *= scb; O[nt][3] *= scb;
        }

        // ---- O += Ph Vh ----
#pragma unroll
        for (int kk = 0; kk < 4; kk++) {
            uint32_t aph[4];
            aph[0] = hpair(sfr[2 * kk][0], sfr[2 * kk][1]);
            aph[1] = hpair(sfr[2 * kk][2], sfr[2 * kk][3]);
            aph[2] = hpair(sfr[2 * kk + 1][0], sfr[2 * kk + 1][1]);
            aph[3] = hpair(sfr[2 * kk + 1][2], sfr[2 * kk + 1][3]);
#pragma unroll
            for (int np = 0; np < 4; np++) {
                uint32_t vh[4];
                uint32_t va = v_off + (uint32_t)kk * 16 * SQB + np * 32;
                ldm_x4_t(vh, cur + O_VH + va);
                hmma(O[2 * np],     aph, vh[0], vh[1]);
                hmma(O[2 * np + 1], aph, vh[2], vh[3]);
            }
        }
    }

    // ---- epilogue ----
    float ilt = 1.0f / l_t, ilb = 1.0f / l_b;
#pragma unroll
    for (int nt = 0; nt < 8; nt++) {
        int c = nt * 8 + c_q;
        float* pt = out + ((size_t)b * S_ + qrt) * H_ + h * DH_ + c;
        ((float2*)pt)[0] = make_float2(O[nt][0] * ilt, O[nt][1] * ilt);
        float* pb = out + ((size_t)b * S_ + qrb) * H_ + h * DH_ + c;
        ((float2*)pb)[0] = make_float2(O[nt][2] * ilb, O[nt][3] * ilb);
    }
}

// ---------------------------------------------------------------------------
extern "C" void kernel_launch(void* const* d_in, const int* in_sizes, int n_in,
                              void* d_out, int out_size)
{
    const float* X    = (const float*)d_in[0];
    const float* mask = (const float*)d_in[1];
    const int*   didx = (const int*)d_in[2];
    const float* Wq   = (const float*)d_in[3];
    const float* bq   = (const float*)d_in[4];
    const float* Wk   = (const float*)d_in[5];
    const float* bk   = (const float*)d_in[6];
    const float* Wv   = (const float*)d_in[7];
    const float* bv   = (const float*)d_in[8];
    const float* de   = (const float*)d_in[9];
    float* out = (float*)d_out;

    cudaFuncSetAttribute(flash_hmma,
                         cudaFuncAttributeMaxDynamicSharedMemorySize,
                         FLASH_SMEM);
    cudaFuncSetAttribute(qkv_proj_hmma,
                         cudaFuncAttributeMaxDynamicSharedMemorySize,
                         PROJ_SMEM);

    cvt_x_t<<<4096, 256>>>(X, de);
    cvt_w_all<<<3072, 256>>>(Wq, Wk, Wv);
    bias_pre<<<dim3(64, 16), 256>>>(didx);
    qkv_proj_hmma<<<dim3(48, 32), 128, PROJ_SMEM>>>(bq, bk, bv);
    flash_hmma<<<dim3(16, NH_, B_), 256, FLASH_SMEM>>>(mask, out);
}

// round 16
// speedup vs baseline: 5.8273x; 1.1351x over previous
#include <cuda_runtime.h>
#include <cuda_fp16.h>
#include <cstdint>

#define B_ 2
#define S_ 2048
#define H_ 1024
#define NH_ 16
#define DH_ 64
#define RV_ 4096

__device__ __forceinline__ uint32_t smem_u32(const void* p) {
    uint32_t a;
    asm("{ .reg .u64 t; cvta.to.shared.u64 t, %1; cvt.u32.u64 %0, t; }"
        : "=r"(a) : "l"(p));
    return a;
}
__device__ __forceinline__ void ldm_x4(uint32_t* r, uint32_t addr) {
    asm volatile("ldmatrix.sync.aligned.m8n8.x4.shared.b16 {%0,%1,%2,%3}, [%4];"
                 : "=r"(r[0]), "=r"(r[1]), "=r"(r[2]), "=r"(r[3]) : "r"(addr));
}
__device__ __forceinline__ void ldm_x4_t(uint32_t* r, uint32_t addr) {
    asm volatile("ldmatrix.sync.aligned.m8n8.x4.trans.shared.b16 {%0,%1,%2,%3}, [%4];"
                 : "=r"(r[0]), "=r"(r[1]), "=r"(r[2]), "=r"(r[3]) : "r"(addr));
}
// fp16 mma m16n8k16 row.col, fp32 accum
__device__ __forceinline__ void hmma(float* c, const uint32_t* a,
                                     uint32_t b0, uint32_t b1) {
    asm volatile(
        "mma.sync.aligned.m16n8k16.row.col.f32.f16.f16.f32 "
        "{%0,%1,%2,%3}, {%4,%5,%6,%7}, {%8,%9}, {%0,%1,%2,%3};"
        : "+f"(c[0]), "+f"(c[1]), "+f"(c[2]), "+f"(c[3])
        : "r"(a[0]), "r"(a[1]), "r"(a[2]), "r"(a[3]), "r"(b0), "r"(b1));
}
__device__ __forceinline__ uint32_t hpair(float x, float y) {
    __half2 h = __floats2half2_rn(x, y);
    return *(uint32_t*)&h;
}
__device__ __forceinline__ uint32_t hpair_lo(float x, float y, uint32_t h) {
    __half2 hh = *(__half2*)&h;
    return hpair(x - __low2float(hh), y - __high2float(hh));
}
// cp.async (sm_80 PTX, valid under compute_103)
__device__ __forceinline__ void cpa16(uint32_t dst, const void* src) {
    asm volatile("cp.async.cg.shared.global [%0], [%1], 16;"
                 :: "r"(dst), "l"(src));
}
__device__ __forceinline__ void cpa_commit() {
    asm volatile("cp.async.commit_group;" ::: "memory");
}
__device__ __forceinline__ void cpa_wait0() {
    asm volatile("cp.async.wait_group 0;" ::: "memory");
}

// Scratch (allocation-free contract)
__device__ __half g_dTh[NH_ * RV_];                      // dist_emb^T fp16
__device__ __half g_bias[(size_t)NH_ * S_ * S_];         // precomputed bias planes
__device__ __half g_xh[(size_t)4096 * 1024];
__device__ __half g_xl[(size_t)4096 * 1024];
__device__ __half g_wh[(size_t)3 * 1024 * 1024];
__device__ __half g_qh[(size_t)B_ * NH_ * S_ * DH_];
__device__ __half g_kh[(size_t)B_ * NH_ * S_ * DH_];
__device__ __half g_vh[(size_t)B_ * NH_ * S_ * DH_];

// ---------------------------------------------------------------------------
// Kernel A: X fp16-split conversion + dist_emb transpose (to fp16).
// ---------------------------------------------------------------------------
__global__ void cvt_x_t(const float* __restrict__ src,
                        const float* __restrict__ de) {
    int i = blockIdx.x * blockDim.x + threadIdx.x;
    if (i < RV_ * NH_) {
        int v = i / NH_;
        int h = i - v * NH_;
        g_dTh[h * RV_ + v] = __float2half(de[i]);
    }
    float4 v4 = ((const float4*)src)[i];
    uint32_t h0 = hpair(v4.x, v4.y), h1 = hpair(v4.z, v4.w);
    uint32_t l0 = hpair_lo(v4.x, v4.y, h0), l1 = hpair_lo(v4.z, v4.w, h1);
    ((uint32_t*)g_xh)[2 * i] = h0; ((uint32_t*)g_xh)[2 * i + 1] = h1;
    ((uint32_t*)g_xl)[2 * i] = l0; ((uint32_t*)g_xl)[2 * i + 1] = l1;
}
// Kernel B: all three W conversions, HI ONLY (Wl is dead now).
__global__ void cvt_w_all(const float* __restrict__ Wq,
                          const float* __restrict__ Wk,
                          const float* __restrict__ Wv) {
    int w = blockIdx.x >> 10;
    const float* src = (w == 0) ? Wq : (w == 1) ? Wk : Wv;
    int i = (blockIdx.x & 1023) * blockDim.x + threadIdx.x;
    float4 v = ((const float4*)src)[i];
    uint32_t* dh = (uint32_t*)(g_wh + (size_t)w * 1048576);
    dh[2 * i]     = hpair(v.x, v.y);
    dh[2 * i + 1] = hpair(v.z, v.w);
}

// ---------------------------------------------------------------------------
// Kernel C: bias precompute. g_bias[h][q][k] = dTh[h][dist_idx[q][k]].
// ---------------------------------------------------------------------------
__global__ __launch_bounds__(256) void bias_pre(const int* __restrict__ didx) {
    __shared__ __half dc[RV_];
    const int h  = blockIdx.y;
    const int q0 = blockIdx.x * 32;
    const int tid = threadIdx.x;
    for (int i = tid; i < RV_; i += 256) dc[i] = g_dTh[h * RV_ + i];
    __syncthreads();
    for (int r = 0; r < 32; r++) {
        const int row = q0 + r;
        const int4* src = (const int4*)(didx + (size_t)row * S_) + tid * 2;
        int4 ia = src[0];
        int4 ib = src[1];
        __half2 p0 = __halves2half2(dc[ia.x], dc[ia.y]);
        __half2 p1 = __halves2half2(dc[ia.z], dc[ia.w]);
        __half2 p2 = __halves2half2(dc[ib.x], dc[ib.y]);
        __half2 p3 = __halves2half2(dc[ib.z], dc[ib.w]);
        uint4 o;
        o.x = *(uint32_t*)&p0; o.y = *(uint32_t*)&p1;
        o.z = *(uint32_t*)&p2; o.w = *(uint32_t*)&p3;
        *(uint4*)(g_bias + ((size_t)h * S_ + row) * S_ + tid * 8) = o;
    }
}

// ---------------------------------------------------------------------------
// Kernel 1a: Q/K projection, 1-term (Ah*Bh). 4 warps x 32 rows.
//   Stage 15360 B: AH 0 (10240), BH 10240 (5120). 2 stages = 30720.
//   Grid: x = 32 (2 weights x 16 heads), y = 32 m-tiles.
// ---------------------------------------------------------------------------
#define SSTR 40
#define QK_STG 15360
#define QK_SMEM (2 * QK_STG)

__global__ __launch_bounds__(128) void qk_proj(
    const float* __restrict__ bq, const float* __restrict__ bk)
{
    extern __shared__ char psm[];
    const uint32_t sb = smem_u32(psm);

    const int w   = blockIdx.x >> 4;          // 0=Q, 1=K
    const int h   = blockIdx.x & 15;
    const int n0  = h * 64;
    const int m0  = blockIdx.y * 128;
    const int tid = threadIdx.x;
    const int wid = tid >> 5;
    const int lane = tid & 31;

    const float* bias = (w == 0) ? bq : bk;
    __half* oh = (w == 0) ? g_qh : g_kh;
    const __half* Wh = g_wh + (size_t)w * 1048576;

    float acc[2][8][4];
#pragma unroll
    for (int mg = 0; mg < 2; mg++)
#pragma unroll
        for (int i = 0; i < 8; i++)
#pragma unroll
            for (int j = 0; j < 4; j++) acc[mg][i][j] = 0.0f;

    const uint32_t a_off0 = (uint32_t)(wid * 32 + (lane & 15)) * (SSTR * 2)
                          + ((lane >> 4) & 1) * 16;
    const uint32_t b_off = (uint32_t)((lane & 7) + ((lane >> 4) & 1) * 8) * (SSTR * 2)
                         + ((lane >> 3) & 1) * 16;

    const int arow0 = tid >> 2, auc = tid & 3;
    const int brow0 = tid >> 2, buc = tid & 3;

    {
        uint32_t dst = sb;
#pragma unroll
        for (int rep = 0; rep < 4; rep++) {
            int row = arow0 + rep * 32;
            cpa16(dst + row * (SSTR * 2) + auc * 16,
                  g_xh + (size_t)(m0 + row) * 1024 + auc * 8);
        }
#pragma unroll
        for (int rep = 0; rep < 2; rep++) {
            int row = brow0 + rep * 32;
            cpa16(dst + 10240 + row * (SSTR * 2) + buc * 16,
                  Wh + (size_t)(n0 + row) * 1024 + buc * 8);
        }
        cpa_commit();
    }

    for (int kc = 0; kc < 32; kc++) {
        const uint32_t cur = sb + (kc & 1) * QK_STG;
        cpa_wait0();
        __syncthreads();
        if (kc < 31) {
            uint32_t dst = sb + ((kc + 1) & 1) * QK_STG;
            int kn = (kc + 1) * 32;
#pragma unroll
            for (int rep = 0; rep < 4; rep++) {
                int row = arow0 + rep * 32;
                cpa16(dst + row * (SSTR * 2) + auc * 16,
                      g_xh + (size_t)(m0 + row) * 1024 + kn + auc * 8);
            }
#pragma unroll
            for (int rep = 0; rep < 2; rep++) {
                int row = brow0 + rep * 32;
                cpa16(dst + 10240 + row * (SSTR * 2) + buc * 16,
                      Wh + (size_t)(n0 + row) * 1024 + kn + buc * 8);
            }
            cpa_commit();
        }

#pragma unroll
        for (int k16 = 0; k16 < 2; k16++) {
            const uint32_t ko = k16 * 32;
            uint32_t ah[2][4];
            ldm_x4(ah[0], cur + a_off0 + ko);
            ldm_x4(ah[1], cur + a_off0 + 16 * (SSTR * 2) + ko);
#pragma unroll
            for (int g = 0; g < 4; g++) {
                uint32_t bh[4];
                ldm_x4(bh, cur + 10240 + b_off + (uint32_t)(g * 16) * (SSTR * 2) + ko);
#pragma unroll
                for (int mg = 0; mg < 2; mg++) {
                    hmma(acc[mg][2 * g],     ah[mg], bh[0], bh[1]);
                    hmma(acc[mg][2 * g + 1], ah[mg], bh[2], bh[3]);
                }
            }
        }
    }

    const int r0 = lane >> 2;
    const int c0 = (lane & 3) * 2;
#pragma unroll
    for (int mg = 0; mg < 2; mg++) {
#pragma unroll
        for (int nt = 0; nt < 8; nt++) {
            int col = nt * 8 + c0;
            float b0v = bias[n0 + col], b1v = bias[n0 + col + 1];

            int m  = m0 + wid * 32 + mg * 16 + r0;
            int bb = m >> 11, s = m & (S_ - 1);
            size_t idx = (((size_t)bb * NH_ + h) * S_ + s) * DH_ + col;
            *(uint32_t*)(oh + idx) = hpair(acc[mg][nt][0] + b0v, acc[mg][nt][1] + b1v);

            m  = m0 + wid * 32 + mg * 16 + r0 + 8;
            bb = m >> 11; s = m & (S_ - 1);
            idx = (((size_t)bb * NH_ + h) * S_ + s) * DH_ + col;
            *(uint32_t*)(oh + idx) = hpair(acc[mg][nt][2] + b0v, acc[mg][nt][3] + b1v);
        }
    }
}

// ---------------------------------------------------------------------------
// Kernel 1b: V projection, 2-term (Ah+Al)*Bh. 4 warps x 32 rows.
//   Stage 25600 B: AH 0, AL 10240, BH 20480. 2 stages = 51200.
//   Grid: x = 16 heads, y = 32 m-tiles.
// ---------------------------------------------------------------------------
#define V_STG 25600
#define V_SMEM (2 * V_STG)

__global__ __launch_bounds__(128) void v_proj(const float* __restrict__ bv)
{
    extern __shared__ char psm[];
    const uint32_t sb = smem_u32(psm);

    const int h   = blockIdx.x;
    const int n0  = h * 64;
    const int m0  = blockIdx.y * 128;
    const int tid = threadIdx.x;
    const int wid = tid >> 5;
    const int lane = tid & 31;

    const __half* Wh = g_wh + (size_t)2 * 1048576;

    float acc[2][8][4];
#pragma unroll
    for (int mg = 0; mg < 2; mg++)
#pragma unroll
        for (int i = 0; i < 8; i++)
#pragma unroll
            for (int j = 0; j < 4; j++) acc[mg][i][j] = 0.0f;

    const uint32_t a_off0 = (uint32_t)(wid * 32 + (lane & 15)) * (SSTR * 2)
                          + ((lane >> 4) & 1) * 16;
    const uint32_t b_off = (uint32_t)((lane & 7) + ((lane >> 4) & 1) * 8) * (SSTR * 2)
                         + ((lane >> 3) & 1) * 16;

    const int arow0 = tid >> 2, auc = tid & 3;
    const int brow0 = tid >> 2, buc = tid & 3;

    {
        uint32_t dst = sb;
#pragma unroll
        for (int rep = 0; rep < 4; rep++) {
            int row = arow0 + rep * 32;
            size_t go = (size_t)(m0 + row) * 1024 + auc * 8;
            uint32_t so = row * (SSTR * 2) + auc * 16;
            cpa16(dst + so,         g_xh + go);
            cpa16(dst + 10240 + so, g_xl + go);
        }
#pragma unroll
        for (int rep = 0; rep < 2; rep++) {
            int row = brow0 + rep * 32;
            cpa16(dst + 20480 + row * (SSTR * 2) + buc * 16,
                  Wh + (size_t)(n0 + row) * 1024 + buc * 8);
        }
        cpa_commit();
    }

    for (int kc = 0; kc < 32; kc++) {
        const uint32_t cur = sb + (kc & 1) * V_STG;
        cpa_wait0();
        __syncthreads();
        if (kc < 31) {
            uint32_t dst = sb + ((kc + 1) & 1) * V_STG;
            int kn = (kc + 1) * 32;
#pragma unroll
            for (int rep = 0; rep < 4; rep++) {
                int row = arow0 + rep * 32;
                size_t go = (size_t)(m0 + row) * 1024 + kn + auc * 8;
                uint32_t so = row * (SSTR * 2) + auc * 16;
                cpa16(dst + so,         g_xh + go);
                cpa16(dst + 10240 + so, g_xl + go);
            }
#pragma unroll
            for (int rep = 0; rep < 2; rep++) {
                int row = brow0 + rep * 32;
                cpa16(dst + 20480 + row * (SSTR * 2) + buc * 16,
                      Wh + (size_t)(n0 + row) * 1024 + kn + buc * 8);
            }
            cpa_commit();
        }

#pragma unroll
        for (int k16 = 0; k16 < 2; k16++) {
            const uint32_t ko = k16 * 32;
            uint32_t ah[2][4], al[2][4];
#pragma unroll
            for (int mg = 0; mg < 2; mg++) {
                ldm_x4(ah[mg], cur + a_off0 + mg * 16 * (SSTR * 2) + ko);
                ldm_x4(al[mg], cur + 10240 + a_off0 + mg * 16 * (SSTR * 2) + ko);
            }
#pragma unroll
            for (int g = 0; g < 4; g++) {
                uint32_t bh[4];
                ldm_x4(bh, cur + 20480 + b_off + (uint32_t)(g * 16) * (SSTR * 2) + ko);
#pragma unroll
                for (int mg = 0; mg < 2; mg++) {
                    hmma(acc[mg][2 * g],     ah[mg], bh[0], bh[1]);
                    hmma(acc[mg][2 * g],     al[mg], bh[0], bh[1]);
                    hmma(acc[mg][2 * g + 1], ah[mg], bh[2], bh[3]);
                    hmma(acc[mg][2 * g + 1], al[mg], bh[2], bh[3]);
                }
            }
        }
    }

    const int r0 = lane >> 2;
    const int c0 = (lane & 3) * 2;
#pragma unroll
    for (int mg = 0; mg < 2; mg++) {
#pragma unroll
        for (int nt = 0; nt < 8; nt++) {
            int col = nt * 8 + c0;
            float b0v = bv[n0 + col], b1v = bv[n0 + col + 1];

            int m  = m0 + wid * 32 + mg * 16 + r0;
            int bb = m >> 11, s = m & (S_ - 1);
            size_t idx = (((size_t)bb * NH_ + h) * S_ + s) * DH_ + col;
            *(uint32_t*)(g_vh + idx) = hpair(acc[mg][nt][0] + b0v, acc[mg][nt][1] + b1v);

            m  = m0 + wid * 32 + mg * 16 + r0 + 8;
            bb = m >> 11; s = m & (S_ - 1);
            idx = (((size_t)bb * NH_ + h) * S_ + s) * DH_ + col;
            *(uint32_t*)(g_vh + idx) = hpair(acc[mg][nt][2] + b0v, acc[mg][nt][3] + b1v);
        }
    }
}

// ---------------------------------------------------------------------------
// Kernel 2: flash attention (unchanged from R15).
//   Per-stage: KH 0 (9216), VH 9216 (9216), BIAS 18432 (18432) = 36864 B.
// ---------------------------------------------------------------------------
#define SQB 144
#define O_VH   9216
#define O_BIAS 18432
#define FSTG   36864
#define FLASH_SMEM (2 * FSTG)              // 73728

__global__ __launch_bounds__(256) void flash_hmma(
    const float* __restrict__ mask,       // [B,1,1,S]
    float*       __restrict__ out)        // [B,S,H]
{
    extern __shared__ char fsm[];
    const uint32_t sb = smem_u32(fsm);

    const int tid  = threadIdx.x;
    const int wid  = tid >> 5;
    const int lane = tid & 31;
    const int q0 = blockIdx.x * 128;
    const int h  = blockIdx.y;
    const int b  = blockIdx.z;
    const size_t base = ((size_t)b * NH_ + h) * S_;
    const float* maskrow = mask + (size_t)b * S_;
    const __half* gb = g_bias + ((size_t)h * S_ + q0) * S_;

    // Phase 1: stage Qh
#pragma unroll
    for (int rep = 0; rep < 4; rep++) {
        int u = tid + rep * 256;
        int row = u >> 3, uc = u & 7;
        size_t go = (base + q0 + row) * DH_ + uc * 8;
        *(uint4*)(fsm + row * SQB + uc * 16) = *(const uint4*)(g_qh + go);
    }
    __syncthreads();

    // Phase 2: hoist Q fragments
    const uint32_t a_off = (uint32_t)(wid * 16 + (lane & 15)) * SQB
                         + ((lane >> 4) & 1) * 16;
    uint32_t qah[4][4];
#pragma unroll
    for (int kk = 0; kk < 4; kk++)
        ldm_x4(qah[kk], sb + a_off + kk * 32);
    __syncthreads();

    const uint32_t b_off = (uint32_t)((lane & 7) + ((lane >> 4) & 1) * 8) * SQB
                         + ((lane >> 3) & 1) * 16;
    const int v_m = lane >> 3, v_r = lane & 7;
    const uint32_t v_off = (uint32_t)((v_m & 1) * 8 + v_r) * SQB + (v_m >> 1) * 16;

    const int r_q = lane >> 2;
    const int c_q = (lane & 3) * 2;
    const int qrt = q0 + wid * 16 + r_q;
    const int qrb = qrt + 8;
    const int broff = (wid * 16 + r_q) * SQB;

    float m_t = -1e30f, m_b = -1e30f, l_t = 0.0f, l_b = 0.0f;
    float O[8][4];
#pragma unroll
    for (int i = 0; i < 8; i++)
#pragma unroll
        for (int j = 0; j < 4; j++) O[i][j] = 0.0f;

    const int prow0 = tid >> 3, puc = tid & 7;

    {
        uint32_t dst = sb;
#pragma unroll
        for (int rep = 0; rep < 2; rep++) {
            int row = prow0 + rep * 32;
            size_t go = (base + row) * DH_ + puc * 8;
            uint32_t so = row * SQB + puc * 16;
            cpa16(dst + so,        g_kh + go);
            cpa16(dst + O_VH + so, g_vh + go);
        }
#pragma unroll
        for (int rep = 0; rep < 4; rep++) {
            int u = tid + rep * 256;
            int row = u >> 3, uc = u & 7;
            cpa16(dst + O_BIAS + row * SQB + uc * 16,
                  gb + (size_t)row * S_ + uc * 8);
        }
        cpa_commit();
    }

    for (int kt = 0; kt < 32; kt++) {
        const int k0 = kt * 64;
        const uint32_t curoff = (kt & 1) * FSTG;
        const uint32_t cur = sb + curoff;
        cpa_wait0();
        __syncthreads();
        if (kt < 31) {
            uint32_t dst = sb + ((kt + 1) & 1) * FSTG;
            int kn = (kt + 1) * 64;
#pragma unroll
            for (int rep = 0; rep < 2; rep++) {
                int row = prow0 + rep * 32;
                size_t go = (base + kn + row) * DH_ + puc * 8;
                uint32_t so = row * SQB + puc * 16;
                cpa16(dst + so,        g_kh + go);
                cpa16(dst + O_VH + so, g_vh + go);
            }
#pragma unroll
            for (int rep = 0; rep < 4; rep++) {
                int u = tid + rep * 256;
                int row = u >> 3, uc = u & 7;
                cpa16(dst + O_BIAS + row * SQB + uc * 16,
                      gb + (size_t)row * S_ + kn + uc * 8);
            }
            cpa_commit();
        }

        float sfr[8][4];
#pragma unroll
        for (int i = 0; i < 8; i++)
#pragma unroll
            for (int j = 0; j < 4; j++) sfr[i][j] = 0.0f;

#pragma unroll
        for (int kk = 0; kk < 4; kk++) {
            const uint32_t ko = kk * 32;
#pragma unroll
            for (int np = 0; np < 4; np++) {
                uint32_t bh[4];
                uint32_t noff = (uint32_t)np * 16 * SQB;
                ldm_x4(bh, cur + b_off + noff + ko);
                hmma(sfr[2 * np],     qah[kk], bh[0], bh[1]);
                hmma(sfr[2 * np + 1], qah[kk], bh[2], bh[3]);
            }
        }

#pragma unroll
        for (int nt = 0; nt < 8; nt++) {
            int c = nt * 8 + c_q;
            const char* bp = fsm + curoff + O_BIAS + broff + c * 2;
            float2 fb_t = __half22float2(*(const __half2*)bp);
            float2 fb_b = __half22float2(*(const __half2*)(bp + 8 * SQB));
            float mk0 = __ldg(maskrow + k0 + c);
            float mk1 = __ldg(maskrow + k0 + c + 1);
            sfr[nt][0] = sfr[nt][0] * 0.125f + fb_t.x + mk0;
            sfr[nt][1] = sfr[nt][1] * 0.125f + fb_t.y + mk1;
            sfr[nt][2] = sfr[nt][2] * 0.125f + fb_b.x + mk0;
            sfr[nt][3] = sfr[nt][3] * 0.125f + fb_b.y + mk1;
        }

        float vt = -1e30f, vb = -1e30f;
#pragma unroll
        for (int nt = 0; nt < 8; nt++) {
            vt = fmaxf(vt, fmaxf(sfr[nt][0], sfr[nt][1]));
            vb = fmaxf(vb, fmaxf(sfr[nt][2], sfr[nt][3]));
        }
        vt = fmaxf(vt, __shfl_xor_sync(0xffffffffu, vt, 1));
        vt = fmaxf(vt, __shfl_xor_sync(0xffffffffu, vt, 2));
        vb = fmaxf(vb, __shfl_xor_sync(0xffffffffu, vb, 1));
        vb = fmaxf(vb, __shfl_xor_sync(0xffffffffu, vb, 2));
        float mnt = fmaxf(m_t, vt), mnb = fmaxf(m_b, vb);
        float sct = __expf(m_t - mnt), scb = __expf(m_b - mnb);
        float rst = 0.0f, rsb = 0.0f;
#pragma unroll
        for (int nt = 0; nt < 8; nt++) {
            sfr[nt][0] = __expf(sfr[nt][0] - mnt);
            sfr[nt][1] = __expf(sfr[nt][1] - mnt);
            sfr[nt][2] = __expf(sfr[nt][2] - mnb);
            sfr[nt][3] = __expf(sfr[nt][3] - mnb);
            rst += sfr[nt][0] + sfr[nt][1];
            rsb += sfr[nt][2] + sfr[nt][3];
        }
        rst += __shfl_xor_sync(0xffffffffu, rst, 1);
        rst += __shfl_xor_sync(0xffffffffu, rst, 2);
        rsb += __shfl_xor_sync(0xffffffffu, rsb, 1);
        rsb += __shfl_xor_sync(0xffffffffu, rsb, 2);
        l_t = l_t * sct + rst;
        l_b = l_b * scb + rsb;
        m_t = mnt; m_b = mnb;
#pragma unroll
        for (int nt = 0; nt < 8; nt++) {
            O[nt][0] *= sct; O[nt][1] *= sct;
            O[nt][2] *= scb; O[nt][3] *= scb;
        }

#pragma unroll
        for (int kk = 0; kk < 4; kk++) {
            uint32_t aph[4];
            aph[0] = hpair(sfr[2 * kk][0], sfr[2 * kk][1]);
            aph[1] = hpair(sfr[2 * kk][2], sfr[2 * kk][3]);
            aph[2] = hpair(sfr[2 * kk + 1][0], sfr[2 * kk + 1][1]);
            aph[3] = hpair(sfr[2 * kk + 1][2], sfr[2 * kk + 1][3]);
#pragma unroll
            for (int np = 0; np < 4; np++) {
                uint32_t vh[4];
                uint32_t va = v_off + (uint32_t)kk * 16 * SQB + np * 32;
                ldm_x4_t(vh, cur + O_VH + va);
                hmma(O[2 * np],     aph, vh[0], vh[1]);
                hmma(O[2 * np + 1], aph, vh[2], vh[3]);
            }
        }
    }

    float ilt = 1.0f / l_t, ilb = 1.0f / l_b;
#pragma unroll
    for (int nt = 0; nt < 8; nt++) {
        int c = nt * 8 + c_q;
        float* pt = out + ((size_t)b * S_ + qrt) * H_ + h * DH_ + c;
        ((float2*)pt)[0] = make_float2(O[nt][0] * ilt, O[nt][1] * ilt);
        float* pb = out + ((size_t)b * S_ + qrb) * H_ + h * DH_ + c;
        ((float2*)pb)[0] = make_float2(O[nt][2] * ilb, O[nt][3] * ilb);
    }
}

// ---------------------------------------------------------------------------
extern "C" void kernel_launch(void* const* d_in, const int* in_sizes, int n_in,
                              void* d_out, int out_size)
{
    const float* X    = (const float*)d_in[0];
    const float* mask = (const float*)d_in[1];
    const int*   didx = (const int*)d_in[2];
    const float* Wq   = (const float*)d_in[3];
    const float* bq   = (const float*)d_in[4];
    const float* Wk   = (const float*)d_in[5];
    const float* bk   = (const float*)d_in[6];
    const float* Wv   = (const float*)d_in[7];
    const float* bv   = (const float*)d_in[8];
    const float* de   = (const float*)d_in[9];
    float* out = (float*)d_out;

    cudaFuncSetAttribute(flash_hmma,
                         cudaFuncAttributeMaxDynamicSharedMemorySize,
                         FLASH_SMEM);
    cudaFuncSetAttribute(qk_proj,
                         cudaFuncAttributeMaxDynamicSharedMemorySize,
                         QK_SMEM);
    cudaFuncSetAttribute(v_proj,
                         cudaFuncAttributeMaxDynamicSharedMemorySize,
                         V_SMEM);

    cvt_x_t<<<4096, 256>>>(X, de);
    cvt_w_all<<<3072, 256>>>(Wq, Wk, Wv);
    bias_pre<<<dim3(64, 16), 256>>>(didx);
    qk_proj<<<dim3(32, 32), 128, QK_SMEM>>>(bq, bk);
    v_proj<<<dim3(16, 32), 128, V_SMEM>>>(bv);
    flash_hmma<<<dim3(16, NH_, B_), 256, FLASH_SMEM>>>(mask, out);
}

// round 17
// speedup vs baseline: 6.0678x; 1.0413x over previous
#include <cuda_runtime.h>
#include <cuda_fp16.h>
#include <cstdint>

#define B_ 2
#define S_ 2048
#define H_ 1024
#define NH_ 16
#define DH_ 64
#define RV_ 4096

__device__ __forceinline__ uint32_t smem_u32(const void* p) {
    uint32_t a;
    asm("{ .reg .u64 t; cvta.to.shared.u64 t, %1; cvt.u32.u64 %0, t; }"
        : "=r"(a) : "l"(p));
    return a;
}
__device__ __forceinline__ void ldm_x4(uint32_t* r, uint32_t addr) {
    asm volatile("ldmatrix.sync.aligned.m8n8.x4.shared.b16 {%0,%1,%2,%3}, [%4];"
                 : "=r"(r[0]), "=r"(r[1]), "=r"(r[2]), "=r"(r[3]) : "r"(addr));
}
__device__ __forceinline__ void ldm_x4_t(uint32_t* r, uint32_t addr) {
    asm volatile("ldmatrix.sync.aligned.m8n8.x4.trans.shared.b16 {%0,%1,%2,%3}, [%4];"
                 : "=r"(r[0]), "=r"(r[1]), "=r"(r[2]), "=r"(r[3]) : "r"(addr));
}
// fp16 mma m16n8k16 row.col, fp32 accum
__device__ __forceinline__ void hmma(float* c, const uint32_t* a,
                                     uint32_t b0, uint32_t b1) {
    asm volatile(
        "mma.sync.aligned.m16n8k16.row.col.f32.f16.f16.f32 "
        "{%0,%1,%2,%3}, {%4,%5,%6,%7}, {%8,%9}, {%0,%1,%2,%3};"
        : "+f"(c[0]), "+f"(c[1]), "+f"(c[2]), "+f"(c[3])
        : "r"(a[0]), "r"(a[1]), "r"(a[2]), "r"(a[3]), "r"(b0), "r"(b1));
}
__device__ __forceinline__ uint32_t hpair(float x, float y) {
    __half2 h = __floats2half2_rn(x, y);
    return *(uint32_t*)&h;
}
__device__ __forceinline__ uint32_t hpair_lo(float x, float y, uint32_t h) {
    __half2 hh = *(__half2*)&h;
    return hpair(x - __low2float(hh), y - __high2float(hh));
}
// cp.async (sm_80 PTX, valid under compute_103)
__device__ __forceinline__ void cpa16(uint32_t dst, const void* src) {
    asm volatile("cp.async.cg.shared.global [%0], [%1], 16;"
                 :: "r"(dst), "l"(src));
}
__device__ __forceinline__ void cpa_commit() {
    asm volatile("cp.async.commit_group;" ::: "memory");
}
__device__ __forceinline__ void cpa_wait0() {
    asm volatile("cp.async.wait_group 0;" ::: "memory");
}

// Scratch (allocation-free contract)
__device__ __half g_dTh[NH_ * RV_];                      // dist_emb^T fp16
__device__ __half g_bias[(size_t)NH_ * S_ * S_];         // precomputed bias planes
__device__ __half g_xh[(size_t)4096 * 1024];
__device__ __half g_xl[(size_t)4096 * 1024];
__device__ __half g_wh[(size_t)3 * 1024 * 1024];
__device__ __half g_qh[(size_t)B_ * NH_ * S_ * DH_];
__device__ __half g_kh[(size_t)B_ * NH_ * S_ * DH_];
__device__ __half g_vh[(size_t)B_ * NH_ * S_ * DH_];

// ---------------------------------------------------------------------------
// Kernel A: X fp16-split conversion + dist_emb transpose (to fp16).
// ---------------------------------------------------------------------------
__global__ void cvt_x_t(const float* __restrict__ src,
                        const float* __restrict__ de) {
    int i = blockIdx.x * blockDim.x + threadIdx.x;
    if (i < RV_ * NH_) {
        int v = i / NH_;
        int h = i - v * NH_;
        g_dTh[h * RV_ + v] = __float2half(de[i]);
    }
    float4 v4 = ((const float4*)src)[i];
    uint32_t h0 = hpair(v4.x, v4.y), h1 = hpair(v4.z, v4.w);
    uint32_t l0 = hpair_lo(v4.x, v4.y, h0), l1 = hpair_lo(v4.z, v4.w, h1);
    ((uint32_t*)g_xh)[2 * i] = h0; ((uint32_t*)g_xh)[2 * i + 1] = h1;
    ((uint32_t*)g_xl)[2 * i] = l0; ((uint32_t*)g_xl)[2 * i + 1] = l1;
}
// Kernel B: all three W conversions, HI ONLY.
__global__ void cvt_w_all(const float* __restrict__ Wq,
                          const float* __restrict__ Wk,
                          const float* __restrict__ Wv) {
    int w = blockIdx.x >> 10;
    const float* src = (w == 0) ? Wq : (w == 1) ? Wk : Wv;
    int i = (blockIdx.x & 1023) * blockDim.x + threadIdx.x;
    float4 v = ((const float4*)src)[i];
    uint32_t* dh = (uint32_t*)(g_wh + (size_t)w * 1048576);
    dh[2 * i]     = hpair(v.x, v.y);
    dh[2 * i + 1] = hpair(v.z, v.w);
}

// ---------------------------------------------------------------------------
// Kernel C: bias precompute. g_bias[h][q][k] = dTh[h][dist_idx[q][k]].
// ---------------------------------------------------------------------------
__global__ __launch_bounds__(256) void bias_pre(const int* __restrict__ didx) {
    __shared__ __half dc[RV_];
    const int h  = blockIdx.y;
    const int q0 = blockIdx.x * 32;
    const int tid = threadIdx.x;
    for (int i = tid; i < RV_; i += 256) dc[i] = g_dTh[h * RV_ + i];
    __syncthreads();
    for (int r = 0; r < 32; r++) {
        const int row = q0 + r;
        const int4* src = (const int4*)(didx + (size_t)row * S_) + tid * 2;
        int4 ia = src[0];
        int4 ib = src[1];
        __half2 p0 = __halves2half2(dc[ia.x], dc[ia.y]);
        __half2 p1 = __halves2half2(dc[ia.z], dc[ia.w]);
        __half2 p2 = __halves2half2(dc[ib.x], dc[ib.y]);
        __half2 p3 = __halves2half2(dc[ib.z], dc[ib.w]);
        uint4 o;
        o.x = *(uint32_t*)&p0; o.y = *(uint32_t*)&p1;
        o.z = *(uint32_t*)&p2; o.w = *(uint32_t*)&p3;
        *(uint4*)(g_bias + ((size_t)h * S_ + row) * S_ + tid * 8) = o;
    }
}

// ---------------------------------------------------------------------------
// Kernel 1a: Q/K projection, 1-term (Ah*Bh). 4 warps x 32 rows.
// ---------------------------------------------------------------------------
#define SSTR 40
#define QK_STG 15360
#define QK_SMEM (2 * QK_STG)

__global__ __launch_bounds__(128) void qk_proj(
    const float* __restrict__ bq, const float* __restrict__ bk)
{
    extern __shared__ char psm[];
    const uint32_t sb = smem_u32(psm);

    const int w   = blockIdx.x >> 4;          // 0=Q, 1=K
    const int h   = blockIdx.x & 15;
    const int n0  = h * 64;
    const int m0  = blockIdx.y * 128;
    const int tid = threadIdx.x;
    const int wid = tid >> 5;
    const int lane = tid & 31;

    const float* bias = (w == 0) ? bq : bk;
    __half* oh = (w == 0) ? g_qh : g_kh;
    const __half* Wh = g_wh + (size_t)w * 1048576;

    float acc[2][8][4];
#pragma unroll
    for (int mg = 0; mg < 2; mg++)
#pragma unroll
        for (int i = 0; i < 8; i++)
#pragma unroll
            for (int j = 0; j < 4; j++) acc[mg][i][j] = 0.0f;

    const uint32_t a_off0 = (uint32_t)(wid * 32 + (lane & 15)) * (SSTR * 2)
                          + ((lane >> 4) & 1) * 16;
    const uint32_t b_off = (uint32_t)((lane & 7) + ((lane >> 4) & 1) * 8) * (SSTR * 2)
                         + ((lane >> 3) & 1) * 16;

    const int arow0 = tid >> 2, auc = tid & 3;
    const int brow0 = tid >> 2, buc = tid & 3;

    {
        uint32_t dst = sb;
#pragma unroll
        for (int rep = 0; rep < 4; rep++) {
            int row = arow0 + rep * 32;
            cpa16(dst + row * (SSTR * 2) + auc * 16,
                  g_xh + (size_t)(m0 + row) * 1024 + auc * 8);
        }
#pragma unroll
        for (int rep = 0; rep < 2; rep++) {
            int row = brow0 + rep * 32;
            cpa16(dst + 10240 + row * (SSTR * 2) + buc * 16,
                  Wh + (size_t)(n0 + row) * 1024 + buc * 8);
        }
        cpa_commit();
    }

    for (int kc = 0; kc < 32; kc++) {
        const uint32_t cur = sb + (kc & 1) * QK_STG;
        cpa_wait0();
        __syncthreads();
        if (kc < 31) {
            uint32_t dst = sb + ((kc + 1) & 1) * QK_STG;
            int kn = (kc + 1) * 32;
#pragma unroll
            for (int rep = 0; rep < 4; rep++) {
                int row = arow0 + rep * 32;
                cpa16(dst + row * (SSTR * 2) + auc * 16,
                      g_xh + (size_t)(m0 + row) * 1024 + kn + auc * 8);
            }
#pragma unroll
            for (int rep = 0; rep < 2; rep++) {
                int row = brow0 + rep * 32;
                cpa16(dst + 10240 + row * (SSTR * 2) + buc * 16,
                      Wh + (size_t)(n0 + row) * 1024 + kn + buc * 8);
            }
            cpa_commit();
        }

#pragma unroll
        for (int k16 = 0; k16 < 2; k16++) {
            const uint32_t ko = k16 * 32;
            uint32_t ah[2][4];
            ldm_x4(ah[0], cur + a_off0 + ko);
            ldm_x4(ah[1], cur + a_off0 + 16 * (SSTR * 2) + ko);
#pragma unroll
            for (int g = 0; g < 4; g++) {
                uint32_t bh[4];
                ldm_x4(bh, cur + 10240 + b_off + (uint32_t)(g * 16) * (SSTR * 2) + ko);
#pragma unroll
                for (int mg = 0; mg < 2; mg++) {
                    hmma(acc[mg][2 * g],     ah[mg], bh[0], bh[1]);
                    hmma(acc[mg][2 * g + 1], ah[mg], bh[2], bh[3]);
                }
            }
        }
    }

    const int r0 = lane >> 2;
    const int c0 = (lane & 3) * 2;
#pragma unroll
    for (int mg = 0; mg < 2; mg++) {
#pragma unroll
        for (int nt = 0; nt < 8; nt++) {
            int col = nt * 8 + c0;
            float b0v = bias[n0 + col], b1v = bias[n0 + col + 1];

            int m  = m0 + wid * 32 + mg * 16 + r0;
            int bb = m >> 11, s = m & (S_ - 1);
            size_t idx = (((size_t)bb * NH_ + h) * S_ + s) * DH_ + col;
            *(uint32_t*)(oh + idx) = hpair(acc[mg][nt][0] + b0v, acc[mg][nt][1] + b1v);

            m  = m0 + wid * 32 + mg * 16 + r0 + 8;
            bb = m >> 11; s = m & (S_ - 1);
            idx = (((size_t)bb * NH_ + h) * S_ + s) * DH_ + col;
            *(uint32_t*)(oh + idx) = hpair(acc[mg][nt][2] + b0v, acc[mg][nt][3] + b1v);
        }
    }
}

// ---------------------------------------------------------------------------
// Kernel 1b: V projection, 2-term (Ah+Al)*Bh. 4 warps x 32 rows.
// ---------------------------------------------------------------------------
#define V_STG 25600
#define V_SMEM (2 * V_STG)

__global__ __launch_bounds__(128) void v_proj(const float* __restrict__ bv)
{
    extern __shared__ char psm[];
    const uint32_t sb = smem_u32(psm);

    const int h   = blockIdx.x;
    const int n0  = h * 64;
    const int m0  = blockIdx.y * 128;
    const int tid = threadIdx.x;
    const int wid = tid >> 5;
    const int lane = tid & 31;

    const __half* Wh = g_wh + (size_t)2 * 1048576;

    float acc[2][8][4];
#pragma unroll
    for (int mg = 0; mg < 2; mg++)
#pragma unroll
        for (int i = 0; i < 8; i++)
#pragma unroll
            for (int j = 0; j < 4; j++) acc[mg][i][j] = 0.0f;

    const uint32_t a_off0 = (uint32_t)(wid * 32 + (lane & 15)) * (SSTR * 2)
                          + ((lane >> 4) & 1) * 16;
    const uint32_t b_off = (uint32_t)((lane & 7) + ((lane >> 4) & 1) * 8) * (SSTR * 2)
                         + ((lane >> 3) & 1) * 16;

    const int arow0 = tid >> 2, auc = tid & 3;
    const int brow0 = tid >> 2, buc = tid & 3;

    {
        uint32_t dst = sb;
#pragma unroll
        for (int rep = 0; rep < 4; rep++) {
            int row = arow0 + rep * 32;
            size_t go = (size_t)(m0 + row) * 1024 + auc * 8;
            uint32_t so = row * (SSTR * 2) + auc * 16;
            cpa16(dst + so,         g_xh + go);
            cpa16(dst + 10240 + so, g_xl + go);
        }
#pragma unroll
        for (int rep = 0; rep < 2; rep++) {
            int row = brow0 + rep * 32;
            cpa16(dst + 20480 + row * (SSTR * 2) + buc * 16,
                  Wh + (size_t)(n0 + row) * 1024 + buc * 8);
        }
        cpa_commit();
    }

    for (int kc = 0; kc < 32; kc++) {
        const uint32_t cur = sb + (kc & 1) * V_STG;
        cpa_wait0();
        __syncthreads();
        if (kc < 31) {
            uint32_t dst = sb + ((kc + 1) & 1) * V_STG;
            int kn = (kc + 1) * 32;
#pragma unroll
            for (int rep = 0; rep < 4; rep++) {
                int row = arow0 + rep * 32;
                size_t go = (size_t)(m0 + row) * 1024 + kn + auc * 8;
                uint32_t so = row * (SSTR * 2) + auc * 16;
                cpa16(dst + so,         g_xh + go);
                cpa16(dst + 10240 + so, g_xl + go);
            }
#pragma unroll
            for (int rep = 0; rep < 2; rep++) {
                int row = brow0 + rep * 32;
                cpa16(dst + 20480 + row * (SSTR * 2) + buc * 16,
                      Wh + (size_t)(n0 + row) * 1024 + kn + buc * 8);
            }
            cpa_commit();
        }

#pragma unroll
        for (int k16 = 0; k16 < 2; k16++) {
            const uint32_t ko = k16 * 32;
            uint32_t ah[2][4], al[2][4];
#pragma unroll
            for (int mg = 0; mg < 2; mg++) {
                ldm_x4(ah[mg], cur + a_off0 + mg * 16 * (SSTR * 2) + ko);
                ldm_x4(al[mg], cur + 10240 + a_off0 + mg * 16 * (SSTR * 2) + ko);
            }
#pragma unroll
            for (int g = 0; g < 4; g++) {
                uint32_t bh[4];
                ldm_x4(bh, cur + 20480 + b_off + (uint32_t)(g * 16) * (SSTR * 2) + ko);
#pragma unroll
                for (int mg = 0; mg < 2; mg++) {
                    hmma(acc[mg][2 * g],     ah[mg], bh[0], bh[1]);
                    hmma(acc[mg][2 * g],     al[mg], bh[0], bh[1]);
                    hmma(acc[mg][2 * g + 1], ah[mg], bh[2], bh[3]);
                    hmma(acc[mg][2 * g + 1], al[mg], bh[2], bh[3]);
                }
            }
        }
    }

    const int r0 = lane >> 2;
    const int c0 = (lane & 3) * 2;
#pragma unroll
    for (int mg = 0; mg < 2; mg++) {
#pragma unroll
        for (int nt = 0; nt < 8; nt++) {
            int col = nt * 8 + c0;
            float b0v = bv[n0 + col], b1v = bv[n0 + col + 1];

            int m  = m0 + wid * 32 + mg * 16 + r0;
            int bb = m >> 11, s = m & (S_ - 1);
            size_t idx = (((size_t)bb * NH_ + h) * S_ + s) * DH_ + col;
            *(uint32_t*)(g_vh + idx) = hpair(acc[mg][nt][0] + b0v, acc[mg][nt][1] + b1v);

            m  = m0 + wid * 32 + mg * 16 + r0 + 8;
            bb = m >> 11; s = m & (S_ - 1);
            idx = (((size_t)bb * NH_ + h) * S_ + s) * DH_ + col;
            *(uint32_t*)(g_vh + idx) = hpair(acc[mg][nt][2] + b0v, acc[mg][nt][3] + b1v);
        }
    }
}

// ---------------------------------------------------------------------------
// Kernel 2: flash attention. Bias read via ldmatrix directly in C-frag layout.
//   Per-stage: KH 0 (9216), VH 9216 (9216), BIAS 18432 (18432) = 36864 B.
// ---------------------------------------------------------------------------
#define SQB 144
#define O_VH   9216
#define O_BIAS 18432
#define FSTG   36864
#define FLASH_SMEM (2 * FSTG)              // 73728

__global__ __launch_bounds__(256) void flash_hmma(
    const float* __restrict__ mask,       // [B,1,1,S]
    float*       __restrict__ out)        // [B,S,H]
{
    extern __shared__ char fsm[];
    const uint32_t sb = smem_u32(fsm);

    const int tid  = threadIdx.x;
    const int wid  = tid >> 5;
    const int lane = tid & 31;
    const int q0 = blockIdx.x * 128;
    const int h  = blockIdx.y;
    const int b  = blockIdx.z;
    const size_t base = ((size_t)b * NH_ + h) * S_;
    const float* maskrow = mask + (size_t)b * S_;
    const __half* gb = g_bias + ((size_t)h * S_ + q0) * S_;

    // Phase 1: stage Qh
#pragma unroll
    for (int rep = 0; rep < 4; rep++) {
        int u = tid + rep * 256;
        int row = u >> 3, uc = u & 7;
        size_t go = (base + q0 + row) * DH_ + uc * 8;
        *(uint4*)(fsm + row * SQB + uc * 16) = *(const uint4*)(g_qh + go);
    }
    __syncthreads();

    // Phase 2: hoist Q fragments
    const uint32_t a_off = (uint32_t)(wid * 16 + (lane & 15)) * SQB
                         + ((lane >> 4) & 1) * 16;
    uint32_t qah[4][4];
#pragma unroll
    for (int kk = 0; kk < 4; kk++)
        ldm_x4(qah[kk], sb + a_off + kk * 32);
    __syncthreads();

    const uint32_t b_off = (uint32_t)((lane & 7) + ((lane >> 4) & 1) * 8) * SQB
                         + ((lane >> 3) & 1) * 16;
    const int v_m = lane >> 3, v_r = lane & 7;
    const uint32_t v_off = (uint32_t)((v_m & 1) * 8 + v_r) * SQB + (v_m >> 1) * 16;

    const int r_q = lane >> 2;
    const int c_q = (lane & 3) * 2;
    const int qrt = q0 + wid * 16 + r_q;
    const int qrb = qrt + 8;

    float m_t = -1e30f, m_b = -1e30f, l_t = 0.0f, l_b = 0.0f;
    float O[8][4];
#pragma unroll
    for (int i = 0; i < 8; i++)
#pragma unroll
        for (int j = 0; j < 4; j++) O[i][j] = 0.0f;

    const int prow0 = tid >> 3, puc = tid & 7;

    {
        uint32_t dst = sb;
#pragma unroll
        for (int rep = 0; rep < 2; rep++) {
            int row = prow0 + rep * 32;
            size_t go = (base + row) * DH_ + puc * 8;
            uint32_t so = row * SQB + puc * 16;
            cpa16(dst + so,        g_kh + go);
            cpa16(dst + O_VH + so, g_vh + go);
        }
#pragma unroll
        for (int rep = 0; rep < 4; rep++) {
            int u = tid + rep * 256;
            int row = u >> 3, uc = u & 7;
            cpa16(dst + O_BIAS + row * SQB + uc * 16,
                  gb + (size_t)row * S_ + uc * 8);
        }
        cpa_commit();
    }

    for (int kt = 0; kt < 32; kt++) {
        const int k0 = kt * 64;
        const uint32_t curoff = (kt & 1) * FSTG;
        const uint32_t cur = sb + curoff;
        cpa_wait0();
        __syncthreads();
        if (kt < 31) {
            uint32_t dst = sb + ((kt + 1) & 1) * FSTG;
            int kn = (kt + 1) * 64;
#pragma unroll
            for (int rep = 0; rep < 2; rep++) {
                int row = prow0 + rep * 32;
                size_t go = (base + kn + row) * DH_ + puc * 8;
                uint32_t so = row * SQB + puc * 16;
                cpa16(dst + so,        g_kh + go);
                cpa16(dst + O_VH + so, g_vh + go);
            }
#pragma unroll
            for (int rep = 0; rep < 4; rep++) {
                int u = tid + rep * 256;
                int row = u >> 3, uc = u & 7;
                cpa16(dst + O_BIAS + row * SQB + uc * 16,
                      gb + (size_t)row * S_ + kn + uc * 8);
            }
            cpa_commit();
        }

        // ---- S = Qh Kh^T ----
        float sfr[8][4];
#pragma unroll
        for (int i = 0; i < 8; i++)
#pragma unroll
            for (int j = 0; j < 4; j++) sfr[i][j] = 0.0f;

#pragma unroll
        for (int kk = 0; kk < 4; kk++) {
            const uint32_t ko = kk * 32;
#pragma unroll
            for (int np = 0; np < 4; np++) {
                uint32_t bh[4];
                uint32_t noff = (uint32_t)np * 16 * SQB;
                ldm_x4(bh, cur + b_off + noff + ko);
                hmma(sfr[2 * np],     qah[kk], bh[0], bh[1]);
                hmma(sfr[2 * np + 1], qah[kk], bh[2], bh[3]);
            }
        }

        // ---- scale + bias (ldmatrix C-frag) + mask ----
#pragma unroll
        for (int g = 0; g < 4; g++) {
            uint32_t bf[4];
            ldm_x4(bf, cur + O_BIAS + a_off + g * 32);
            float2 t0 = __half22float2(*(__half2*)&bf[0]);   // rows r_q,   cols 16g+c_q
            float2 b0 = __half22float2(*(__half2*)&bf[1]);   // rows r_q+8, cols 16g+c_q
            float2 t1 = __half22float2(*(__half2*)&bf[2]);   // rows r_q,   cols 16g+8+c_q
            float2 b1 = __half22float2(*(__half2*)&bf[3]);   // rows r_q+8, cols 16g+8+c_q
            int c = g * 16 + c_q;
            float mk0 = __ldg(maskrow + k0 + c);
            float mk1 = __ldg(maskrow + k0 + c + 1);
            float mk2 = __ldg(maskrow + k0 + c + 8);
            float mk3 = __ldg(maskrow + k0 + c + 9);
            sfr[2 * g][0] = sfr[2 * g][0] * 0.125f + t0.x + mk0;
            sfr[2 * g][1] = sfr[2 * g][1] * 0.125f + t0.y + mk1;
            sfr[2 * g][2] = sfr[2 * g][2] * 0.125f + b0.x + mk0;
            sfr[2 * g][3] = sfr[2 * g][3] * 0.125f + b0.y + mk1;
            sfr[2 * g + 1][0] = sfr[2 * g + 1][0] * 0.125f + t1.x + mk2;
            sfr[2 * g + 1][1] = sfr[2 * g + 1][1] * 0.125f + t1.y + mk3;
            sfr[2 * g + 1][2] = sfr[2 * g + 1][2] * 0.125f + b1.x + mk2;
            sfr[2 * g + 1][3] = sfr[2 * g + 1][3] * 0.125f + b1.y + mk3;
        }

        // ---- online softmax ----
        float vt = -1e30f, vb = -1e30f;
#pragma unroll
        for (int nt = 0; nt < 8; nt++) {
            vt = fmaxf(vt, fmaxf(sfr[nt][0], sfr[nt][1]));
            vb = fmaxf(vb, fmaxf(sfr[nt][2], sfr[nt][3]));
        }
        vt = fmaxf(vt, __shfl_xor_sync(0xffffffffu, vt, 1));
        vt = fmaxf(vt, __shfl_xor_sync(0xffffffffu, vt, 2));
        vb = fmaxf(vb, __shfl_xor_sync(0xffffffffu, vb, 1));
        vb = fmaxf(vb, __shfl_xor_sync(0xffffffffu, vb, 2));
        float mnt = fmaxf(m_t, vt), mnb = fmaxf(m_b, vb);
        float sct = __expf(m_t - mnt), scb = __expf(m_b - mnb);
        float rst = 0.0f, rsb = 0.0f;
#pragma unroll
        for (int nt = 0; nt < 8; nt++) {
            sfr[nt][0] = __expf(sfr[nt][0] - mnt);
            sfr[nt][1] = __expf(sfr[nt][1] - mnt);
            sfr[nt][2] = __expf(sfr[nt][2] - mnb);
            sfr[nt][3] = __expf(sfr[nt][3] - mnb);
            rst += sfr[nt][0] + sfr[nt][1];
            rsb += sfr[nt][2] + sfr[nt][3];
        }
        rst += __shfl_xor_sync(0xffffffffu, rst, 1);
        rst += __shfl_xor_sync(0xffffffffu, rst, 2);
        rsb += __shfl_xor_sync(0xffffffffu, rsb, 1);
        rsb += __shfl_xor_sync(0xffffffffu, rsb, 2);
        l_t = l_t * sct + rst;
        l_b = l_b * scb + rsb;
        m_t = mnt; m_b = mnb;
#pragma unroll
        for (int nt = 0; nt < 8; nt++) {
            O[nt][0] *= sct; O[nt][1] *= sct;
            O[nt][2] *= scb; O[nt][3] *= scb;
        }

        // ---- O += Ph Vh ----
#pragma unroll
        for (int kk = 0; kk < 4; kk++) {
            uint32_t aph[4];
            aph[0] = hpair(sfr[2 * kk][0], sfr[2 * kk][1]);
            aph[1] = hpair(sfr[2 * kk][2], sfr[2 * kk][3]);
            aph[2] = hpair(sfr[2 * kk + 1][0], sfr[2 * kk + 1][1]);
            aph[3] = hpair(sfr[2 * kk + 1][2], sfr[2 * kk + 1][3]);
#pragma unroll
            for (int np = 0; np < 4; np++) {
                uint32_t vh[4];
                uint32_t va = v_off + (uint32_t)kk * 16 * SQB + np * 32;
                ldm_x4_t(vh, cur + O_VH + va);
                hmma(O[2 * np],     aph, vh[0], vh[1]);
                hmma(O[2 * np + 1], aph, vh[2], vh[3]);
            }
        }
    }

    // ---- epilogue ----
    float ilt = 1.0f / l_t, ilb = 1.0f / l_b;
#pragma unroll
    for (int nt = 0; nt < 8; nt++) {
        int c = nt * 8 + c_q;
        float* pt = out + ((size_t)b * S_ + qrt) * H_ + h * DH_ + c;
        ((float2*)pt)[0] = make_float2(O[nt][0] * ilt, O[nt][1] * ilt);
        float* pb = out + ((size_t)b * S_ + qrb) * H_ + h * DH_ + c;
        ((float2*)pb)[0] = make_float2(O[nt][2] * ilb, O[nt][3] * ilb);
    }
}

// ---------------------------------------------------------------------------
extern "C" void kernel_launch(void* const* d_in, const int* in_sizes, int n_in,
                              void* d_out, int out_size)
{
    const float* X    = (const float*)d_in[0];
    const float* mask = (const float*)d_in[1];
    const int*   didx = (const int*)d_in[2];
    const float* Wq   = (const float*)d_in[3];
    const float* bq   = (const float*)d_in[4];
    const float* Wk   = (const float*)d_in[5];
    const float* bk   = (const float*)d_in[6];
    const float* Wv   = (const float*)d_in[7];
    const float* bv   = (const float*)d_in[8];
    const float* de   = (const float*)d_in[9];
    float* out = (float*)d_out;

    cudaFuncSetAttribute(flash_hmma,
                         cudaFuncAttributeMaxDynamicSharedMemorySize,
                         FLASH_SMEM);
    cudaFuncSetAttribute(qk_proj,
                         cudaFuncAttributeMaxDynamicSharedMemorySize,
                         QK_SMEM);
    cudaFuncSetAttribute(v_proj,
                         cudaFuncAttributeMaxDynamicSharedMemorySize,
                         V_SMEM);

    cvt_x_t<<<4096, 256>>>(X, de);
    cvt_w_all<<<3072, 256>>>(Wq, Wk, Wv);
    bias_pre<<<dim3(64, 16), 256>>>(didx);
    qk_proj<<<dim3(32, 32), 128, QK_SMEM>>>(bq, bk);
    v_proj<<<dim3(16, 32), 128, V_SMEM>>>(bv);
    flash_hmma<<<dim3(16, NH_, B_), 256, FLASH_SMEM>>>(mask, out);
}